// round 7
// baseline (speedup 1.0000x reference)
#include <cuda_runtime.h>
#include <math.h>
#include <stdint.h>

#define NHID   512
#define HEADS  8
#define NKD    64
#define BB     16
#define SS     511
#define LL     512
#define NNODE  8176      // BB*SS
#define NTOK   8192      // BB*LL
#define EE     131072
#define QKVD   1536
#define FFD    2048

// ----------------------------- scratch (device globals; no allocation) -----
__device__ float g_h   [NTOK*NHID];
__device__ float g_ht  [NTOK*NHID];     // tf32-rounded shadow of h
__device__ float g_qkv [NTOK*QKVD];     // stored tf32-rounded
__device__ float g_o   [NTOK*NHID];     // stored tf32-rounded
__device__ float g_x   [NTOK*NHID];
__device__ float g_xt  [NTOK*NHID];     // tf32-rounded shadow of x
__device__ float g_ff  [NTOK*FFD];      // stored tf32-rounded
__device__ float g_xf  [NNODE*NHID];
__device__ float g_P   [NNODE*NHID];
__device__ float g_Q   [NNODE*NHID];
__device__ float g_T   [2*NNODE*NHID];  // stored tf32-rounded
__device__ float g_xc  [NNODE*NHID];
__device__ float g_xg  [NNODE*NHID];
__device__ float g_xgt [NNODE*NHID];    // tf32-rounded shadow of xg
__device__ float g_fg  [NNODE*NHID];    // stored tf32-rounded
__device__ float g_M   [HEADS*NHID*NHID];
__device__ float g_Ncat[HEADS*NHID*64];
__device__ float g_ccat[HEADS*NHID];
__device__ float g_dcat[HEADS*64];
__device__ float g_tvec[2*NNODE];
__device__ float g_sin [2*NNODE];
__device__ float g_sout[2*NNODE];
__device__ float g_inv1[2*NNODE];
__device__ int   g_ind [2*NNODE];
__device__ int   g_outd[2*NNODE];
__device__ int   g_off [2*NNODE];
__device__ int   g_cur [2*NNODE];
__device__ int   g_csr [2*EE];
__device__ unsigned g_pm[(size_t)BB*HEADS*LL*(LL/32)];

// pre-rounded weights
__device__ float g_qkvw_r [4*NHID*QKVD];
__device__ float g_attnw_r[4*NHID*NHID];
__device__ float g_ff1w_r [4*NHID*FFD];
__device__ float g_ff2w_r [4*FFD*NHID];
__device__ float g_s1w_r  [HEADS*NHID*NHID];
__device__ float g_s2w_r  [HEADS*NHID*NHID];
__device__ float g_gc3w_r [HEADS*NHID*64];
__device__ float g_gff1w_r[NHID*NHID];
__device__ float g_gff2w_r[NHID*NHID];

__constant__ int c_pat[8] = {0,0,1,1,0,0,1,1};

// ----------------------------- common GEMM param block ---------------------
struct GP {
    const float *A, *B, *bias, *res;
    float *C, *Ct;
    int lda, ldb, ldc, ldres;
    int M, N, K;
    float resScale;
    int relu;
    int roundC;    // round C in place (tf32 rna)
    int zDiv;
    int hmode;     // per-head graph GEMM mode: A selected by (z>>1)&1
    long long aO, aI, bO, bI, cO, cI, rO, rI, biasO;
};

// ----------------------------- tf32 helpers --------------------------------
__device__ __forceinline__ unsigned f2tf(float f) {
    unsigned u; asm("cvt.rna.tf32.f32 %0, %1;" : "=r"(u) : "f"(f)); return u;
}
__device__ __forceinline__ float tfr(float f) { return __uint_as_float(f2tf(f)); }
__device__ __forceinline__ uint4 cvt4(float4 v) {
    uint4 r; r.x=f2tf(v.x); r.y=f2tf(v.y); r.z=f2tf(v.z); r.w=f2tf(v.w); return r;
}
__device__ __forceinline__ void ldsm4(unsigned &d0, unsigned &d1, unsigned &d2, unsigned &d3,
                                      unsigned addr) {
    asm volatile("ldmatrix.sync.aligned.m8n8.x4.shared.b16 {%0,%1,%2,%3}, [%4];"
                 : "=r"(d0), "=r"(d1), "=r"(d2), "=r"(d3) : "r"(addr));
}
__device__ __forceinline__ void mma8(float* c, const unsigned* a, const unsigned* b) {
    asm volatile(
        "mma.sync.aligned.m16n8k8.row.col.f32.tf32.tf32.f32 "
        "{%0,%1,%2,%3}, {%4,%5,%6,%7}, {%8,%9}, {%0,%1,%2,%3};"
        : "+f"(c[0]), "+f"(c[1]), "+f"(c[2]), "+f"(c[3])
        : "r"(a[0]), "r"(a[1]), "r"(a[2]), "r"(a[3]), "r"(b[0]), "r"(b[1]));
}
__device__ __forceinline__ void cpa16(unsigned d, const float* s, bool v) {
    asm volatile("cp.async.cg.shared.global [%0], [%1], 16, %2;"
                 :: "r"(d), "l"(s), "r"(v ? 16u : 0u));
}
#define CP_COMMIT asm volatile("cp.async.commit_group;")
#define CP_WAIT1  asm volatile("cp.async.wait_group 1;")

// ----------------------------- tf32 tensor-core GEMM (cp.async, 3-stage) ---
// Operands MUST be pre-rounded to tf32. CTA tile 128 x BN, 8 warps, K-slice 16.
template<int BN, int WGN>
__global__ __launch_bounds__(256) void mma_k(GP p) {
    constexpr int WGM = 8 / WGN;
    constexpr int WM  = 128 / WGM;
    constexpr int WN  = BN / WGN;
    constexpr int MF  = WM / 16;
    constexpr int NF  = WN / 8;
    constexpr int AST = 20;        // A smem row stride (words), conflict-free ldmatrix
    constexpr int BST = BN + 8;    // B smem row stride

    extern __shared__ unsigned sm[];
    // layout: 3 A stages (128*AST each), then 3 B stages (16*BST each)
    unsigned* sA[3]; unsigned* sB[3];
    #pragma unroll
    for (int s = 0; s < 3; s++) {
        sA[s] = sm + s * (128 * AST);
        sB[s] = sm + 3 * (128 * AST) + s * (16 * BST);
    }

    const float *A, *B; float *C, *Ct = nullptr;
    const float *bias = nullptr, *res = nullptr;
    if (p.hmode) {
        int hd = blockIdx.z;
        A = p.A + (((hd >> 1) & 1) ? p.aI : 0);
        B = p.B + (size_t)hd * p.bO;
        C = p.C + (size_t)hd * p.cO;
    } else {
        int zo = blockIdx.z / p.zDiv, zi = blockIdx.z % p.zDiv;
        A = p.A + zo * p.aO + zi * p.aI;
        B = p.B + zo * p.bO + zi * p.bI;
        C = p.C + zo * p.cO + zi * p.cI;
        if (p.Ct)   Ct  = p.Ct + zo * p.cO + zi * p.cI;
        if (p.bias) bias = p.bias + zo * p.biasO;
        if (p.res)  res  = p.res + zo * p.rO + zi * p.rI;
    }

    int tid = threadIdx.x, lane = tid & 31, warp = tid >> 5;
    int wm = warp / WGN, wn = warp % WGN;
    int m0 = blockIdx.x * 128, n0 = blockIdx.y * BN;

    int ar = tid >> 1, ak = (tid & 1) * 8;
    bool aval = (m0 + ar) < p.M;
    const float* aptr = A + (size_t)(m0 + ar) * p.lda + ak;

    int bk_t, bn4_t;
    if (BN == 128) { bk_t = tid >> 5; bn4_t = (tid & 31) * 4; }
    else           { bk_t = tid >> 4; bn4_t = (tid & 15) * 4; }
    const float* bptr = B + (size_t)bk_t * p.ldb + n0 + bn4_t;

    unsigned saA[3], saB[3];
    #pragma unroll
    for (int s = 0; s < 3; s++) {
        saA[s] = (unsigned)__cvta_generic_to_shared(sA[s]);
        saB[s] = (unsigned)__cvta_generic_to_shared(sB[s]);
    }

    auto issue = [&](int s, int k0) {
        unsigned da = saA[s] + (unsigned)((ar * AST + ak) * 4);
        cpa16(da,      aptr + k0,     aval);
        cpa16(da + 16, aptr + k0 + 4, aval);
        unsigned db = saB[s] + (unsigned)((bk_t * BST + bn4_t) * 4);
        cpa16(db, bptr + (size_t)k0 * p.ldb, true);
        if (BN == 128)
            cpa16(saB[s] + (unsigned)(((bk_t + 8) * BST + bn4_t) * 4),
                  bptr + (size_t)(k0 + 8) * p.ldb, true);
    };

    float acc[MF][NF][4];
    #pragma unroll
    for (int f = 0; f < MF; f++)
        #pragma unroll
        for (int j = 0; j < NF; j++)
            #pragma unroll
            for (int q = 0; q < 4; q++) acc[f][j][q] = 0.f;

    int nIter = p.K >> 4;
    issue(0, 0);  CP_COMMIT;
    issue(1, 16); CP_COMMIT;

    for (int i = 0; i < nIter; i++) {
        CP_WAIT1;
        __syncthreads();
        if (i + 2 < nIter) issue((i + 2) % 3, (i + 2) * 16);
        CP_COMMIT;

        int s = i % 3;
        unsigned sAb = saA[s];
        const unsigned* Bc = sB[s];
        #pragma unroll
        for (int kk = 0; kk < 16; kk += 8) {
            unsigned bfr[NF][2];
            #pragma unroll
            for (int j = 0; j < NF; j++) {
                int nb = wn * WN + j * 8 + (lane >> 2);
                bfr[j][0] = Bc[(kk + (lane & 3)) * BST + nb];
                bfr[j][1] = Bc[(kk + 4 + (lane & 3)) * BST + nb];
            }
            #pragma unroll
            for (int f = 0; f < MF; f++) {
                int mi = lane >> 3, r = lane & 7;
                int row = wm * WM + f * 16 + r + (mi & 1) * 8;
                unsigned addr = sAb + 4u * (unsigned)(row * AST + kk + (mi >> 1) * 4);
                unsigned afr[4];
                ldsm4(afr[0], afr[1], afr[2], afr[3], addr);
                #pragma unroll
                for (int j = 0; j < NF; j++) mma8(acc[f][j], afr, bfr[j]);
            }
        }
    }

    #pragma unroll
    for (int f = 0; f < MF; f++) {
        int r0 = m0 + wm * WM + f * 16 + (lane >> 2);
        int r1 = r0 + 8;
        #pragma unroll
        for (int j = 0; j < NF; j++) {
            int col = n0 + wn * WN + j * 8 + 2 * (lane & 3);
            float b0 = 0.f, b1 = 0.f;
            if (bias) { b0 = bias[col]; b1 = bias[col + 1]; }
            float v0 = acc[f][j][0] + b0, v1 = acc[f][j][1] + b1;
            float v2 = acc[f][j][2] + b0, v3 = acc[f][j][3] + b1;
            if (p.relu) {
                v0 = fmaxf(v0, 0.f); v1 = fmaxf(v1, 0.f);
                v2 = fmaxf(v2, 0.f); v3 = fmaxf(v3, 0.f);
            }
            if (r0 < p.M) {
                if (res) {
                    v0 += p.resScale * res[(size_t)r0 * p.ldres + col];
                    v1 += p.resScale * res[(size_t)r0 * p.ldres + col + 1];
                }
                if (p.roundC) { v0 = tfr(v0); v1 = tfr(v1); }
                *(float2*)&C[(size_t)r0 * p.ldc + col] = make_float2(v0, v1);
                if (Ct) *(float2*)&Ct[(size_t)r0 * p.ldc + col] = make_float2(tfr(v0), tfr(v1));
            }
            if (r1 < p.M) {
                if (res) {
                    v2 += p.resScale * res[(size_t)r1 * p.ldres + col];
                    v3 += p.resScale * res[(size_t)r1 * p.ldres + col + 1];
                }
                if (p.roundC) { v2 = tfr(v2); v3 = tfr(v3); }
                *(float2*)&C[(size_t)r1 * p.ldc + col] = make_float2(v2, v3);
                if (Ct) *(float2*)&Ct[(size_t)r1 * p.ldc + col] = make_float2(tfr(v2), tfr(v3));
            }
        }
    }
}

#define MMA_SMEM(BN) ((3*128*20 + 3*16*((BN)+8)) * 4)

static void mgemm(const float* A, int lda, const float* B, int ldb, float* C, int ldc,
                  int M, int N, int K,
                  const float* bias = nullptr, const float* res = nullptr, int ldres = 0,
                  float resScale = 0.f, int relu = 0,
                  int roundC = 0, float* Ct = nullptr,
                  int z = 1, int zDiv = 1,
                  long long aO=0, long long aI=0, long long bO=0, long long bI=0,
                  long long cO=0, long long cI=0, long long rO=0, long long rI=0,
                  long long biasO=0, int hmode = 0) {
    GP p;
    p.A=A; p.B=B; p.bias=bias; p.res=res; p.C=C; p.Ct=Ct;
    p.lda=lda; p.ldb=ldb; p.ldc=ldc; p.ldres=ldres;
    p.M=M; p.N=N; p.K=K; p.resScale=resScale; p.relu=relu; p.roundC=roundC;
    p.zDiv=zDiv; p.hmode=hmode;
    p.aO=aO; p.aI=aI; p.bO=bO; p.bI=bI; p.cO=cO; p.cI=cI; p.rO=rO; p.rI=rI; p.biasO=biasO;
    if (N % 128 == 0) {
        dim3 grid((M + 127) / 128, N / 128, z);
        mma_k<128, 4><<<grid, 256, MMA_SMEM(128)>>>(p);
    } else {
        dim3 grid((M + 127) / 128, N / 64, z);
        mma_k<64, 2><<<grid, 256, MMA_SMEM(64)>>>(p);
    }
}

// round a float array to tf32 (n multiple of 4)
__global__ void k_round(const float* __restrict__ in, float* __restrict__ out, int n) {
    int i = (blockIdx.x * blockDim.x + threadIdx.x) * 4;
    if (i < n) {
        float4 v = *(const float4*)(in + i);
        *(uint4*)(out + i) = cvt4(v);
    }
}

// ----------------------------- fused flash attention v3 --------------------
// Inputs (g_qkv) pre-rounded to tf32 -> no conversions on Q/K/V loads.
#define KT     64
#define SKST   72
#define SVST   72
#define SPST   68
#define FLASH_SMEM ((64*SKST + 64*SVST + 128*SPST) * 4)

__global__ __launch_bounds__(256, 2) void k_flash() {
    extern __shared__ unsigned sm[];
    unsigned* sK = sm;
    unsigned* sV = sK + 64*SKST;
    unsigned* sP = sV + 64*SVST;

    int tid = threadIdx.x, lane = tid & 31, w = tid >> 5;
    int m0 = blockIdx.x * 128;
    int bh = blockIdx.y; int h = bh & 7, b = bh >> 3;
    const float* qbase = g_qkv + (size_t)(b * LL) * QKVD + h * 192;

    unsigned sPb = (unsigned)__cvta_generic_to_shared(sP);
    int mi = lane >> 3, rr = lane & 7;
    int arow = 16*w + rr + (mi & 1) * 8;

    // ---- stage Q tile through sP (raw copy; already tf32), pull to regs ----
    {
        int row = tid >> 1, half = tid & 1;
        const unsigned* src = (const unsigned*)(qbase + (size_t)(m0 + row) * QKVD) + half * 32;
        unsigned* dst = sP + row * SPST + half * 32;
        #pragma unroll
        for (int c = 0; c < 8; c++)
            *(uint4*)(dst + 4*c) = *(const uint4*)(src + 4*c);
    }
    __syncthreads();
    unsigned qf[8][4];
    #pragma unroll
    for (int kc = 0; kc < 8; kc++)
        ldsm4(qf[kc][0], qf[kc][1], qf[kc][2], qf[kc][3],
              sPb + 4u * (unsigned)(arow * SPST + kc*8 + (mi >> 1) * 4));
    __syncthreads();

    float accO[8][4];
    #pragma unroll
    for (int j = 0; j < 8; j++)
        #pragma unroll
        for (int q = 0; q < 4; q++) accO[j][q] = 0.f;
    float m0r = -INFINITY, m1r = -INFINITY, l0r = 0.f, l1r = 0.f;

    const unsigned* pmr0 = g_pm + ((size_t)bh * LL + m0 + 16*w + (lane >> 2)) * 16;
    const unsigned* pmr1 = pmr0 + 8 * 16;

    for (int kt = 0; kt < 8; kt++) {
        __syncthreads();
        {
            int key = tid >> 2, quarter = tid & 3;
            const unsigned* ks = (const unsigned*)(qbase + (size_t)(kt*KT + key) * QKVD) + 64 + quarter*16;
            #pragma unroll
            for (int c = 0; c < 4; c++) {
                uint4 v = *(const uint4*)(ks + 4*c);
                int d = quarter*16 + 4*c;
                sK[(d+0)*SKST + key] = v.x;
                sK[(d+1)*SKST + key] = v.y;
                sK[(d+2)*SKST + key] = v.z;
                sK[(d+3)*SKST + key] = v.w;
            }
            const unsigned* vs = (const unsigned*)(qbase + (size_t)(kt*KT + key) * QKVD) + 128 + quarter*16;
            unsigned* vd = sV + key * SVST + quarter*16;
            #pragma unroll
            for (int c = 0; c < 4; c++)
                *(uint4*)(vd + 4*c) = *(const uint4*)(vs + 4*c);
        }
        __syncthreads();

        float S[8][4];
        #pragma unroll
        for (int nt = 0; nt < 8; nt++)
            #pragma unroll
            for (int q = 0; q < 4; q++) S[nt][q] = 0.f;
        #pragma unroll
        for (int kc = 0; kc < 8; kc++) {
            #pragma unroll
            for (int nt = 0; nt < 8; nt++) {
                unsigned bb[2];
                int nb = nt*8 + (lane >> 2);
                bb[0] = sK[(kc*8     + (lane & 3)) * SKST + nb];
                bb[1] = sK[(kc*8 + 4 + (lane & 3)) * SKST + nb];
                mma8(S[nt], qf[kc], bb);
            }
        }

        uint2 mw0 = *(const uint2*)(pmr0 + kt*2);
        uint2 mw1 = *(const uint2*)(pmr1 + kt*2);
        unsigned q0[2] = {mw0.x, mw0.y};
        unsigned q1[2] = {mw1.x, mw1.y};
        float rm0 = -INFINITY, rm1 = -INFINITY;
        #pragma unroll
        for (int nt = 0; nt < 8; nt++) {
            int j0 = nt*8 + 2*(lane & 3), j1 = j0 + 1;
            S[nt][0] = ((q0[j0>>5] >> (j0&31)) & 1u) ? S[nt][0]*0.125f : -INFINITY;
            S[nt][1] = ((q0[j1>>5] >> (j1&31)) & 1u) ? S[nt][1]*0.125f : -INFINITY;
            S[nt][2] = ((q1[j0>>5] >> (j0&31)) & 1u) ? S[nt][2]*0.125f : -INFINITY;
            S[nt][3] = ((q1[j1>>5] >> (j1&31)) & 1u) ? S[nt][3]*0.125f : -INFINITY;
            rm0 = fmaxf(rm0, fmaxf(S[nt][0], S[nt][1]));
            rm1 = fmaxf(rm1, fmaxf(S[nt][2], S[nt][3]));
        }
        rm0 = fmaxf(rm0, __shfl_xor_sync(0xffffffffu, rm0, 1));
        rm0 = fmaxf(rm0, __shfl_xor_sync(0xffffffffu, rm0, 2));
        rm1 = fmaxf(rm1, __shfl_xor_sync(0xffffffffu, rm1, 1));
        rm1 = fmaxf(rm1, __shfl_xor_sync(0xffffffffu, rm1, 2));

        float mn0 = fmaxf(m0r, rm0), mn1 = fmaxf(m1r, rm1);
        float a0 = __expf(m0r - mn0), a1 = __expf(m1r - mn1);
        m0r = mn0; m1r = mn1;

        int prow0 = 16*w + (lane >> 2), prow1 = prow0 + 8;
        float rs0 = 0.f, rs1 = 0.f;
        #pragma unroll
        for (int nt = 0; nt < 8; nt++) {
            int j0 = nt*8 + 2*(lane & 3);
            float p00 = __expf(S[nt][0] - mn0), p01 = __expf(S[nt][1] - mn0);
            float p10 = __expf(S[nt][2] - mn1), p11 = __expf(S[nt][3] - mn1);
            rs0 += p00 + p01; rs1 += p10 + p11;
            sP[prow0*SPST + j0]     = f2tf(p00);
            sP[prow0*SPST + j0 + 1] = f2tf(p01);
            sP[prow1*SPST + j0]     = f2tf(p10);
            sP[prow1*SPST + j0 + 1] = f2tf(p11);
        }
        rs0 += __shfl_xor_sync(0xffffffffu, rs0, 1);
        rs0 += __shfl_xor_sync(0xffffffffu, rs0, 2);
        rs1 += __shfl_xor_sync(0xffffffffu, rs1, 1);
        rs1 += __shfl_xor_sync(0xffffffffu, rs1, 2);
        l0r = l0r * a0 + rs0;
        l1r = l1r * a1 + rs1;

        #pragma unroll
        for (int j = 0; j < 8; j++) {
            accO[j][0] *= a0; accO[j][1] *= a0;
            accO[j][2] *= a1; accO[j][3] *= a1;
        }
        __syncwarp();

        #pragma unroll
        for (int kc = 0; kc < 8; kc++) {
            unsigned pf[4];
            ldsm4(pf[0], pf[1], pf[2], pf[3],
                  sPb + 4u * (unsigned)(arow * SPST + kc*8 + (mi >> 1) * 4));
            #pragma unroll
            for (int nt = 0; nt < 8; nt++) {
                unsigned bb[2];
                int nb = nt*8 + (lane >> 2);
                bb[0] = sV[(kc*8     + (lane & 3)) * SVST + nb];
                bb[1] = sV[(kc*8 + 4 + (lane & 3)) * SVST + nb];
                mma8(accO[nt], pf, bb);
            }
        }
    }

    // epilogue: O /= l, store tf32-rounded (feeds attn-out GEMM only)
    float inv0 = 1.f / l0r, inv1 = 1.f / l1r;
    int r0 = m0 + 16*w + (lane >> 2), r1 = r0 + 8;
    float* o0 = g_o + (size_t)(b*LL + r0) * NHID + h*64;
    float* o1 = g_o + (size_t)(b*LL + r1) * NHID + h*64;
    #pragma unroll
    for (int nt = 0; nt < 8; nt++) {
        int col = nt*8 + 2*(lane & 3);
        *(float2*)(o0 + col) = make_float2(tfr(accO[nt][0]*inv0), tfr(accO[nt][1]*inv0));
        *(float2*)(o1 + col) = make_float2(tfr(accO[nt][2]*inv1), tfr(accO[nt][3]*inv1));
    }
}

// pack mask (int32 bool, layout [b][i][h][j]) -> bits [b][h][i][j/32]
__global__ void k_packmask(const int* __restrict__ mask) {
    int row = blockIdx.x * 8 + (threadIdx.x >> 5);
    int lane = threadIdx.x & 31;
    const int* mr = mask + (size_t)row * LL;
    int b_i = row >> 3, h = row & 7;
    int b = b_i >> 9, i = b_i & 511;
    unsigned* out = g_pm + (((size_t)(b*HEADS + h) * LL + i) << 4);
    #pragma unroll
    for (int wd = 0; wd < 16; wd++) {
        unsigned bits = __ballot_sync(0xffffffffu, mr[wd*32 + lane] != 0);
        if (lane == 0) out[wd] = bits;
    }
}

// ----------------------------- small FFMA GEMM (tiny M=1 cases) ------------
__global__ void gemm1_k(GP p) {
    int zo = blockIdx.z;
    const float* A = p.A + zo * p.aO;
    const float* B = p.B + zo * p.bO;
    float* C = p.C + zo * p.cO;
    const float* bias = p.bias ? p.bias + zo * p.biasO : nullptr;
    int n = blockIdx.x * 64 + threadIdx.x;
    if (n >= p.N) return;
    float s = 0.f;
    for (int k = 0; k < p.K; k++) s += A[k] * B[(size_t)k * p.ldb + n];
    if (bias) s += bias[n];
    C[n] = s;
}

// ----------------------------- small kernels -------------------------------
__global__ void k_embed(const float* __restrict__ emb, const float* __restrict__ pos,
                        const int* __restrict__ idxs) {
    int tok = blockIdx.x;
    int b = tok >> 9, s = tok & 511;
    int id = (s == 0) ? 0 : idxs[b*SS + s - 1];
    const float4* e  = (const float4*)(emb + (size_t)id * NHID);
    const float4* pr = (const float4*)(pos + (size_t)s  * NHID);
    float4* hr  = (float4*)(g_h  + (size_t)tok * NHID);
    uint4*  hrt = (uint4*) (g_ht + (size_t)tok * NHID);
    int t = threadIdx.x;
    float4 a = e[t], c = pr[t];
    float4 v = make_float4(a.x+c.x, a.y+c.y, a.z+c.z, a.w+c.w);
    hr[t] = v;
    hrt[t] = cvt4(v);
}

__global__ void k_ln_add(float* __restrict__ out, const float* __restrict__ inp,
                         const float* __restrict__ base, int hgMap,
                         const float* __restrict__ gw, const float* __restrict__ bw,
                         float* __restrict__ outT) {
    int n = blockIdx.x;
    const float* xr = inp + (size_t)n * NHID;
    size_t brow;
    if (hgMap) { int b = n / SS, s = n % SS; brow = ((size_t)(b*LL + s + 1)) * NHID; }
    else brow = (size_t)n * NHID;
    int t = threadIdx.x;  // 128
    float x[4];
    #pragma unroll
    for (int i = 0; i < 4; i++) x[i] = xr[t + i*128];
    __shared__ float red[128];
    red[t] = x[0]+x[1]+x[2]+x[3]; __syncthreads();
    for (int s = 64; s > 0; s >>= 1) { if (t < s) red[t] += red[t+s]; __syncthreads(); }
    float mu = red[0] * (1.f/512.f); __syncthreads();
    float d[4], vs = 0.f;
    #pragma unroll
    for (int i = 0; i < 4; i++) { d[i] = x[i] - mu; vs += d[i]*d[i]; }
    red[t] = vs; __syncthreads();
    for (int s = 64; s > 0; s >>= 1) { if (t < s) red[t] += red[t+s]; __syncthreads(); }
    float inv = rsqrtf(red[0] * (1.f/512.f) + 1e-5f);
    #pragma unroll
    for (int i = 0; i < 4; i++) {
        int c = t + i*128;
        float v = base[brow + c] + d[i]*inv*gw[c] + bw[c];
        out[(size_t)n*NHID + c] = v;
        if (outT) outT[(size_t)n*NHID + c] = tfr(v);
    }
}

__global__ void k_zg(float* __restrict__ dout) {
    int b = blockIdx.x; int t = threadIdx.x;
    #pragma unroll
    for (int i = 0; i < 4; i++) {
        int c = t + i*128;
        dout[(size_t)NNODE*NHID + b*NHID + c] = g_h[((size_t)b*LL) * NHID + c];
    }
}

__global__ void k_copyxf() {
    int n = blockIdx.x;
    int b = n / SS, s = n % SS;
    const float4* src = (const float4*)(g_h + ((size_t)(b*LL + s + 1)) * NHID);
    float4* dst = (float4*)(g_xf + (size_t)n * NHID);
    dst[threadIdx.x] = src[threadIdx.x];
}

__global__ void k_zero_ints() {
    int i = blockIdx.x*blockDim.x + threadIdx.x;
    if (i < 2*NNODE) { g_ind[i] = 0; g_outd[i] = 0; g_cur[i] = 0; }
}

__global__ void k_count(const int* __restrict__ src, const int* __restrict__ dst, int gi) {
    int e = blockIdx.x*blockDim.x + threadIdx.x;
    if (e < EE) {
        atomicAdd(&g_ind [gi*NNODE + dst[e]], 1);
        atomicAdd(&g_outd[gi*NNODE + src[e]], 1);
    }
}

__global__ void k_scan(int gi) {
    __shared__ int sh[1024];
    int t = threadIdx.x;
    int base = gi * NNODE;
    int loc[8]; int sum = 0;
    #pragma unroll
    for (int i = 0; i < 8; i++) {
        int idx = t*8 + i;
        int v = (idx < NNODE) ? g_ind[base + idx] : 0;
        loc[i] = sum; sum += v;
    }
    sh[t] = sum; __syncthreads();
    for (int d = 1; d < 1024; d <<= 1) {
        int v = (t >= d) ? sh[t-d] : 0; __syncthreads();
        sh[t] += v; __syncthreads();
    }
    int pre = (t > 0) ? sh[t-1] : 0;
    #pragma unroll
    for (int i = 0; i < 8; i++) {
        int idx = t*8 + i;
        if (idx < NNODE) g_off[base + idx] = pre + loc[i];
    }
}

__global__ void k_scatter(const int* __restrict__ src, const int* __restrict__ dst, int gi) {
    int e = blockIdx.x*blockDim.x + threadIdx.x;
    if (e < EE) {
        int d = dst[e];
        int p = g_off[gi*NNODE + d] + atomicAdd(&g_cur[gi*NNODE + d], 1);
        g_csr[gi*EE + p] = src[e];
    }
}

__global__ void k_scales() {
    int i = blockIdx.x*blockDim.x + threadIdx.x;
    if (i < 2*NNODE) {
        float in = (float)g_ind[i], od = (float)g_outd[i];
        g_sin [i] = rsqrtf(fmaxf(in, 1.f));
        g_sout[i] = rsqrtf(fmaxf(od, 1.f));
        g_inv1[i] = 1.f / (in + 1.f);
    }
}

__global__ void k_prop_sage(const float* __restrict__ x, float* __restrict__ out, int gi) {
    int wid = blockIdx.x * (blockDim.x >> 5) + (threadIdx.x >> 5);
    if (wid >= NNODE) return;
    int lane = threadIdx.x & 31;
    const float4* xr = (const float4*)(x + (size_t)wid * NHID);
    float4 a0 = xr[lane], a1 = xr[lane+32], a2 = xr[lane+64], a3 = xr[lane+96];
    int s = g_off[gi*NNODE + wid], e = s + g_ind[gi*NNODE + wid];
    const int* csr = g_csr + gi*EE;
    for (int j = s; j < e; j++) {
        int sn = csr[j];
        const float4* sr = (const float4*)(x + (size_t)sn * NHID);
        float4 v;
        v = sr[lane];    a0.x+=v.x; a0.y+=v.y; a0.z+=v.z; a0.w+=v.w;
        v = sr[lane+32]; a1.x+=v.x; a1.y+=v.y; a1.z+=v.z; a1.w+=v.w;
        v = sr[lane+64]; a2.x+=v.x; a2.y+=v.y; a2.z+=v.z; a2.w+=v.w;
        v = sr[lane+96]; a3.x+=v.x; a3.y+=v.y; a3.z+=v.z; a3.w+=v.w;
    }
    float sc = g_inv1[gi*NNODE + wid];
    float4* o = (float4*)(out + (size_t)wid * NHID);
    a0.x*=sc; a0.y*=sc; a0.z*=sc; a0.w*=sc; o[lane]    = a0;
    a1.x*=sc; a1.y*=sc; a1.z*=sc; a1.w*=sc; o[lane+32] = a1;
    a2.x*=sc; a2.y*=sc; a2.z*=sc; a2.w*=sc; o[lane+64] = a2;
    a3.x*=sc; a3.y*=sc; a3.z*=sc; a3.w*=sc; o[lane+96] = a3;
}

__device__ __forceinline__ float4 r4(float4 v) {
    return make_float4(tfr(v.x), tfr(v.y), tfr(v.z), tfr(v.w));
}

// T (tf32-rounded) = sum_in s_out[src]*Q[src];  tvec = sum_in s_out[src]
__global__ void k_prop_gc(const float* __restrict__ q, float* __restrict__ outT, int gi) {
    int wid = blockIdx.x * (blockDim.x >> 5) + (threadIdx.x >> 5);
    if (wid >= NNODE) return;
    int lane = threadIdx.x & 31;
    float4 a0 = make_float4(0,0,0,0), a1 = a0, a2 = a0, a3 = a0;
    float ts = 0.f;
    int s = g_off[gi*NNODE + wid], e = s + g_ind[gi*NNODE + wid];
    const int* csr = g_csr + gi*EE;
    for (int j = s; j < e; j++) {
        int sn = csr[j];
        float so = g_sout[gi*NNODE + sn];
        ts += so;
        const float4* sr = (const float4*)(q + (size_t)sn * NHID);
        float4 v;
        v = sr[lane];    a0.x+=v.x*so; a0.y+=v.y*so; a0.z+=v.z*so; a0.w+=v.w*so;
        v = sr[lane+32]; a1.x+=v.x*so; a1.y+=v.y*so; a1.z+=v.z*so; a1.w+=v.w*so;
        v = sr[lane+64]; a2.x+=v.x*so; a2.y+=v.y*so; a2.z+=v.z*so; a2.w+=v.w*so;
        v = sr[lane+96]; a3.x+=v.x*so; a3.y+=v.y*so; a3.z+=v.z*so; a3.w+=v.w*so;
    }
    float4* o = (float4*)(outT + (size_t)wid * NHID);
    o[lane] = r4(a0); o[lane+32] = r4(a1); o[lane+64] = r4(a2); o[lane+96] = r4(a3);
    if (lane == 0) g_tvec[gi*NNODE + wid] = ts;
}

__global__ void k_xcepi(const float* __restrict__ gc3b) {
    int n = blockIdx.x; int c = threadIdx.x;
    int g = c_pat[c >> 6];
    float si = g_sin[g*NNODE + n], tv = g_tvec[g*NNODE + n];
    size_t idx = (size_t)n*NHID + c;
    g_xc[idx] = si * g_xc[idx] + si * tv * g_dcat[c] + gc3b[c];
}

// ----------------------------- host orchestration --------------------------
#define SYM(name, var) { void* _p; cudaGetSymbolAddress(&_p, name); var = (float*)_p; }

extern "C" void kernel_launch(void* const* d_in, const int* in_sizes, int n_in,
                              void* d_out, int out_size) {
    const float* in_embed  = (const float*)d_in[0];
    const float* pos_embed = (const float*)d_in[1];
    const float* qkv_w     = (const float*)d_in[2];
    const float* qkv_b     = (const float*)d_in[3];
    const float* attn_w    = (const float*)d_in[4];
    const float* attn_b    = (const float*)d_in[5];
    const float* ff1_w     = (const float*)d_in[6];
    const float* ff1_b     = (const float*)d_in[7];
    const float* ff2_w     = (const float*)d_in[8];
    const float* ff2_b     = (const float*)d_in[9];
    const float* sage1_w   = (const float*)d_in[10];
    const float* sage1_b   = (const float*)d_in[11];
    const float* sage2_w   = (const float*)d_in[12];
    const float* sage2_b   = (const float*)d_in[13];
    const float* gc3_w     = (const float*)d_in[14];
    const float* gc3_b     = (const float*)d_in[15];
    const float* gff1_w    = (const float*)d_in[16];
    const float* gff1_b    = (const float*)d_in[17];
    const float* gff2_w    = (const float*)d_in[18];
    const float* gff2_b    = (const float*)d_in[19];
    const float* ln_g      = (const float*)d_in[20];
    const float* ln_b      = (const float*)d_in[21];
    const int*   in_idxs   = (const int*)d_in[22];
    const int*   mask      = (const int*)d_in[23];   // bool marshalled as int32
    const int*   gt_src    = (const int*)d_in[24];
    const int*   gt_dst    = (const int*)d_in[25];
    const int*   at_src    = (const int*)d_in[26];
    const int*   at_dst    = (const int*)d_in[27];

    float *h, *ht, *qkv, *o, *x, *xt, *ff, *xf, *P, *Q, *T, *xc, *xg, *xgt, *fg;
    float *Mb, *Nc, *cc, *dc;
    float *qkvw_r, *attnw_r, *ff1w_r, *ff2w_r, *s1w_r, *s2w_r, *gc3w_r, *gff1w_r, *gff2w_r;
    SYM(g_h, h); SYM(g_ht, ht); SYM(g_qkv, qkv); SYM(g_o, o); SYM(g_x, x); SYM(g_xt, xt);
    SYM(g_ff, ff); SYM(g_xf, xf); SYM(g_P, P); SYM(g_Q, Q); SYM(g_T, T); SYM(g_xc, xc);
    SYM(g_xg, xg); SYM(g_xgt, xgt); SYM(g_fg, fg);
    SYM(g_M, Mb); SYM(g_Ncat, Nc); SYM(g_ccat, cc); SYM(g_dcat, dc);
    SYM(g_qkvw_r, qkvw_r); SYM(g_attnw_r, attnw_r); SYM(g_ff1w_r, ff1w_r);
    SYM(g_ff2w_r, ff2w_r); SYM(g_s1w_r, s1w_r); SYM(g_s2w_r, s2w_r);
    SYM(g_gc3w_r, gc3w_r); SYM(g_gff1w_r, gff1w_r); SYM(g_gff2w_r, gff2w_r);

    static int smemSet = 0;
    if (!smemSet) {
        cudaFuncSetAttribute(k_flash, cudaFuncAttributeMaxDynamicSharedMemorySize, FLASH_SMEM);
        cudaFuncSetAttribute(mma_k<128,4>, cudaFuncAttributeMaxDynamicSharedMemorySize, MMA_SMEM(128));
        cudaFuncSetAttribute(mma_k<64,2>,  cudaFuncAttributeMaxDynamicSharedMemorySize, MMA_SMEM(64));
        smemSet = 1;
    }

    // ---- weight pre-rounding ----
    #define RND(src, dst, n) k_round<<<((n)/4 + 255)/256, 256>>>(src, dst, n)
    RND(qkv_w,  qkvw_r,  4*NHID*QKVD);
    RND(attn_w, attnw_r, 4*NHID*NHID);
    RND(ff1_w,  ff1w_r,  4*NHID*FFD);
    RND(ff2_w,  ff2w_r,  4*FFD*NHID);
    RND(sage1_w, s1w_r,  HEADS*NHID*NHID);
    RND(sage2_w, s2w_r,  HEADS*NHID*NHID);
    RND(gc3_w,  gc3w_r,  HEADS*NHID*64);
    RND(gff1_w, gff1w_r, NHID*NHID);
    RND(gff2_w, gff2w_r, NHID*NHID);

    // ---- embedding + mask packing ----
    k_embed<<<NTOK, 128>>>(in_embed, pos_embed, in_idxs);
    k_packmask<<<BB*LL*HEADS/8, 256>>>(mask);

    // ---- transformer layers ----
    for (int l = 0; l < 4; l++) {
        // qkv = round(ht @ W + b)  (rounded: feeds flash only)
        mgemm(ht, NHID, qkvw_r + (size_t)l*NHID*QKVD, QKVD, qkv, QKVD,
              NTOK, QKVD, NHID, qkv_b + l*QKVD, nullptr, 0, 0.f, 0, /*roundC=*/1);
        k_flash<<<dim3(LL/128, BB*HEADS), 256, FLASH_SMEM>>>();
        // x = 2h + (o @ Wout + b); shadow xt rounded
        mgemm(o, NHID, attnw_r + (size_t)l*NHID*NHID, NHID, x, NHID,
              NTOK, NHID, NHID, attn_b + l*NHID, h, NHID, 2.0f, 0, 0, xt);
        // ff = round(relu(xt @ W1 + b1))
        mgemm(xt, NHID, ff1w_r + (size_t)l*NHID*FFD, FFD, ff, FFD,
              NTOK, FFD, NHID, ff1_b + l*FFD, nullptr, 0, 0.f, /*relu=*/1, /*roundC=*/1);
        // h = x + (ff @ W2 + b2); shadow ht rounded
        mgemm(ff, FFD, ff2w_r + (size_t)l*FFD*NHID, NHID, h, NHID,
              NTOK, NHID, FFD, ff2_b + l*NHID, x, NHID, 1.0f, 0, 0, ht);
    }

    // ---- graph preprocessing ----
    k_zero_ints<<<(2*NNODE + 255)/256, 256>>>();
    k_count<<<EE/256, 256>>>(gt_src, gt_dst, 0);
    k_count<<<EE/256, 256>>>(at_src, at_dst, 1);
    k_scan<<<1, 1024>>>(0);
    k_scan<<<1, 1024>>>(1);
    k_scatter<<<EE/256, 256>>>(gt_src, gt_dst, 0);
    k_scatter<<<EE/256, 256>>>(at_src, at_dst, 1);
    k_scales<<<(2*NNODE + 255)/256, 256>>>();
    k_copyxf<<<NNODE, 128>>>();

    // ---- propagations (3 per graph; T written tf32-rounded) ----
    int propBlocks = (NNODE + 7) / 8;
    for (int g = 0; g < 2; g++) {
        k_prop_sage<<<propBlocks, 256>>>(xf, P, g);
        k_prop_sage<<<propBlocks, 256>>>(P,  Q, g);
        k_prop_gc  <<<propBlocks, 256>>>(Q,  T + (size_t)g*NNODE*NHID, g);
    }

    // ---- collapse per-head weights: M_i = W1 W2 (rounded), N_i = M W3 (rounded) ----
    mgemm(s1w_r, NHID, s2w_r, NHID, Mb, NHID, NHID, NHID, NHID,
          nullptr, nullptr, 0, 0.f, 0, /*roundC=*/1, nullptr, HEADS, 1,
          (long long)NHID*NHID, 0, (long long)NHID*NHID, 0, (long long)NHID*NHID, 0);
    mgemm(Mb, NHID, gc3w_r, 64, Nc, 64, NHID, 64, NHID,
          nullptr, nullptr, 0, 0.f, 0, /*roundC=*/1, nullptr, HEADS, 1,
          (long long)NHID*NHID, 0, (long long)NHID*64, 0, (long long)NHID*64, 0);
    {
        GP p; p.A=sage1_b; p.B=sage2_w; p.bias=sage2_b; p.res=nullptr; p.C=cc; p.Ct=nullptr;
        p.lda=NHID; p.ldb=NHID; p.ldc=NHID; p.ldres=0;
        p.M=1; p.N=NHID; p.K=NHID; p.resScale=0; p.relu=0; p.roundC=0; p.zDiv=1; p.hmode=0;
        p.aO=NHID; p.bO=(long long)NHID*NHID; p.cO=NHID; p.biasO=NHID;
        p.aI=p.bI=p.cI=p.rO=p.rI=0;
        gemm1_k<<<dim3((NHID+63)/64,1,HEADS), 64>>>(p);
    }
    {
        GP p; p.A=cc; p.B=gc3_w; p.bias=nullptr; p.res=nullptr; p.C=dc; p.Ct=nullptr;
        p.lda=NHID; p.ldb=64; p.ldc=64; p.ldres=0;
        p.M=1; p.N=64; p.K=NHID; p.resScale=0; p.relu=0; p.roundC=0; p.zDiv=1; p.hmode=0;
        p.aO=NHID; p.bO=(long long)NHID*64; p.cO=64; p.biasO=0;
        p.aI=p.bI=p.cI=p.rO=p.rI=0;
        gemm1_k<<<dim3(1,1,HEADS), 64>>>(p);
    }

    // ---- xc per head: one launch, A = T[(z>>1)&1], via hmode ----
    mgemm(T, NHID, Nc, 64, xc, NHID,
          NNODE, 64, NHID, nullptr, nullptr, 0, 0.f, 0, 0, nullptr,
          HEADS, 1,
          0, (long long)NNODE*NHID,
          (long long)NHID*64, 0,
          64, 0, 0, 0, 0, /*hmode=*/1);
    k_xcepi<<<NNODE, 512>>>(gc3_b);

    // ---- final: x = hg + LN(xc); ff = relu(x W1+b) W2 + b; zbar = x + LN(ff) ----
    k_ln_add<<<NNODE, 128>>>(xg, xc, h, /*hgMap=*/1, ln_g, ln_b, xgt);
    mgemm(xgt, NHID, gff1w_r, NHID, fg, NHID, NNODE, NHID, NHID, gff1_b,
          nullptr, 0, 0.f, /*relu=*/1, /*roundC=*/1);
    mgemm(fg, NHID, gff2w_r, NHID, xc, NHID, NNODE, NHID, NHID, gff2_b);
    k_ln_add<<<NNODE, 128>>>((float*)d_out, xc, xg, /*hgMap=*/0, ln_g, ln_b, nullptr);

    // ---- zg ----
    if (out_size >= NNODE*NHID + BB*NHID)
        k_zg<<<BB, 128>>>((float*)d_out);
}

// round 8
// speedup vs baseline: 1.0223x; 1.0223x over previous
#include <cuda_runtime.h>
#include <math.h>
#include <stdint.h>

#define NHID   512
#define HEADS  8
#define NKD    64
#define BB     16
#define SS     511
#define LL     512
#define NNODE  8176      // BB*SS
#define NTOK   8192      // BB*LL
#define EE     131072
#define QKVD   1536
#define FFD    2048

// ----------------------------- scratch (device globals; no allocation) -----
__device__ float g_h   [NTOK*NHID];
__device__ float g_qkv [NTOK*QKVD];
__device__ float g_o   [NTOK*NHID];
__device__ float g_x   [NTOK*NHID];
__device__ float g_ff  [NTOK*FFD];
__device__ float g_xf  [NNODE*NHID];
__device__ float g_P   [NNODE*NHID];
__device__ float g_Q   [NNODE*NHID];
__device__ float g_T   [2*NNODE*NHID];
__device__ float g_xc  [NNODE*NHID];
__device__ float g_xg  [NNODE*NHID];
__device__ float g_fg  [NNODE*NHID];
__device__ float g_M   [HEADS*NHID*NHID];
__device__ float g_Ncat[HEADS*NHID*64];
__device__ float g_ccat[HEADS*NHID];
__device__ float g_dcat[HEADS*64];
__device__ float g_tvec[2*NNODE];
__device__ float g_sin [2*NNODE];
__device__ float g_sout[2*NNODE];
__device__ float g_inv1[2*NNODE];
__device__ int   g_ind [2*NNODE];
__device__ int   g_outd[2*NNODE];
__device__ int   g_off [2*NNODE];
__device__ int   g_cur [2*NNODE];
__device__ int   g_csr [2*EE];
__device__ unsigned g_pm[(size_t)BB*HEADS*LL*(LL/32)];   // packed mask bits (4 MB)

__constant__ int c_pat[8] = {0,0,1,1,0,0,1,1};

// ----------------------------- common GEMM param block ---------------------
struct GP {
    const float *A, *B, *bias, *res;
    float *C;
    int lda, ldb, ldc, ldres;
    int M, N, K;
    float resScale;
    int relu;
    int zDiv;
    int hmode;     // per-head graph GEMM mode: A selected by (z>>1)&1
    long long aO, aI, bO, bI, cO, cI, rO, rI, biasO;
};

// ----------------------------- tf32 helpers --------------------------------
__device__ __forceinline__ unsigned f2tf(float f) {
    unsigned u; asm("cvt.rna.tf32.f32 %0, %1;" : "=r"(u) : "f"(f)); return u;
}
__device__ __forceinline__ uint4 cvt4(float4 v) {
    uint4 r; r.x=f2tf(v.x); r.y=f2tf(v.y); r.z=f2tf(v.z); r.w=f2tf(v.w); return r;
}
__device__ __forceinline__ void ldsm4(unsigned &d0, unsigned &d1, unsigned &d2, unsigned &d3,
                                      unsigned addr) {
    asm volatile("ldmatrix.sync.aligned.m8n8.x4.shared.b16 {%0,%1,%2,%3}, [%4];"
                 : "=r"(d0), "=r"(d1), "=r"(d2), "=r"(d3) : "r"(addr));
}
__device__ __forceinline__ void mma8(float* c, const unsigned* a, const unsigned* b) {
    asm volatile(
        "mma.sync.aligned.m16n8k8.row.col.f32.tf32.tf32.f32 "
        "{%0,%1,%2,%3}, {%4,%5,%6,%7}, {%8,%9}, {%0,%1,%2,%3};"
        : "+f"(c[0]), "+f"(c[1]), "+f"(c[2]), "+f"(c[3])
        : "r"(a[0]), "r"(a[1]), "r"(a[2]), "r"(a[3]), "r"(b[0]), "r"(b[1]));
}

// ----------------------------- tf32 tensor-core GEMM (2-stage) -------------
// CTA tile 128 x BN, 8 warps, K-slice 16, double-buffered smem.
// __launch_bounds__(256, 2): cap regs at 128 -> 2 CTAs/SM (4 warps/SMSP).
template<int BN, int WGN, bool TB>
__global__ __launch_bounds__(256, 2) void mma_k(GP p) {
    constexpr int WGM = 8 / WGN;
    constexpr int WM  = 128 / WGM;
    constexpr int WN  = BN / WGN;
    constexpr int MF  = WM / 16;
    constexpr int NF  = WN / 8;
    constexpr int AST = 20;        // A smem row stride (words), conflict-free ldmatrix
    constexpr int BST = BN + 8;    // B smem row stride: =8 mod 32 -> conflict-free LDS

    __shared__ unsigned sA[2][128 * AST];
    __shared__ unsigned sB[2][16 * BST];

    const float *A, *B; float *C;
    const float *bias = nullptr, *res = nullptr;
    if (p.hmode) {
        int hd = blockIdx.z;
        A = p.A + (((hd >> 1) & 1) ? p.aI : 0);
        B = p.B + (size_t)hd * p.bO;
        C = p.C + (size_t)hd * p.cO;
    } else {
        int zo = blockIdx.z / p.zDiv, zi = blockIdx.z % p.zDiv;
        A = p.A + zo * p.aO + zi * p.aI;
        B = p.B + zo * p.bO + zi * p.bI;
        C = p.C + zo * p.cO + zi * p.cI;
        if (p.bias) bias = p.bias + zo * p.biasO;
        if (p.res)  res  = p.res + zo * p.rO + zi * p.rI;
    }

    int tid = threadIdx.x, lane = tid & 31, warp = tid >> 5;
    int wm = warp / WGN, wn = warp % WGN;
    int m0 = blockIdx.x * 128, n0 = blockIdx.y * BN;

    int ar = tid >> 1, ak = (tid & 1) * 8;
    bool aval = (m0 + ar) < p.M;
    const float* aptr = A + (size_t)(m0 + ar) * p.lda + ak;

    const float* bptr;
    int bn_t = 0, bk_t = 0, bn4_t = 0;
    if (TB) {
        bn_t = tid >> 1; bk_t = (tid & 1) * 8;
        bptr = B + (size_t)(n0 + bn_t) * p.ldb + bk_t;
    } else if (BN == 128) {
        bk_t = tid >> 5; bn4_t = (tid & 31) * 4;
        bptr = B + (size_t)bk_t * p.ldb + n0 + bn4_t;
    } else {
        bk_t = tid >> 4; bn4_t = (tid & 15) * 4;
        bptr = B + (size_t)bk_t * p.ldb + n0 + bn4_t;
    }

    float acc[MF][NF][4];
    #pragma unroll
    for (int f = 0; f < MF; f++)
        #pragma unroll
        for (int j = 0; j < NF; j++)
            #pragma unroll
            for (int q = 0; q < 4; q++) acc[f][j][q] = 0.f;

    float4 pa0, pa1, pb0, pb1;
    pa0 = pa1 = pb0 = pb1 = make_float4(0.f,0.f,0.f,0.f);

    auto loadRegs = [&](int k0) {
        if (aval) { pa0 = *(const float4*)(aptr + k0); pa1 = *(const float4*)(aptr + k0 + 4); }
        if (TB)             { pb0 = *(const float4*)(bptr + k0); pb1 = *(const float4*)(bptr + k0 + 4); }
        else if (BN == 128) { pb0 = *(const float4*)(bptr + (size_t)k0 * p.ldb);
                              pb1 = *(const float4*)(bptr + (size_t)(k0 + 8) * p.ldb); }
        else                { pb0 = *(const float4*)(bptr + (size_t)k0 * p.ldb); }
    };
    auto storeStage = [&](int s) {
        unsigned* A_ = sA[s];
        unsigned* B_ = sB[s];
        *(uint4*)&A_[ar * AST + ak]     = cvt4(pa0);
        *(uint4*)&A_[ar * AST + ak + 4] = cvt4(pa1);
        if (TB) {
            B_[(bk_t + 0) * BST + bn_t] = f2tf(pb0.x);
            B_[(bk_t + 1) * BST + bn_t] = f2tf(pb0.y);
            B_[(bk_t + 2) * BST + bn_t] = f2tf(pb0.z);
            B_[(bk_t + 3) * BST + bn_t] = f2tf(pb0.w);
            B_[(bk_t + 4) * BST + bn_t] = f2tf(pb1.x);
            B_[(bk_t + 5) * BST + bn_t] = f2tf(pb1.y);
            B_[(bk_t + 6) * BST + bn_t] = f2tf(pb1.z);
            B_[(bk_t + 7) * BST + bn_t] = f2tf(pb1.w);
        } else if (BN == 128) {
            *(uint4*)&B_[bk_t * BST + bn4_t]       = cvt4(pb0);
            *(uint4*)&B_[(bk_t + 8) * BST + bn4_t] = cvt4(pb1);
        } else {
            *(uint4*)&B_[bk_t * BST + bn4_t] = cvt4(pb0);
        }
    };

    // prologue: fill stage 0, prefetch iter 1 into regs
    loadRegs(0);
    storeStage(0);
    if (16 < p.K) loadRegs(16);
    __syncthreads();

    int cur = 0;
    for (int k0 = 0; k0 < p.K; k0 += 16) {
        int nxt = cur ^ 1;
        if (k0 + 16 < p.K) storeStage(nxt);
        if (k0 + 32 < p.K) loadRegs(k0 + 32);

        unsigned sAb = (unsigned)__cvta_generic_to_shared(sA[cur]);
        const unsigned* Bc = sB[cur];
        #pragma unroll
        for (int kk = 0; kk < 16; kk += 8) {
            unsigned bfr[NF][2];
            #pragma unroll
            for (int j = 0; j < NF; j++) {
                int nb = wn * WN + j * 8 + (lane >> 2);
                bfr[j][0] = Bc[(kk + (lane & 3)) * BST + nb];
                bfr[j][1] = Bc[(kk + 4 + (lane & 3)) * BST + nb];
            }
            #pragma unroll
            for (int f = 0; f < MF; f++) {
                int mi = lane >> 3, r = lane & 7;
                int row = wm * WM + f * 16 + r + (mi & 1) * 8;
                unsigned addr = sAb + 4u * (unsigned)(row * AST + kk + (mi >> 1) * 4);
                unsigned afr[4];
                ldsm4(afr[0], afr[1], afr[2], afr[3], addr);
                #pragma unroll
                for (int j = 0; j < NF; j++) mma8(acc[f][j], afr, bfr[j]);
            }
        }
        __syncthreads();
        cur = nxt;
    }

    #pragma unroll
    for (int f = 0; f < MF; f++) {
        int r0 = m0 + wm * WM + f * 16 + (lane >> 2);
        int r1 = r0 + 8;
        #pragma unroll
        for (int j = 0; j < NF; j++) {
            int col = n0 + wn * WN + j * 8 + 2 * (lane & 3);
            float b0 = 0.f, b1 = 0.f;
            if (bias) { b0 = bias[col]; b1 = bias[col + 1]; }
            float v0 = acc[f][j][0] + b0, v1 = acc[f][j][1] + b1;
            float v2 = acc[f][j][2] + b0, v3 = acc[f][j][3] + b1;
            if (p.relu) {
                v0 = fmaxf(v0, 0.f); v1 = fmaxf(v1, 0.f);
                v2 = fmaxf(v2, 0.f); v3 = fmaxf(v3, 0.f);
            }
            if (r0 < p.M) {
                if (res) {
                    v0 += p.resScale * res[(size_t)r0 * p.ldres + col];
                    v1 += p.resScale * res[(size_t)r0 * p.ldres + col + 1];
                }
                *(float2*)&C[(size_t)r0 * p.ldc + col] = make_float2(v0, v1);
            }
            if (r1 < p.M) {
                if (res) {
                    v2 += p.resScale * res[(size_t)r1 * p.ldres + col];
                    v3 += p.resScale * res[(size_t)r1 * p.ldres + col + 1];
                }
                *(float2*)&C[(size_t)r1 * p.ldc + col] = make_float2(v2, v3);
            }
        }
    }
}

static void mgemm(const float* A, int lda, const float* B, int ldb, float* C, int ldc,
                  int M, int N, int K,
                  const float* bias = nullptr, const float* res = nullptr, int ldres = 0,
                  float resScale = 0.f, int relu = 0, int transB = 0,
                  int z = 1, int zDiv = 1,
                  long long aO=0, long long aI=0, long long bO=0, long long bI=0,
                  long long cO=0, long long cI=0, long long rO=0, long long rI=0,
                  long long biasO=0, int hmode = 0) {
    GP p;
    p.A=A; p.B=B; p.bias=bias; p.res=res; p.C=C;
    p.lda=lda; p.ldb=ldb; p.ldc=ldc; p.ldres=ldres;
    p.M=M; p.N=N; p.K=K; p.resScale=resScale; p.relu=relu; p.zDiv=zDiv; p.hmode=hmode;
    p.aO=aO; p.aI=aI; p.bO=bO; p.bI=bI; p.cO=cO; p.cI=cI; p.rO=rO; p.rI=rI; p.biasO=biasO;
    if (transB) {
        dim3 grid((M + 127) / 128, N / 128, z);
        mma_k<128, 4, true><<<grid, 256>>>(p);
    } else if (N % 128 == 0) {
        dim3 grid((M + 127) / 128, N / 128, z);
        mma_k<128, 4, false><<<grid, 256>>>(p);
    } else {
        dim3 grid((M + 127) / 128, N / 64, z);
        mma_k<64, 2, false><<<grid, 256>>>(p);
    }
}

// ----------------------------- fused flash attention v2 --------------------
// grid (L/128, B*H), 256 threads (8 warps), warp owns 16 Q rows.
// Q register-resident; K-tiles of 64 keys. smem 70 KB, 2 CTAs/SM.
#define KT     64
#define SKST   72
#define SVST   72
#define SPST   68
#define FLASH_SMEM ((64*SKST + 64*SVST + 128*SPST) * 4)

__global__ __launch_bounds__(256, 2) void k_flash() {
    extern __shared__ unsigned sm[];
    unsigned* sK = sm;
    unsigned* sV = sK + 64*SKST;
    unsigned* sP = sV + 64*SVST;

    int tid = threadIdx.x, lane = tid & 31, w = tid >> 5;
    int m0 = blockIdx.x * 128;
    int bh = blockIdx.y; int h = bh & 7, b = bh >> 3;
    const float* qbase = g_qkv + (size_t)(b * LL) * QKVD + h * 192;

    unsigned sPb = (unsigned)__cvta_generic_to_shared(sP);
    int mi = lane >> 3, rr = lane & 7;
    int arow = 16*w + rr + (mi & 1) * 8;

    // ---- stage Q tile through sP, then pull fragments into registers ----
    {
        int row = tid >> 1, half = tid & 1;
        const float* src = qbase + (size_t)(m0 + row) * QKVD + half * 32;
        unsigned* dst = sP + row * SPST + half * 32;
        #pragma unroll
        for (int c = 0; c < 8; c++)
            *(uint4*)(dst + 4*c) = cvt4(*(const float4*)(src + 4*c));
    }
    __syncthreads();
    unsigned qf[8][4];
    #pragma unroll
    for (int kc = 0; kc < 8; kc++)
        ldsm4(qf[kc][0], qf[kc][1], qf[kc][2], qf[kc][3],
              sPb + 4u * (unsigned)(arow * SPST + kc*8 + (mi >> 1) * 4));
    __syncthreads();

    float accO[8][4];
    #pragma unroll
    for (int j = 0; j < 8; j++)
        #pragma unroll
        for (int q = 0; q < 4; q++) accO[j][q] = 0.f;
    float m0r = -INFINITY, m1r = -INFINITY, l0r = 0.f, l1r = 0.f;

    const unsigned* pmr0 = g_pm + ((size_t)bh * LL + m0 + 16*w + (lane >> 2)) * 16;
    const unsigned* pmr1 = pmr0 + 8 * 16;

    for (int kt = 0; kt < 8; kt++) {
        __syncthreads();
        {
            int key = tid >> 2, quarter = tid & 3;
            const float* ks = qbase + (size_t)(kt*KT + key) * QKVD + 64 + quarter*16;
            #pragma unroll
            for (int c = 0; c < 4; c++) {
                float4 v = *(const float4*)(ks + 4*c);
                int d = quarter*16 + 4*c;
                sK[(d+0)*SKST + key] = f2tf(v.x);
                sK[(d+1)*SKST + key] = f2tf(v.y);
                sK[(d+2)*SKST + key] = f2tf(v.z);
                sK[(d+3)*SKST + key] = f2tf(v.w);
            }
            const float* vs = qbase + (size_t)(kt*KT + key) * QKVD + 128 + quarter*16;
            unsigned* vd = sV + key * SVST + quarter*16;
            #pragma unroll
            for (int c = 0; c < 4; c++)
                *(uint4*)(vd + 4*c) = cvt4(*(const float4*)(vs + 4*c));
        }
        __syncthreads();

        float S[8][4];
        #pragma unroll
        for (int nt = 0; nt < 8; nt++)
            #pragma unroll
            for (int q = 0; q < 4; q++) S[nt][q] = 0.f;
        #pragma unroll
        for (int kc = 0; kc < 8; kc++) {
            #pragma unroll
            for (int nt = 0; nt < 8; nt++) {
                unsigned bb[2];
                int nb = nt*8 + (lane >> 2);
                bb[0] = sK[(kc*8     + (lane & 3)) * SKST + nb];
                bb[1] = sK[(kc*8 + 4 + (lane & 3)) * SKST + nb];
                mma8(S[nt], qf[kc], bb);
            }
        }

        uint2 mw0 = *(const uint2*)(pmr0 + kt*2);
        uint2 mw1 = *(const uint2*)(pmr1 + kt*2);
        unsigned q0[2] = {mw0.x, mw0.y};
        unsigned q1[2] = {mw1.x, mw1.y};
        float rm0 = -INFINITY, rm1 = -INFINITY;
        #pragma unroll
        for (int nt = 0; nt < 8; nt++) {
            int j0 = nt*8 + 2*(lane & 3), j1 = j0 + 1;
            S[nt][0] = ((q0[j0>>5] >> (j0&31)) & 1u) ? S[nt][0]*0.125f : -INFINITY;
            S[nt][1] = ((q0[j1>>5] >> (j1&31)) & 1u) ? S[nt][1]*0.125f : -INFINITY;
            S[nt][2] = ((q1[j0>>5] >> (j0&31)) & 1u) ? S[nt][2]*0.125f : -INFINITY;
            S[nt][3] = ((q1[j1>>5] >> (j1&31)) & 1u) ? S[nt][3]*0.125f : -INFINITY;
            rm0 = fmaxf(rm0, fmaxf(S[nt][0], S[nt][1]));
            rm1 = fmaxf(rm1, fmaxf(S[nt][2], S[nt][3]));
        }
        rm0 = fmaxf(rm0, __shfl_xor_sync(0xffffffffu, rm0, 1));
        rm0 = fmaxf(rm0, __shfl_xor_sync(0xffffffffu, rm0, 2));
        rm1 = fmaxf(rm1, __shfl_xor_sync(0xffffffffu, rm1, 1));
        rm1 = fmaxf(rm1, __shfl_xor_sync(0xffffffffu, rm1, 2));

        float mn0 = fmaxf(m0r, rm0), mn1 = fmaxf(m1r, rm1);
        float a0 = __expf(m0r - mn0), a1 = __expf(m1r - mn1);
        m0r = mn0; m1r = mn1;

        int prow0 = 16*w + (lane >> 2), prow1 = prow0 + 8;
        float rs0 = 0.f, rs1 = 0.f;
        #pragma unroll
        for (int nt = 0; nt < 8; nt++) {
            int j0 = nt*8 + 2*(lane & 3);
            float p00 = __expf(S[nt][0] - mn0), p01 = __expf(S[nt][1] - mn0);
            float p10 = __expf(S[nt][2] - mn1), p11 = __expf(S[nt][3] - mn1);
            rs0 += p00 + p01; rs1 += p10 + p11;
            sP[prow0*SPST + j0]     = f2tf(p00);
            sP[prow0*SPST + j0 + 1] = f2tf(p01);
            sP[prow1*SPST + j0]     = f2tf(p10);
            sP[prow1*SPST + j0 + 1] = f2tf(p11);
        }
        rs0 += __shfl_xor_sync(0xffffffffu, rs0, 1);
        rs0 += __shfl_xor_sync(0xffffffffu, rs0, 2);
        rs1 += __shfl_xor_sync(0xffffffffu, rs1, 1);
        rs1 += __shfl_xor_sync(0xffffffffu, rs1, 2);
        l0r = l0r * a0 + rs0;
        l1r = l1r * a1 + rs1;

        #pragma unroll
        for (int j = 0; j < 8; j++) {
            accO[j][0] *= a0; accO[j][1] *= a0;
            accO[j][2] *= a1; accO[j][3] *= a1;
        }
        __syncwarp();

        #pragma unroll
        for (int kc = 0; kc < 8; kc++) {
            unsigned pf[4];
            ldsm4(pf[0], pf[1], pf[2], pf[3],
                  sPb + 4u * (unsigned)(arow * SPST + kc*8 + (mi >> 1) * 4));
            #pragma unroll
            for (int nt = 0; nt < 8; nt++) {
                unsigned bb[2];
                int nb = nt*8 + (lane >> 2);
                bb[0] = sV[(kc*8     + (lane & 3)) * SVST + nb];
                bb[1] = sV[(kc*8 + 4 + (lane & 3)) * SVST + nb];
                mma8(accO[nt], pf, bb);
            }
        }
    }

    float inv0 = 1.f / l0r, inv1 = 1.f / l1r;
    int r0 = m0 + 16*w + (lane >> 2), r1 = r0 + 8;
    float* o0 = g_o + (size_t)(b*LL + r0) * NHID + h*64;
    float* o1 = g_o + (size_t)(b*LL + r1) * NHID + h*64;
    #pragma unroll
    for (int nt = 0; nt < 8; nt++) {
        int col = nt*8 + 2*(lane & 3);
        *(float2*)(o0 + col) = make_float2(accO[nt][0]*inv0, accO[nt][1]*inv0);
        *(float2*)(o1 + col) = make_float2(accO[nt][2]*inv1, accO[nt][3]*inv1);
    }
}

// pack mask (int32 bool, layout [b][i][h][j]) -> bits [b][h][i][j/32]
__global__ void k_packmask(const int* __restrict__ mask) {
    int row = blockIdx.x * 8 + (threadIdx.x >> 5);
    int lane = threadIdx.x & 31;
    const int* mr = mask + (size_t)row * LL;
    int b_i = row >> 3, h = row & 7;
    int b = b_i >> 9, i = b_i & 511;
    unsigned* out = g_pm + (((size_t)(b*HEADS + h) * LL + i) << 4);
    #pragma unroll
    for (int wd = 0; wd < 16; wd++) {
        unsigned bits = __ballot_sync(0xffffffffu, mr[wd*32 + lane] != 0);
        if (lane == 0) out[wd] = bits;
    }
}

// ----------------------------- small FFMA GEMM (tiny M=1 cases) ------------
__global__ void gemm1_k(GP p) {
    int zo = blockIdx.z;
    const float* A = p.A + zo * p.aO;
    const float* B = p.B + zo * p.bO;
    float* C = p.C + zo * p.cO;
    const float* bias = p.bias ? p.bias + zo * p.biasO : nullptr;
    int n = blockIdx.x * 64 + threadIdx.x;
    if (n >= p.N) return;
    float s = 0.f;
    for (int k = 0; k < p.K; k++) s += A[k] * B[(size_t)k * p.ldb + n];
    if (bias) s += bias[n];
    C[n] = s;
}

// ----------------------------- small kernels -------------------------------
__global__ void k_embed(const float* __restrict__ emb, const float* __restrict__ pos,
                        const int* __restrict__ idxs) {
    int tok = blockIdx.x;
    int b = tok >> 9, s = tok & 511;
    int id = (s == 0) ? 0 : idxs[b*SS + s - 1];
    const float4* e  = (const float4*)(emb + (size_t)id * NHID);
    const float4* pr = (const float4*)(pos + (size_t)s  * NHID);
    float4* hr = (float4*)(g_h + (size_t)tok * NHID);
    int t = threadIdx.x;
    float4 a = e[t], c = pr[t];
    hr[t] = make_float4(a.x+c.x, a.y+c.y, a.z+c.z, a.w+c.w);
}

__global__ void k_ln_add(float* __restrict__ out, const float* __restrict__ inp,
                         const float* __restrict__ base, int hgMap,
                         const float* __restrict__ gw, const float* __restrict__ bw) {
    int n = blockIdx.x;
    const float* xr = inp + (size_t)n * NHID;
    size_t brow;
    if (hgMap) { int b = n / SS, s = n % SS; brow = ((size_t)(b*LL + s + 1)) * NHID; }
    else brow = (size_t)n * NHID;
    int t = threadIdx.x;  // 128
    float x[4];
    #pragma unroll
    for (int i = 0; i < 4; i++) x[i] = xr[t + i*128];
    __shared__ float red[128];
    red[t] = x[0]+x[1]+x[2]+x[3]; __syncthreads();
    for (int s = 64; s > 0; s >>= 1) { if (t < s) red[t] += red[t+s]; __syncthreads(); }
    float mu = red[0] * (1.f/512.f); __syncthreads();
    float d[4], vs = 0.f;
    #pragma unroll
    for (int i = 0; i < 4; i++) { d[i] = x[i] - mu; vs += d[i]*d[i]; }
    red[t] = vs; __syncthreads();
    for (int s = 64; s > 0; s >>= 1) { if (t < s) red[t] += red[t+s]; __syncthreads(); }
    float inv = rsqrtf(red[0] * (1.f/512.f) + 1e-5f);
    #pragma unroll
    for (int i = 0; i < 4; i++) {
        int c = t + i*128;
        out[(size_t)n*NHID + c] = base[brow + c] + d[i]*inv*gw[c] + bw[c];
    }
}

__global__ void k_zg(float* __restrict__ dout) {
    int b = blockIdx.x; int t = threadIdx.x;
    #pragma unroll
    for (int i = 0; i < 4; i++) {
        int c = t + i*128;
        dout[(size_t)NNODE*NHID + b*NHID + c] = g_h[((size_t)b*LL) * NHID + c];
    }
}

__global__ void k_copyxf() {
    int n = blockIdx.x;
    int b = n / SS, s = n % SS;
    const float4* src = (const float4*)(g_h + ((size_t)(b*LL + s + 1)) * NHID);
    float4* dst = (float4*)(g_xf + (size_t)n * NHID);
    dst[threadIdx.x] = src[threadIdx.x];
}

__global__ void k_zero_ints() {
    int i = blockIdx.x*blockDim.x + threadIdx.x;
    if (i < 2*NNODE) { g_ind[i] = 0; g_outd[i] = 0; g_cur[i] = 0; }
}

__global__ void k_count(const int* __restrict__ src, const int* __restrict__ dst, int gi) {
    int e = blockIdx.x*blockDim.x + threadIdx.x;
    if (e < EE) {
        atomicAdd(&g_ind [gi*NNODE + dst[e]], 1);
        atomicAdd(&g_outd[gi*NNODE + src[e]], 1);
    }
}

__global__ void k_scan(int gi) {
    __shared__ int sh[1024];
    int t = threadIdx.x;
    int base = gi * NNODE;
    int loc[8]; int sum = 0;
    #pragma unroll
    for (int i = 0; i < 8; i++) {
        int idx = t*8 + i;
        int v = (idx < NNODE) ? g_ind[base + idx] : 0;
        loc[i] = sum; sum += v;
    }
    sh[t] = sum; __syncthreads();
    for (int d = 1; d < 1024; d <<= 1) {
        int v = (t >= d) ? sh[t-d] : 0; __syncthreads();
        sh[t] += v; __syncthreads();
    }
    int pre = (t > 0) ? sh[t-1] : 0;
    #pragma unroll
    for (int i = 0; i < 8; i++) {
        int idx = t*8 + i;
        if (idx < NNODE) g_off[base + idx] = pre + loc[i];
    }
}

__global__ void k_scatter(const int* __restrict__ src, const int* __restrict__ dst, int gi) {
    int e = blockIdx.x*blockDim.x + threadIdx.x;
    if (e < EE) {
        int d = dst[e];
        int p = g_off[gi*NNODE + d] + atomicAdd(&g_cur[gi*NNODE + d], 1);
        g_csr[gi*EE + p] = src[e];
    }
}

__global__ void k_scales() {
    int i = blockIdx.x*blockDim.x + threadIdx.x;
    if (i < 2*NNODE) {
        float in = (float)g_ind[i], od = (float)g_outd[i];
        g_sin [i] = rsqrtf(fmaxf(in, 1.f));
        g_sout[i] = rsqrtf(fmaxf(od, 1.f));
        g_inv1[i] = 1.f / (in + 1.f);
    }
}

__global__ void k_prop_sage(const float* __restrict__ x, float* __restrict__ out, int gi) {
    int wid = blockIdx.x * (blockDim.x >> 5) + (threadIdx.x >> 5);
    if (wid >= NNODE) return;
    int lane = threadIdx.x & 31;
    const float4* xr = (const float4*)(x + (size_t)wid * NHID);
    float4 a0 = xr[lane], a1 = xr[lane+32], a2 = xr[lane+64], a3 = xr[lane+96];
    int s = g_off[gi*NNODE + wid], e = s + g_ind[gi*NNODE + wid];
    const int* csr = g_csr + gi*EE;
    for (int j = s; j < e; j++) {
        int sn = csr[j];
        const float4* sr = (const float4*)(x + (size_t)sn * NHID);
        float4 v;
        v = sr[lane];    a0.x+=v.x; a0.y+=v.y; a0.z+=v.z; a0.w+=v.w;
        v = sr[lane+32]; a1.x+=v.x; a1.y+=v.y; a1.z+=v.z; a1.w+=v.w;
        v = sr[lane+64]; a2.x+=v.x; a2.y+=v.y; a2.z+=v.z; a2.w+=v.w;
        v = sr[lane+96]; a3.x+=v.x; a3.y+=v.y; a3.z+=v.z; a3.w+=v.w;
    }
    float sc = g_inv1[gi*NNODE + wid];
    float4* o = (float4*)(out + (size_t)wid * NHID);
    a0.x*=sc; a0.y*=sc; a0.z*=sc; a0.w*=sc; o[lane]    = a0;
    a1.x*=sc; a1.y*=sc; a1.z*=sc; a1.w*=sc; o[lane+32] = a1;
    a2.x*=sc; a2.y*=sc; a2.z*=sc; a2.w*=sc; o[lane+64] = a2;
    a3.x*=sc; a3.y*=sc; a3.z*=sc; a3.w*=sc; o[lane+96] = a3;
}

__global__ void k_prop_gc(const float* __restrict__ q, float* __restrict__ outT, int gi) {
    int wid = blockIdx.x * (blockDim.x >> 5) + (threadIdx.x >> 5);
    if (wid >= NNODE) return;
    int lane = threadIdx.x & 31;
    float4 a0 = make_float4(0,0,0,0), a1 = a0, a2 = a0, a3 = a0;
    float ts = 0.f;
    int s = g_off[gi*NNODE + wid], e = s + g_ind[gi*NNODE + wid];
    const int* csr = g_csr + gi*EE;
    for (int j = s; j < e; j++) {
        int sn = csr[j];
        float so = g_sout[gi*NNODE + sn];
        ts += so;
        const float4* sr = (const float4*)(q + (size_t)sn * NHID);
        float4 v;
        v = sr[lane];    a0.x+=v.x*so; a0.y+=v.y*so; a0.z+=v.z*so; a0.w+=v.w*so;
        v = sr[lane+32]; a1.x+=v.x*so; a1.y+=v.y*so; a1.z+=v.z*so; a1.w+=v.w*so;
        v = sr[lane+64]; a2.x+=v.x*so; a2.y+=v.y*so; a2.z+=v.z*so; a2.w+=v.w*so;
        v = sr[lane+96]; a3.x+=v.x*so; a3.y+=v.y*so; a3.z+=v.z*so; a3.w+=v.w*so;
    }
    float4* o = (float4*)(outT + (size_t)wid * NHID);
    o[lane] = a0; o[lane+32] = a1; o[lane+64] = a2; o[lane+96] = a3;
    if (lane == 0) g_tvec[gi*NNODE + wid] = ts;
}

__global__ void k_xcepi(const float* __restrict__ gc3b) {
    int n = blockIdx.x; int c = threadIdx.x;
    int g = c_pat[c >> 6];
    float si = g_sin[g*NNODE + n], tv = g_tvec[g*NNODE + n];
    size_t idx = (size_t)n*NHID + c;
    g_xc[idx] = si * g_xc[idx] + si * tv * g_dcat[c] + gc3b[c];
}

// ----------------------------- host orchestration --------------------------
#define SYM(name, var) { void* _p; cudaGetSymbolAddress(&_p, name); var = (float*)_p; }

extern "C" void kernel_launch(void* const* d_in, const int* in_sizes, int n_in,
                              void* d_out, int out_size) {
    const float* in_embed  = (const float*)d_in[0];
    const float* pos_embed = (const float*)d_in[1];
    const float* qkv_w     = (const float*)d_in[2];
    const float* qkv_b     = (const float*)d_in[3];
    const float* attn_w    = (const float*)d_in[4];
    const float* attn_b    = (const float*)d_in[5];
    const float* ff1_w     = (const float*)d_in[6];
    const float* ff1_b     = (const float*)d_in[7];
    const float* ff2_w     = (const float*)d_in[8];
    const float* ff2_b     = (const float*)d_in[9];
    const float* sage1_w   = (const float*)d_in[10];
    const float* sage1_b   = (const float*)d_in[11];
    const float* sage2_w   = (const float*)d_in[12];
    const float* sage2_b   = (const float*)d_in[13];
    const float* gc3_w     = (const float*)d_in[14];
    const float* gc3_b     = (const float*)d_in[15];
    const float* gff1_w    = (const float*)d_in[16];
    const float* gff1_b    = (const float*)d_in[17];
    const float* gff2_w    = (const float*)d_in[18];
    const float* gff2_b    = (const float*)d_in[19];
    const float* ln_g      = (const float*)d_in[20];
    const float* ln_b      = (const float*)d_in[21];
    const int*   in_idxs   = (const int*)d_in[22];
    const int*   mask      = (const int*)d_in[23];   // bool marshalled as int32
    const int*   gt_src    = (const int*)d_in[24];
    const int*   gt_dst    = (const int*)d_in[25];
    const int*   at_src    = (const int*)d_in[26];
    const int*   at_dst    = (const int*)d_in[27];

    float *h, *qkv, *o, *x, *ff, *xf, *P, *Q, *T, *xc, *xg, *fg, *Mb, *Nc, *cc, *dc;
    SYM(g_h, h); SYM(g_qkv, qkv); SYM(g_o, o); SYM(g_x, x); SYM(g_ff, ff);
    SYM(g_xf, xf); SYM(g_P, P); SYM(g_Q, Q); SYM(g_T, T); SYM(g_xc, xc); SYM(g_xg, xg);
    SYM(g_fg, fg); SYM(g_M, Mb); SYM(g_Ncat, Nc); SYM(g_ccat, cc); SYM(g_dcat, dc);

    static int smemSet = 0;
    if (!smemSet) {
        cudaFuncSetAttribute(k_flash, cudaFuncAttributeMaxDynamicSharedMemorySize, FLASH_SMEM);
        smemSet = 1;
    }

    // ---- embedding + mask packing ----
    k_embed<<<NTOK, 128>>>(in_embed, pos_embed, in_idxs);
    k_packmask<<<BB*LL*HEADS/8, 256>>>(mask);

    // ---- transformer layers ----
    for (int l = 0; l < 4; l++) {
        mgemm(h, NHID, qkv_w + (size_t)l*NHID*QKVD, QKVD, qkv, QKVD,
              NTOK, QKVD, NHID, qkv_b + l*QKVD);
        k_flash<<<dim3(LL/128, BB*HEADS), 256, FLASH_SMEM>>>();
        mgemm(o, NHID, attn_w + (size_t)l*NHID*NHID, NHID, x, NHID,
              NTOK, NHID, NHID, attn_b + l*NHID, h, NHID, 2.0f);
        mgemm(x, NHID, ff1_w + (size_t)l*NHID*FFD, FFD, ff, FFD,
              NTOK, FFD, NHID, ff1_b + l*FFD, nullptr, 0, 0.f, /*relu=*/1);
        mgemm(ff, FFD, ff2_w + (size_t)l*FFD*NHID, NHID, h, NHID,
              NTOK, NHID, FFD, ff2_b + l*NHID, x, NHID, 1.0f);
    }

    // ---- graph preprocessing ----
    k_zero_ints<<<(2*NNODE + 255)/256, 256>>>();
    k_count<<<EE/256, 256>>>(gt_src, gt_dst, 0);
    k_count<<<EE/256, 256>>>(at_src, at_dst, 1);
    k_scan<<<1, 1024>>>(0);
    k_scan<<<1, 1024>>>(1);
    k_scatter<<<EE/256, 256>>>(gt_src, gt_dst, 0);
    k_scatter<<<EE/256, 256>>>(at_src, at_dst, 1);
    k_scales<<<(2*NNODE + 255)/256, 256>>>();
    k_copyxf<<<NNODE, 128>>>();

    // ---- propagations (3 per graph) ----
    int propBlocks = (NNODE + 7) / 8;
    for (int g = 0; g < 2; g++) {
        k_prop_sage<<<propBlocks, 256>>>(xf, P, g);
        k_prop_sage<<<propBlocks, 256>>>(P,  Q, g);
        k_prop_gc  <<<propBlocks, 256>>>(Q,  T + (size_t)g*NNODE*NHID, g);
    }

    // ---- collapse per-head weights: M_i = W1 W2, N_i = M_i W3, c_i, d_i ----
    mgemm(sage1_w, NHID, sage2_w, NHID, Mb, NHID, NHID, NHID, NHID,
          nullptr, nullptr, 0, 0.f, 0, 0, HEADS, 1,
          (long long)NHID*NHID, 0, (long long)NHID*NHID, 0, (long long)NHID*NHID, 0);
    mgemm(Mb, NHID, gc3_w, 64, Nc, 64, NHID, 64, NHID,
          nullptr, nullptr, 0, 0.f, 0, 0, HEADS, 1,
          (long long)NHID*NHID, 0, (long long)NHID*64, 0, (long long)NHID*64, 0);
    {
        GP p; p.A=sage1_b; p.B=sage2_w; p.bias=sage2_b; p.res=nullptr; p.C=cc;
        p.lda=NHID; p.ldb=NHID; p.ldc=NHID; p.ldres=0;
        p.M=1; p.N=NHID; p.K=NHID; p.resScale=0; p.relu=0; p.zDiv=1; p.hmode=0;
        p.aO=NHID; p.bO=(long long)NHID*NHID; p.cO=NHID; p.biasO=NHID;
        p.aI=p.bI=p.cI=p.rO=p.rI=0;
        gemm1_k<<<dim3((NHID+63)/64,1,HEADS), 64>>>(p);
    }
    {
        GP p; p.A=cc; p.B=gc3_w; p.bias=nullptr; p.res=nullptr; p.C=dc;
        p.lda=NHID; p.ldb=64; p.ldc=64; p.ldres=0;
        p.M=1; p.N=64; p.K=NHID; p.resScale=0; p.relu=0; p.zDiv=1; p.hmode=0;
        p.aO=NHID; p.bO=(long long)NHID*64; p.cO=64; p.biasO=0;
        p.aI=p.bI=p.cI=p.rO=p.rI=0;
        gemm1_k<<<dim3(1,1,HEADS), 64>>>(p);
    }

    // ---- xc per head: one launch, A = T[(z>>1)&1], via hmode ----
    mgemm(T, NHID, Nc, 64, xc, NHID,
          NNODE, 64, NHID, nullptr, nullptr, 0, 0.f, 0, 0,
          HEADS, 1,
          0, (long long)NNODE*NHID,
          (long long)NHID*64, 0,
          64, 0, 0, 0, 0, /*hmode=*/1);
    k_xcepi<<<NNODE, 512>>>(gc3_b);

    // ---- final: x = hg + LN(xc); ff = relu(x W1+b) W2 + b; zbar = x + LN(ff) ----
    k_ln_add<<<NNODE, 128>>>(xg, xc, h, /*hgMap=*/1, ln_g, ln_b);
    mgemm(xg, NHID, gff1_w, NHID, fg, NHID, NNODE, NHID, NHID, gff1_b,
          nullptr, 0, 0.f, /*relu=*/1);
    mgemm(fg, NHID, gff2_w, NHID, xc, NHID, NNODE, NHID, NHID, gff2_b);
    k_ln_add<<<NNODE, 128>>>((float*)d_out, xc, xg, /*hgMap=*/0, ln_g, ln_b);

    // ---- zg ----
    if (out_size >= NNODE*NHID + BB*NHID)
        k_zg<<<BB, 128>>>((float*)d_out);
}

// round 9
// speedup vs baseline: 1.1902x; 1.1643x over previous
#include <cuda_runtime.h>
#include <cuda_fp16.h>
#include <math.h>
#include <stdint.h>

#define NHID   512
#define HEADS  8
#define NKD    64
#define BB     16
#define SS     511
#define LL     512
#define NNODE  8176      // BB*SS
#define NTOK   8192      // BB*LL
#define EE     131072
#define QKVD   1536
#define FFD    2048

// ----------------------------- scratch (device globals; no allocation) -----
__device__ float g_h   [NTOK*NHID];
__device__ float g_qkv [NTOK*QKVD];
__device__ float g_o   [NTOK*NHID];
__device__ float g_x   [NTOK*NHID];
__device__ float g_ff  [NTOK*FFD];
__device__ float g_xf  [NNODE*NHID];
__device__ float g_P   [NNODE*NHID];
__device__ float g_Q   [NNODE*NHID];
__device__ float g_T   [2*NNODE*NHID];
__device__ float g_xc  [NNODE*NHID];
__device__ float g_xg  [NNODE*NHID];
__device__ float g_fg  [NNODE*NHID];
__device__ float g_M   [HEADS*NHID*NHID];
__device__ float g_Ncat[HEADS*NHID*64];
__device__ float g_ccat[HEADS*NHID];
__device__ float g_dcat[HEADS*64];
__device__ float g_tvec[2*NNODE];
__device__ float g_sin [2*NNODE];
__device__ float g_sout[2*NNODE];
__device__ float g_inv1[2*NNODE];
__device__ int   g_ind [2*NNODE];
__device__ int   g_outd[2*NNODE];
__device__ int   g_off [2*NNODE];
__device__ int   g_cur [2*NNODE];
__device__ int   g_csr [2*EE];
__device__ unsigned g_pm[(size_t)BB*HEADS*LL*(LL/32)];   // packed mask bits (4 MB)

__constant__ int c_pat[8] = {0,0,1,1,0,0,1,1};

// ----------------------------- common GEMM param block ---------------------
struct GP {
    const float *A, *B, *bias, *res;
    float *C;
    int lda, ldb, ldc, ldres;
    int M, N, K;
    float resScale;
    int relu;
    int zDiv;
    int hmode;     // per-head graph GEMM mode: A selected by (z>>1)&1
    long long aO, aI, bO, bI, cO, cI, rO, rI, biasO;
};

// ----------------------------- fp16 helpers --------------------------------
__device__ __forceinline__ unsigned h2u(float a, float b) {
    __half2 h = __floats2half2_rn(a, b);
    return *reinterpret_cast<unsigned*>(&h);
}
__device__ __forceinline__ uint2 f4h(float4 v) {
    uint2 r; r.x = h2u(v.x, v.y); r.y = h2u(v.z, v.w); return r;
}
__device__ __forceinline__ void ldsm4(unsigned &d0, unsigned &d1, unsigned &d2, unsigned &d3,
                                      unsigned addr) {
    asm volatile("ldmatrix.sync.aligned.m8n8.x4.shared.b16 {%0,%1,%2,%3}, [%4];"
                 : "=r"(d0), "=r"(d1), "=r"(d2), "=r"(d3) : "r"(addr));
}
__device__ __forceinline__ void ldsm2(unsigned &d0, unsigned &d1, unsigned addr) {
    asm volatile("ldmatrix.sync.aligned.m8n8.x2.shared.b16 {%0,%1}, [%2];"
                 : "=r"(d0), "=r"(d1) : "r"(addr));
}
__device__ __forceinline__ void ldsm2t(unsigned &d0, unsigned &d1, unsigned addr) {
    asm volatile("ldmatrix.sync.aligned.m8n8.x2.trans.shared.b16 {%0,%1}, [%2];"
                 : "=r"(d0), "=r"(d1) : "r"(addr));
}
__device__ __forceinline__ void mma16(float* c, const unsigned* a, const unsigned* b) {
    asm volatile(
        "mma.sync.aligned.m16n8k16.row.col.f32.f16.f16.f32 "
        "{%0,%1,%2,%3}, {%4,%5,%6,%7}, {%8,%9}, {%0,%1,%2,%3};"
        : "+f"(c[0]), "+f"(c[1]), "+f"(c[2]), "+f"(c[3])
        : "r"(a[0]), "r"(a[1]), "r"(a[2]), "r"(a[3]), "r"(b[0]), "r"(b[1]));
}

// ----------------------------- fp16 tensor-core GEMM (2-stage) -------------
// CTA tile 128 x BN, 8 warps, K-slice 32, double-buffered smem.
// A smem: [m][k] halves, row stride 40 halves (20 words) - ldmatrix-safe.
// B smem: [k][n] halves, row stride BN+8 halves - ldsm.x2.trans per fragment.
template<int BN, int WGN>
__global__ __launch_bounds__(256) void mma_k(GP p) {
    constexpr int WGM  = 8 / WGN;
    constexpr int WM   = 128 / WGM;
    constexpr int WN   = BN / WGN;
    constexpr int MF   = WM / 16;
    constexpr int NF   = WN / 8;
    constexpr int ASTW = 20;            // A row stride in 4B words (40 halves)
    constexpr int BSTH = BN + 8;        // B row stride in halves
    constexpr int BSTW = BSTH / 2;

    __shared__ unsigned sA[2][128 * ASTW];
    __shared__ unsigned sB[2][32 * BSTW];

    const float *A, *B; float *C;
    const float *bias = nullptr, *res = nullptr;
    if (p.hmode) {
        int hd = blockIdx.z;
        A = p.A + (((hd >> 1) & 1) ? p.aI : 0);
        B = p.B + (size_t)hd * p.bO;
        C = p.C + (size_t)hd * p.cO;
    } else {
        int zo = blockIdx.z / p.zDiv, zi = blockIdx.z % p.zDiv;
        A = p.A + zo * p.aO + zi * p.aI;
        B = p.B + zo * p.bO + zi * p.bI;
        C = p.C + zo * p.cO + zi * p.cI;
        if (p.bias) bias = p.bias + zo * p.biasO;
        if (p.res)  res  = p.res + zo * p.rO + zi * p.rI;
    }

    int tid = threadIdx.x, lane = tid & 31, warp = tid >> 5;
    int wm = warp / WGN, wn = warp % WGN;
    int m0 = blockIdx.x * 128, n0 = blockIdx.y * BN;

    // A gmem mapping: row = tid>>1, 16 halves starting at kh=(tid&1)*16
    int ar = tid >> 1, akh = (tid & 1) * 16;
    bool aval = (m0 + ar) < p.M;
    const float* aptr = A + (size_t)(m0 + ar) * p.lda + akh;

    // B gmem mapping: k-row = tid>>3, halves at nh
    int bk = tid >> 3;
    int bnh = (BN == 128) ? (tid & 7) * 16 : (tid & 7) * 8;
    const float* bptr = B + (size_t)bk * p.ldb + n0 + bnh;

    float acc[MF][NF][4];
    #pragma unroll
    for (int f = 0; f < MF; f++)
        #pragma unroll
        for (int j = 0; j < NF; j++)
            #pragma unroll
            for (int q = 0; q < 4; q++) acc[f][j][q] = 0.f;

    float4 pa[4], pb[4];
    #pragma unroll
    for (int i = 0; i < 4; i++) pa[i] = pb[i] = make_float4(0.f,0.f,0.f,0.f);

    auto loadRegs = [&](int k0) {
        if (aval) {
            #pragma unroll
            for (int i = 0; i < 4; i++) pa[i] = *(const float4*)(aptr + k0 + i*4);
        }
        #pragma unroll
        for (int i = 0; i < (BN == 128 ? 4 : 2); i++)
            pb[i] = *(const float4*)(bptr + (size_t)(k0 + bk - bk) * 0 + (size_t)(k0) * p.ldb + i*4);
    };
    auto storeStage = [&](int s) {
        // A: 16 halves = 8 words = 2 uint4
        uint2 a0 = f4h(pa[0]), a1 = f4h(pa[1]), a2 = f4h(pa[2]), a3 = f4h(pa[3]);
        unsigned* Ad = &sA[s][ar * ASTW + akh/2];
        *(uint4*)(Ad)     = make_uint4(a0.x, a0.y, a1.x, a1.y);
        *(uint4*)(Ad + 4) = make_uint4(a2.x, a2.y, a3.x, a3.y);
        unsigned* Bd = &sB[s][bk * BSTW + bnh/2];
        uint2 b0 = f4h(pb[0]), b1 = f4h(pb[1]);
        *(uint4*)(Bd) = make_uint4(b0.x, b0.y, b1.x, b1.y);
        if (BN == 128) {
            uint2 b2 = f4h(pb[2]), b3 = f4h(pb[3]);
            *(uint4*)(Bd + 4) = make_uint4(b2.x, b2.y, b3.x, b3.y);
        }
    };

    // ldmatrix per-thread address components
    int l15 = lane & 15;
    int aRow = (lane & 7) + ((lane >> 3) & 1) * 8;       // + wm*WM + f*16
    int aKoff = ((lane >> 4) & 1) * 16;                  // bytes (8 halves)
    int bRowK = (l15 & 7) + (l15 >> 3) * 8;              // + kk
    unsigned sAb[2], sBb[2];
    #pragma unroll
    for (int s = 0; s < 2; s++) {
        sAb[s] = (unsigned)__cvta_generic_to_shared(sA[s]);
        sBb[s] = (unsigned)__cvta_generic_to_shared(sB[s]);
    }

    // prologue
    loadRegs(0);
    storeStage(0);
    if (32 < p.K) loadRegs(32);
    __syncthreads();

    int cur = 0;
    for (int k0 = 0; k0 < p.K; k0 += 32) {
        int nxt = cur ^ 1;
        if (k0 + 32 < p.K) storeStage(nxt);
        if (k0 + 64 < p.K) loadRegs(k0 + 64);

        unsigned aB = sAb[cur], bB = sBb[cur];
        #pragma unroll
        for (int kk = 0; kk < 32; kk += 16) {
            unsigned bfr[NF][2];
            #pragma unroll
            for (int j = 0; j < NF; j++) {
                int nb = wn * WN + j * 8;
                unsigned addr = bB + (unsigned)((kk + bRowK) * BSTH + nb) * 2u;
                ldsm2t(bfr[j][0], bfr[j][1], addr);
            }
            #pragma unroll
            for (int f = 0; f < MF; f++) {
                int row = wm * WM + f * 16 + aRow;
                unsigned addr = aB + (unsigned)(row * ASTW) * 4u + (unsigned)kk * 2u + aKoff;
                unsigned afr[4];
                ldsm4(afr[0], afr[1], afr[2], afr[3], addr);
                #pragma unroll
                for (int j = 0; j < NF; j++) mma16(acc[f][j], afr, bfr[j]);
            }
        }
        __syncthreads();
        cur = nxt;
    }

    #pragma unroll
    for (int f = 0; f < MF; f++) {
        int r0 = m0 + wm * WM + f * 16 + (lane >> 2);
        int r1 = r0 + 8;
        #pragma unroll
        for (int j = 0; j < NF; j++) {
            int col = n0 + wn * WN + j * 8 + 2 * (lane & 3);
            float b0 = 0.f, b1 = 0.f;
            if (bias) { b0 = bias[col]; b1 = bias[col + 1]; }
            float v0 = acc[f][j][0] + b0, v1 = acc[f][j][1] + b1;
            float v2 = acc[f][j][2] + b0, v3 = acc[f][j][3] + b1;
            if (p.relu) {
                v0 = fmaxf(v0, 0.f); v1 = fmaxf(v1, 0.f);
                v2 = fmaxf(v2, 0.f); v3 = fmaxf(v3, 0.f);
            }
            if (r0 < p.M) {
                if (res) {
                    v0 += p.resScale * res[(size_t)r0 * p.ldres + col];
                    v1 += p.resScale * res[(size_t)r0 * p.ldres + col + 1];
                }
                *(float2*)&C[(size_t)r0 * p.ldc + col] = make_float2(v0, v1);
            }
            if (r1 < p.M) {
                if (res) {
                    v2 += p.resScale * res[(size_t)r1 * p.ldres + col];
                    v3 += p.resScale * res[(size_t)r1 * p.ldres + col + 1];
                }
                *(float2*)&C[(size_t)r1 * p.ldc + col] = make_float2(v2, v3);
            }
        }
    }
}

static void mgemm(const float* A, int lda, const float* B, int ldb, float* C, int ldc,
                  int M, int N, int K,
                  const float* bias = nullptr, const float* res = nullptr, int ldres = 0,
                  float resScale = 0.f, int relu = 0, int transB_unused = 0,
                  int z = 1, int zDiv = 1,
                  long long aO=0, long long aI=0, long long bO=0, long long bI=0,
                  long long cO=0, long long cI=0, long long rO=0, long long rI=0,
                  long long biasO=0, int hmode = 0) {
    GP p;
    p.A=A; p.B=B; p.bias=bias; p.res=res; p.C=C;
    p.lda=lda; p.ldb=ldb; p.ldc=ldc; p.ldres=ldres;
    p.M=M; p.N=N; p.K=K; p.resScale=resScale; p.relu=relu; p.zDiv=zDiv; p.hmode=hmode;
    p.aO=aO; p.aI=aI; p.bO=bO; p.bI=bI; p.cO=cO; p.cI=cI; p.rO=rO; p.rI=rI; p.biasO=biasO;
    if (N % 128 == 0) {
        dim3 grid((M + 127) / 128, N / 128, z);
        mma_k<128, 4><<<grid, 256>>>(p);
    } else {
        dim3 grid((M + 127) / 128, N / 64, z);
        mma_k<64, 2><<<grid, 256>>>(p);
    }
}

// ----------------------------- fused flash attention (fp16 MMA) ------------
// grid (L/128, B*H), 256 threads (8 warps), warp owns 16 Q rows.
// Q register-resident (4 k16 fragments); K-tiles of 64 keys.
// smem: sK 64x72h, sV 64x72h, sP 128x72h  (halves) = 36 KB, 2 CTAs/SM.
#define KT      64
#define KSTW    36     // 72 halves row stride (words)
#define FLASH_SMEM ((64*KSTW + 64*KSTW + 128*KSTW) * 4)

__global__ __launch_bounds__(256, 2) void k_flash() {
    extern __shared__ unsigned sm[];
    unsigned* sK = sm;
    unsigned* sV = sK + 64*KSTW;
    unsigned* sP = sV + 64*KSTW;

    int tid = threadIdx.x, lane = tid & 31, w = tid >> 5;
    int m0 = blockIdx.x * 128;
    int bh = blockIdx.y; int h = bh & 7, b = bh >> 3;
    const float* qbase = g_qkv + (size_t)(b * LL) * QKVD + h * 192;

    unsigned sKb = (unsigned)__cvta_generic_to_shared(sK);
    unsigned sVb = (unsigned)__cvta_generic_to_shared(sV);
    unsigned sPb = (unsigned)__cvta_generic_to_shared(sP);

    int l15 = lane & 15;
    int aRow = (lane & 7) + ((lane >> 3) & 1) * 8;      // A-fragment row within 16
    unsigned aKoff = ((lane >> 4) & 1) * 16;            // byte offset (8 halves)
    int arow = 16*w + aRow;

    // ---- stage Q tile through sP as halves, pull 4 k16 fragments to regs ----
    {
        int row = tid >> 1, dh = (tid & 1) * 32;        // 32 halves per thread
        const float* src = qbase + (size_t)(m0 + row) * QKVD + dh;
        unsigned* dst = sP + row * KSTW + dh/2;
        #pragma unroll
        for (int c = 0; c < 4; c++) {
            uint2 u0 = f4h(*(const float4*)(src + c*8));
            uint2 u1 = f4h(*(const float4*)(src + c*8 + 4));
            *(uint4*)(dst + c*4) = make_uint4(u0.x, u0.y, u1.x, u1.y);
        }
    }
    __syncthreads();
    unsigned qf[4][4];
    #pragma unroll
    for (int kc = 0; kc < 4; kc++)
        ldsm4(qf[kc][0], qf[kc][1], qf[kc][2], qf[kc][3],
              sPb + (unsigned)(arow * KSTW) * 4u + (unsigned)kc * 32u + aKoff);
    __syncthreads();

    float accO[8][4];
    #pragma unroll
    for (int j = 0; j < 8; j++)
        #pragma unroll
        for (int q = 0; q < 4; q++) accO[j][q] = 0.f;
    float m0r = -INFINITY, m1r = -INFINITY, l0r = 0.f, l1r = 0.f;

    const unsigned* pmr0 = g_pm + ((size_t)bh * LL + m0 + 16*w + (lane >> 2)) * 16;
    const unsigned* pmr1 = pmr0 + 8 * 16;

    for (int kt = 0; kt < 8; kt++) {
        __syncthreads();
        // ---- load K and V tiles ([key][d] halves, natural layout) ----
        {
            int key = tid >> 2, dh = (tid & 3) * 16;
            const float* ks = qbase + (size_t)(kt*KT + key) * QKVD + 64 + dh;
            unsigned* kd = sK + key * KSTW + dh/2;
            uint2 u0 = f4h(*(const float4*)(ks));
            uint2 u1 = f4h(*(const float4*)(ks + 4));
            uint2 u2 = f4h(*(const float4*)(ks + 8));
            uint2 u3 = f4h(*(const float4*)(ks + 12));
            *(uint4*)(kd)     = make_uint4(u0.x, u0.y, u1.x, u1.y);
            *(uint4*)(kd + 4) = make_uint4(u2.x, u2.y, u3.x, u3.y);
            const float* vs = ks + 64;
            unsigned* vd = sV + key * KSTW + dh/2;
            u0 = f4h(*(const float4*)(vs));
            u1 = f4h(*(const float4*)(vs + 4));
            u2 = f4h(*(const float4*)(vs + 8));
            u3 = f4h(*(const float4*)(vs + 12));
            *(uint4*)(vd)     = make_uint4(u0.x, u0.y, u1.x, u1.y);
            *(uint4*)(vd + 4) = make_uint4(u2.x, u2.y, u3.x, u3.y);
        }
        __syncthreads();

        // ---- S = Q K^T: B fragments via non-trans ldsm.x2 on [key][d] ----
        float S[8][4];
        #pragma unroll
        for (int nt = 0; nt < 8; nt++)
            #pragma unroll
            for (int q = 0; q < 4; q++) S[nt][q] = 0.f;
        #pragma unroll
        for (int kc = 0; kc < 4; kc++) {
            #pragma unroll
            for (int nt = 0; nt < 8; nt++) {
                unsigned bb[2];
                unsigned addr = sKb + (unsigned)((nt*8 + (l15 & 7)) * KSTW) * 4u
                                    + (unsigned)kc * 32u + (unsigned)(l15 >> 3) * 16u;
                ldsm2(bb[0], bb[1], addr);
                mma16(S[nt], qf[kc], bb);
            }
        }

        // ---- mask + scale ----
        uint2 mw0 = *(const uint2*)(pmr0 + kt*2);
        uint2 mw1 = *(const uint2*)(pmr1 + kt*2);
        unsigned q0[2] = {mw0.x, mw0.y};
        unsigned q1[2] = {mw1.x, mw1.y};
        float rm0 = -INFINITY, rm1 = -INFINITY;
        #pragma unroll
        for (int nt = 0; nt < 8; nt++) {
            int j0 = nt*8 + 2*(lane & 3), j1 = j0 + 1;
            S[nt][0] = ((q0[j0>>5] >> (j0&31)) & 1u) ? S[nt][0]*0.125f : -INFINITY;
            S[nt][1] = ((q0[j1>>5] >> (j1&31)) & 1u) ? S[nt][1]*0.125f : -INFINITY;
            S[nt][2] = ((q1[j0>>5] >> (j0&31)) & 1u) ? S[nt][2]*0.125f : -INFINITY;
            S[nt][3] = ((q1[j1>>5] >> (j1&31)) & 1u) ? S[nt][3]*0.125f : -INFINITY;
            rm0 = fmaxf(rm0, fmaxf(S[nt][0], S[nt][1]));
            rm1 = fmaxf(rm1, fmaxf(S[nt][2], S[nt][3]));
        }
        rm0 = fmaxf(rm0, __shfl_xor_sync(0xffffffffu, rm0, 1));
        rm0 = fmaxf(rm0, __shfl_xor_sync(0xffffffffu, rm0, 2));
        rm1 = fmaxf(rm1, __shfl_xor_sync(0xffffffffu, rm1, 1));
        rm1 = fmaxf(rm1, __shfl_xor_sync(0xffffffffu, rm1, 2));

        float mn0 = fmaxf(m0r, rm0), mn1 = fmaxf(m1r, rm1);
        float a0 = __expf(m0r - mn0), a1 = __expf(m1r - mn1);
        m0r = mn0; m1r = mn1;

        // ---- P = exp(S - m) -> fp16 in sP (own warp rows) ----
        int prow0 = 16*w + (lane >> 2), prow1 = prow0 + 8;
        float rs0 = 0.f, rs1 = 0.f;
        #pragma unroll
        for (int nt = 0; nt < 8; nt++) {
            int jw = nt*4 + (lane & 3);     // half2 word index (j0/2)
            float p00 = __expf(S[nt][0] - mn0), p01 = __expf(S[nt][1] - mn0);
            float p10 = __expf(S[nt][2] - mn1), p11 = __expf(S[nt][3] - mn1);
            rs0 += p00 + p01; rs1 += p10 + p11;
            sP[prow0*KSTW + jw] = h2u(p00, p01);
            sP[prow1*KSTW + jw] = h2u(p10, p11);
        }
        rs0 += __shfl_xor_sync(0xffffffffu, rs0, 1);
        rs0 += __shfl_xor_sync(0xffffffffu, rs0, 2);
        rs1 += __shfl_xor_sync(0xffffffffu, rs1, 1);
        rs1 += __shfl_xor_sync(0xffffffffu, rs1, 2);
        l0r = l0r * a0 + rs0;
        l1r = l1r * a1 + rs1;

        #pragma unroll
        for (int j = 0; j < 8; j++) {
            accO[j][0] *= a0; accO[j][1] *= a0;
            accO[j][2] *= a1; accO[j][3] *= a1;
        }
        __syncwarp();

        // ---- O += P @ V: P via ldsm.x4 (rows q), V via ldsm.x2.trans ----
        #pragma unroll
        for (int kc = 0; kc < 4; kc++) {
            unsigned pf[4];
            ldsm4(pf[0], pf[1], pf[2], pf[3],
                  sPb + (unsigned)(arow * KSTW) * 4u + (unsigned)kc * 32u + aKoff);
            #pragma unroll
            for (int nt = 0; nt < 8; nt++) {
                unsigned bb[2];
                unsigned addr = sVb + (unsigned)((kc*16 + (l15 & 7) + (l15 >> 3)*8) * KSTW) * 4u
                                    + (unsigned)nt * 16u;
                ldsm2t(bb[0], bb[1], addr);
                mma16(accO[nt], pf, bb);
            }
        }
    }

    // ---- epilogue: O /= l, write to g_o[b, i, h*64 + d] ----
    float inv0 = 1.f / l0r, inv1 = 1.f / l1r;
    int r0 = m0 + 16*w + (lane >> 2), r1 = r0 + 8;
    float* o0 = g_o + (size_t)(b*LL + r0) * NHID + h*64;
    float* o1 = g_o + (size_t)(b*LL + r1) * NHID + h*64;
    #pragma unroll
    for (int nt = 0; nt < 8; nt++) {
        int col = nt*8 + 2*(lane & 3);
        *(float2*)(o0 + col) = make_float2(accO[nt][0]*inv0, accO[nt][1]*inv0);
        *(float2*)(o1 + col) = make_float2(accO[nt][2]*inv1, accO[nt][3]*inv1);
    }
}

// pack mask (int32 bool, layout [b][i][h][j]) -> bits [b][h][i][j/32]
__global__ void k_packmask(const int* __restrict__ mask) {
    int row = blockIdx.x * 8 + (threadIdx.x >> 5);
    int lane = threadIdx.x & 31;
    const int* mr = mask + (size_t)row * LL;
    int b_i = row >> 3, h = row & 7;
    int b = b_i >> 9, i = b_i & 511;
    unsigned* out = g_pm + (((size_t)(b*HEADS + h) * LL + i) << 4);
    #pragma unroll
    for (int wd = 0; wd < 16; wd++) {
        unsigned bits = __ballot_sync(0xffffffffu, mr[wd*32 + lane] != 0);
        if (lane == 0) out[wd] = bits;
    }
}

// ----------------------------- small FFMA GEMM (tiny M=1 cases) ------------
__global__ void gemm1_k(GP p) {
    int zo = blockIdx.z;
    const float* A = p.A + zo * p.aO;
    const float* B = p.B + zo * p.bO;
    float* C = p.C + zo * p.cO;
    const float* bias = p.bias ? p.bias + zo * p.biasO : nullptr;
    int n = blockIdx.x * 64 + threadIdx.x;
    if (n >= p.N) return;
    float s = 0.f;
    for (int k = 0; k < p.K; k++) s += A[k] * B[(size_t)k * p.ldb + n];
    if (bias) s += bias[n];
    C[n] = s;
}

// ----------------------------- small kernels -------------------------------
__global__ void k_embed(const float* __restrict__ emb, const float* __restrict__ pos,
                        const int* __restrict__ idxs) {
    int tok = blockIdx.x;
    int b = tok >> 9, s = tok & 511;
    int id = (s == 0) ? 0 : idxs[b*SS + s - 1];
    const float4* e  = (const float4*)(emb + (size_t)id * NHID);
    const float4* pr = (const float4*)(pos + (size_t)s  * NHID);
    float4* hr = (float4*)(g_h + (size_t)tok * NHID);
    int t = threadIdx.x;
    float4 a = e[t], c = pr[t];
    hr[t] = make_float4(a.x+c.x, a.y+c.y, a.z+c.z, a.w+c.w);
}

__global__ void k_ln_add(float* __restrict__ out, const float* __restrict__ inp,
                         const float* __restrict__ base, int hgMap,
                         const float* __restrict__ gw, const float* __restrict__ bw) {
    int n = blockIdx.x;
    const float* xr = inp + (size_t)n * NHID;
    size_t brow;
    if (hgMap) { int b = n / SS, s = n % SS; brow = ((size_t)(b*LL + s + 1)) * NHID; }
    else brow = (size_t)n * NHID;
    int t = threadIdx.x;  // 128
    float x[4];
    #pragma unroll
    for (int i = 0; i < 4; i++) x[i] = xr[t + i*128];
    __shared__ float red[128];
    red[t] = x[0]+x[1]+x[2]+x[3]; __syncthreads();
    for (int s = 64; s > 0; s >>= 1) { if (t < s) red[t] += red[t+s]; __syncthreads(); }
    float mu = red[0] * (1.f/512.f); __syncthreads();
    float d[4], vs = 0.f;
    #pragma unroll
    for (int i = 0; i < 4; i++) { d[i] = x[i] - mu; vs += d[i]*d[i]; }
    red[t] = vs; __syncthreads();
    for (int s = 64; s > 0; s >>= 1) { if (t < s) red[t] += red[t+s]; __syncthreads(); }
    float inv = rsqrtf(red[0] * (1.f/512.f) + 1e-5f);
    #pragma unroll
    for (int i = 0; i < 4; i++) {
        int c = t + i*128;
        out[(size_t)n*NHID + c] = base[brow + c] + d[i]*inv*gw[c] + bw[c];
    }
}

__global__ void k_zg(float* __restrict__ dout) {
    int b = blockIdx.x; int t = threadIdx.x;
    #pragma unroll
    for (int i = 0; i < 4; i++) {
        int c = t + i*128;
        dout[(size_t)NNODE*NHID + b*NHID + c] = g_h[((size_t)b*LL) * NHID + c];
    }
}

__global__ void k_copyxf() {
    int n = blockIdx.x;
    int b = n / SS, s = n % SS;
    const float4* src = (const float4*)(g_h + ((size_t)(b*LL + s + 1)) * NHID);
    float4* dst = (float4*)(g_xf + (size_t)n * NHID);
    dst[threadIdx.x] = src[threadIdx.x];
}

__global__ void k_zero_ints() {
    int i = blockIdx.x*blockDim.x + threadIdx.x;
    if (i < 2*NNODE) { g_ind[i] = 0; g_outd[i] = 0; g_cur[i] = 0; }
}

__global__ void k_count(const int* __restrict__ src, const int* __restrict__ dst, int gi) {
    int e = blockIdx.x*blockDim.x + threadIdx.x;
    if (e < EE) {
        atomicAdd(&g_ind [gi*NNODE + dst[e]], 1);
        atomicAdd(&g_outd[gi*NNODE + src[e]], 1);
    }
}

__global__ void k_scan(int gi) {
    __shared__ int sh[1024];
    int t = threadIdx.x;
    int base = gi * NNODE;
    int loc[8]; int sum = 0;
    #pragma unroll
    for (int i = 0; i < 8; i++) {
        int idx = t*8 + i;
        int v = (idx < NNODE) ? g_ind[base + idx] : 0;
        loc[i] = sum; sum += v;
    }
    sh[t] = sum; __syncthreads();
    for (int d = 1; d < 1024; d <<= 1) {
        int v = (t >= d) ? sh[t-d] : 0; __syncthreads();
        sh[t] += v; __syncthreads();
    }
    int pre = (t > 0) ? sh[t-1] : 0;
    #pragma unroll
    for (int i = 0; i < 8; i++) {
        int idx = t*8 + i;
        if (idx < NNODE) g_off[base + idx] = pre + loc[i];
    }
}

__global__ void k_scatter(const int* __restrict__ src, const int* __restrict__ dst, int gi) {
    int e = blockIdx.x*blockDim.x + threadIdx.x;
    if (e < EE) {
        int d = dst[e];
        int p = g_off[gi*NNODE + d] + atomicAdd(&g_cur[gi*NNODE + d], 1);
        g_csr[gi*EE + p] = src[e];
    }
}

__global__ void k_scales() {
    int i = blockIdx.x*blockDim.x + threadIdx.x;
    if (i < 2*NNODE) {
        float in = (float)g_ind[i], od = (float)g_outd[i];
        g_sin [i] = rsqrtf(fmaxf(in, 1.f));
        g_sout[i] = rsqrtf(fmaxf(od, 1.f));
        g_inv1[i] = 1.f / (in + 1.f);
    }
}

__global__ void k_prop_sage(const float* __restrict__ x, float* __restrict__ out, int gi) {
    int wid = blockIdx.x * (blockDim.x >> 5) + (threadIdx.x >> 5);
    if (wid >= NNODE) return;
    int lane = threadIdx.x & 31;
    const float4* xr = (const float4*)(x + (size_t)wid * NHID);
    float4 a0 = xr[lane], a1 = xr[lane+32], a2 = xr[lane+64], a3 = xr[lane+96];
    int s = g_off[gi*NNODE + wid], e = s + g_ind[gi*NNODE + wid];
    const int* csr = g_csr + gi*EE;
    for (int j = s; j < e; j++) {
        int sn = csr[j];
        const float4* sr = (const float4*)(x + (size_t)sn * NHID);
        float4 v;
        v = sr[lane];    a0.x+=v.x; a0.y+=v.y; a0.z+=v.z; a0.w+=v.w;
        v = sr[lane+32]; a1.x+=v.x; a1.y+=v.y; a1.z+=v.z; a1.w+=v.w;
        v = sr[lane+64]; a2.x+=v.x; a2.y+=v.y; a2.z+=v.z; a2.w+=v.w;
        v = sr[lane+96]; a3.x+=v.x; a3.y+=v.y; a3.z+=v.z; a3.w+=v.w;
    }
    float sc = g_inv1[gi*NNODE + wid];
    float4* o = (float4*)(out + (size_t)wid * NHID);
    a0.x*=sc; a0.y*=sc; a0.z*=sc; a0.w*=sc; o[lane]    = a0;
    a1.x*=sc; a1.y*=sc; a1.z*=sc; a1.w*=sc; o[lane+32] = a1;
    a2.x*=sc; a2.y*=sc; a2.z*=sc; a2.w*=sc; o[lane+64] = a2;
    a3.x*=sc; a3.y*=sc; a3.z*=sc; a3.w*=sc; o[lane+96] = a3;
}

__global__ void k_prop_gc(const float* __restrict__ q, float* __restrict__ outT, int gi) {
    int wid = blockIdx.x * (blockDim.x >> 5) + (threadIdx.x >> 5);
    if (wid >= NNODE) return;
    int lane = threadIdx.x & 31;
    float4 a0 = make_float4(0,0,0,0), a1 = a0, a2 = a0, a3 = a0;
    float ts = 0.f;
    int s = g_off[gi*NNODE + wid], e = s + g_ind[gi*NNODE + wid];
    const int* csr = g_csr + gi*EE;
    for (int j = s; j < e; j++) {
        int sn = csr[j];
        float so = g_sout[gi*NNODE + sn];
        ts += so;
        const float4* sr = (const float4*)(q + (size_t)sn * NHID);
        float4 v;
        v = sr[lane];    a0.x+=v.x*so; a0.y+=v.y*so; a0.z+=v.z*so; a0.w+=v.w*so;
        v = sr[lane+32]; a1.x+=v.x*so; a1.y+=v.y*so; a1.z+=v.z*so; a1.w+=v.w*so;
        v = sr[lane+64]; a2.x+=v.x*so; a2.y+=v.y*so; a2.z+=v.z*so; a2.w+=v.w*so;
        v = sr[lane+96]; a3.x+=v.x*so; a3.y+=v.y*so; a3.z+=v.z*so; a3.w+=v.w*so;
    }
    float4* o = (float4*)(outT + (size_t)wid * NHID);
    o[lane] = a0; o[lane+32] = a1; o[lane+64] = a2; o[lane+96] = a3;
    if (lane == 0) g_tvec[gi*NNODE + wid] = ts;
}

__global__ void k_xcepi(const float* __restrict__ gc3b) {
    int n = blockIdx.x; int c = threadIdx.x;
    int g = c_pat[c >> 6];
    float si = g_sin[g*NNODE + n], tv = g_tvec[g*NNODE + n];
    size_t idx = (size_t)n*NHID + c;
    g_xc[idx] = si * g_xc[idx] + si * tv * g_dcat[c] + gc3b[c];
}

// ----------------------------- host orchestration --------------------------
#define SYM(name, var) { void* _p; cudaGetSymbolAddress(&_p, name); var = (float*)_p; }

extern "C" void kernel_launch(void* const* d_in, const int* in_sizes, int n_in,
                              void* d_out, int out_size) {
    const float* in_embed  = (const float*)d_in[0];
    const float* pos_embed = (const float*)d_in[1];
    const float* qkv_w     = (const float*)d_in[2];
    const float* qkv_b     = (const float*)d_in[3];
    const float* attn_w    = (const float*)d_in[4];
    const float* attn_b    = (const float*)d_in[5];
    const float* ff1_w     = (const float*)d_in[6];
    const float* ff1_b     = (const float*)d_in[7];
    const float* ff2_w     = (const float*)d_in[8];
    const float* ff2_b     = (const float*)d_in[9];
    const float* sage1_w   = (const float*)d_in[10];
    const float* sage1_b   = (const float*)d_in[11];
    const float* sage2_w   = (const float*)d_in[12];
    const float* sage2_b   = (const float*)d_in[13];
    const float* gc3_w     = (const float*)d_in[14];
    const float* gc3_b     = (const float*)d_in[15];
    const float* gff1_w    = (const float*)d_in[16];
    const float* gff1_b    = (const float*)d_in[17];
    const float* gff2_w    = (const float*)d_in[18];
    const float* gff2_b    = (const float*)d_in[19];
    const float* ln_g      = (const float*)d_in[20];
    const float* ln_b      = (const float*)d_in[21];
    const int*   in_idxs   = (const int*)d_in[22];
    const int*   mask      = (const int*)d_in[23];   // bool marshalled as int32
    const int*   gt_src    = (const int*)d_in[24];
    const int*   gt_dst    = (const int*)d_in[25];
    const int*   at_src    = (const int*)d_in[26];
    const int*   at_dst    = (const int*)d_in[27];

    float *h, *qkv, *o, *x, *ff, *xf, *P, *Q, *T, *xc, *xg, *fg, *Mb, *Nc, *cc, *dc;
    SYM(g_h, h); SYM(g_qkv, qkv); SYM(g_o, o); SYM(g_x, x); SYM(g_ff, ff);
    SYM(g_xf, xf); SYM(g_P, P); SYM(g_Q, Q); SYM(g_T, T); SYM(g_xc, xc); SYM(g_xg, xg);
    SYM(g_fg, fg); SYM(g_M, Mb); SYM(g_Ncat, Nc); SYM(g_ccat, cc); SYM(g_dcat, dc);

    static int smemSet = 0;
    if (!smemSet) {
        cudaFuncSetAttribute(k_flash, cudaFuncAttributeMaxDynamicSharedMemorySize, FLASH_SMEM);
        smemSet = 1;
    }

    // ---- embedding + mask packing ----
    k_embed<<<NTOK, 128>>>(in_embed, pos_embed, in_idxs);
    k_packmask<<<BB*LL*HEADS/8, 256>>>(mask);

    // ---- transformer layers ----
    for (int l = 0; l < 4; l++) {
        mgemm(h, NHID, qkv_w + (size_t)l*NHID*QKVD, QKVD, qkv, QKVD,
              NTOK, QKVD, NHID, qkv_b + l*QKVD);
        k_flash<<<dim3(LL/128, BB*HEADS), 256, FLASH_SMEM>>>();
        mgemm(o, NHID, attn_w + (size_t)l*NHID*NHID, NHID, x, NHID,
              NTOK, NHID, NHID, attn_b + l*NHID, h, NHID, 2.0f);
        mgemm(x, NHID, ff1_w + (size_t)l*NHID*FFD, FFD, ff, FFD,
              NTOK, FFD, NHID, ff1_b + l*FFD, nullptr, 0, 0.f, /*relu=*/1);
        mgemm(ff, FFD, ff2_w + (size_t)l*FFD*NHID, NHID, h, NHID,
              NTOK, NHID, FFD, ff2_b + l*NHID, x, NHID, 1.0f);
    }

    // ---- graph preprocessing ----
    k_zero_ints<<<(2*NNODE + 255)/256, 256>>>();
    k_count<<<EE/256, 256>>>(gt_src, gt_dst, 0);
    k_count<<<EE/256, 256>>>(at_src, at_dst, 1);
    k_scan<<<1, 1024>>>(0);
    k_scan<<<1, 1024>>>(1);
    k_scatter<<<EE/256, 256>>>(gt_src, gt_dst, 0);
    k_scatter<<<EE/256, 256>>>(at_src, at_dst, 1);
    k_scales<<<(2*NNODE + 255)/256, 256>>>();
    k_copyxf<<<NNODE, 128>>>();

    // ---- propagations (3 per graph) ----
    int propBlocks = (NNODE + 7) / 8;
    for (int g = 0; g < 2; g++) {
        k_prop_sage<<<propBlocks, 256>>>(xf, P, g);
        k_prop_sage<<<propBlocks, 256>>>(P,  Q, g);
        k_prop_gc  <<<propBlocks, 256>>>(Q,  T + (size_t)g*NNODE*NHID, g);
    }

    // ---- collapse per-head weights: M_i = W1 W2, N_i = M_i W3, c_i, d_i ----
    mgemm(sage1_w, NHID, sage2_w, NHID, Mb, NHID, NHID, NHID, NHID,
          nullptr, nullptr, 0, 0.f, 0, 0, HEADS, 1,
          (long long)NHID*NHID, 0, (long long)NHID*NHID, 0, (long long)NHID*NHID, 0);
    mgemm(Mb, NHID, gc3_w, 64, Nc, 64, NHID, 64, NHID,
          nullptr, nullptr, 0, 0.f, 0, 0, HEADS, 1,
          (long long)NHID*NHID, 0, (long long)NHID*64, 0, (long long)NHID*64, 0);
    {
        GP p; p.A=sage1_b; p.B=sage2_w; p.bias=sage2_b; p.res=nullptr; p.C=cc;
        p.lda=NHID; p.ldb=NHID; p.ldc=NHID; p.ldres=0;
        p.M=1; p.N=NHID; p.K=NHID; p.resScale=0; p.relu=0; p.zDiv=1; p.hmode=0;
        p.aO=NHID; p.bO=(long long)NHID*NHID; p.cO=NHID; p.biasO=NHID;
        p.aI=p.bI=p.cI=p.rO=p.rI=0;
        gemm1_k<<<dim3((NHID+63)/64,1,HEADS), 64>>>(p);
    }
    {
        GP p; p.A=cc; p.B=gc3_w; p.bias=nullptr; p.res=nullptr; p.C=dc;
        p.lda=NHID; p.ldb=64; p.ldc=64; p.ldres=0;
        p.M=1; p.N=64; p.K=NHID; p.resScale=0; p.relu=0; p.zDiv=1; p.hmode=0;
        p.aO=NHID; p.bO=(long long)NHID*64; p.cO=64; p.biasO=0;
        p.aI=p.bI=p.cI=p.rO=p.rI=0;
        gemm1_k<<<dim3(1,1,HEADS), 64>>>(p);
    }

    // ---- xc per head: one launch, A = T[(z>>1)&1], via hmode ----
    mgemm(T, NHID, Nc, 64, xc, NHID,
          NNODE, 64, NHID, nullptr, nullptr, 0, 0.f, 0, 0,
          HEADS, 1,
          0, (long long)NNODE*NHID,
          (long long)NHID*64, 0,
          64, 0, 0, 0, 0, /*hmode=*/1);
    k_xcepi<<<NNODE, 512>>>(gc3_b);

    // ---- final: x = hg + LN(xc); ff = relu(x W1+b) W2 + b; zbar = x + LN(ff) ----
    k_ln_add<<<NNODE, 128>>>(xg, xc, h, /*hgMap=*/1, ln_g, ln_b);
    mgemm(xg, NHID, gff1_w, NHID, fg, NHID, NNODE, NHID, NHID, gff1_b,
          nullptr, 0, 0.f, /*relu=*/1);
    mgemm(fg, NHID, gff2_w, NHID, xc, NHID, NNODE, NHID, NHID, gff2_b);
    k_ln_add<<<NNODE, 128>>>((float*)d_out, xc, xg, /*hgMap=*/0, ln_g, ln_b);

    // ---- zg ----
    if (out_size >= NNODE*NHID + BB*NHID)
        k_zg<<<BB, 128>>>((float*)d_out);
}

// round 11
// speedup vs baseline: 1.7513x; 1.4714x over previous
#include <cuda_runtime.h>
#include <cuda_fp16.h>
#include <math.h>
#include <stdint.h>

#define NHID   512
#define HEADS  8
#define BB     16
#define SS     511
#define LL     512
#define NNODE  8176
#define NTOK   8192
#define EE     131072
#define QKVD   1536
#define FFD    2048

// ----------------------------- scratch (device globals) --------------------
__device__ float g_h   [NTOK*NHID];
__device__ float g_x   [NTOK*NHID];
__device__ float g_xf  [NNODE*NHID];
__device__ float g_P   [NNODE*NHID];
__device__ float g_Q   [NNODE*NHID];
__device__ float g_xc  [NNODE*NHID];
__device__ float g_xg  [NNODE*NHID];
__device__ float g_ccat[HEADS*NHID];
__device__ float g_dcat[HEADS*64];
__device__ float g_tvec[2*NNODE];
__device__ float g_sin [2*NNODE];
__device__ float g_sout[2*NNODE];
__device__ float g_inv1[2*NNODE];
__device__ int   g_ind [2*NNODE];
__device__ int   g_outd[2*NNODE];
__device__ int   g_off [2*NNODE];
__device__ int   g_cur [2*NNODE];
__device__ int   g_csr [2*EE];
__device__ unsigned g_pm[(size_t)BB*HEADS*LL*(LL/32)];

// fp16 activations / weights
__device__ __half g_hh  [NTOK*NHID];
__device__ __half g_qkvh[NTOK*QKVD];
__device__ __half g_oh  [NTOK*NHID];
__device__ __half g_xh  [NTOK*NHID];
__device__ __half g_ffh [NTOK*FFD];
__device__ __half g_Th  [2*NNODE*NHID];
__device__ __half g_Mh  [HEADS*NHID*NHID];
__device__ __half g_Nch [HEADS*NHID*64];
__device__ __half g_xgh [NNODE*NHID];
__device__ __half g_fgh [NNODE*NHID];
__device__ __half g_qkvwh [4*NHID*QKVD];
__device__ __half g_attnwh[4*NHID*NHID];
__device__ __half g_ff1wh [4*NHID*FFD];
__device__ __half g_ff2wh [4*FFD*NHID];
__device__ __half g_s1wh  [HEADS*NHID*NHID];
__device__ __half g_s2wh  [HEADS*NHID*NHID];
__device__ __half g_gc3wh [HEADS*NHID*64];
__device__ __half g_gff1wh[NHID*NHID];
__device__ __half g_gff2wh[NHID*NHID];

__constant__ int c_pat[8] = {0,0,1,1,0,0,1,1};

// ----------------------------- helpers -------------------------------------
__device__ __forceinline__ unsigned h2u(float a, float b) {
    __half2 h = __floats2half2_rn(a, b);
    return *reinterpret_cast<unsigned*>(&h);
}
__device__ __forceinline__ uint2 f4h(float4 v) {
    uint2 r; r.x = h2u(v.x, v.y); r.y = h2u(v.z, v.w); return r;
}
__device__ __forceinline__ void ldsm4(unsigned &d0, unsigned &d1, unsigned &d2, unsigned &d3,
                                      unsigned addr) {
    asm volatile("ldmatrix.sync.aligned.m8n8.x4.shared.b16 {%0,%1,%2,%3}, [%4];"
                 : "=r"(d0), "=r"(d1), "=r"(d2), "=r"(d3) : "r"(addr));
}
__device__ __forceinline__ void ldsm2(unsigned &d0, unsigned &d1, unsigned addr) {
    asm volatile("ldmatrix.sync.aligned.m8n8.x2.shared.b16 {%0,%1}, [%2];"
                 : "=r"(d0), "=r"(d1) : "r"(addr));
}
__device__ __forceinline__ void ldsm2t(unsigned &d0, unsigned &d1, unsigned addr) {
    asm volatile("ldmatrix.sync.aligned.m8n8.x2.trans.shared.b16 {%0,%1}, [%2];"
                 : "=r"(d0), "=r"(d1) : "r"(addr));
}
__device__ __forceinline__ void mma16(float* c, const unsigned* a, const unsigned* b) {
    asm volatile(
        "mma.sync.aligned.m16n8k16.row.col.f32.f16.f16.f32 "
        "{%0,%1,%2,%3}, {%4,%5,%6,%7}, {%8,%9}, {%0,%1,%2,%3};"
        : "+f"(c[0]), "+f"(c[1]), "+f"(c[2]), "+f"(c[3])
        : "r"(a[0]), "r"(a[1]), "r"(a[2]), "r"(a[3]), "r"(b[0]), "r"(b[1]));
}
__device__ __forceinline__ void cpa16(unsigned d, const void* s, bool v) {
    asm volatile("cp.async.cg.shared.global [%0], [%1], 16, %2;"
                 :: "r"(d), "l"(s), "r"(v ? 16u : 0u));
}
#define CP_COMMIT asm volatile("cp.async.commit_group;" ::: "memory")
#define CP_WAIT1  asm volatile("cp.async.wait_group 1;" ::: "memory")
#define CP_WAIT0  asm volatile("cp.async.wait_group 0;" ::: "memory")

// ----------------------------- GEMM param block -----------------------------
struct GPH {
    const __half *A, *B;
    const float *bias, *res;
    float *C; __half *Ch;
    int lda, ldb, ldc, ldres;
    int M, N, K;
    float resScale;
    int relu;
    int zDiv, hmode;
    long long aO, aI, bO, bI, cO, cI, rO, rI, biasO;
};
struct GP {
    const float *A, *B, *bias;
    float *C;
    int ldb, N, K;
    long long aO, bO, cO, biasO;
};

// ----------------------------- fp16 cp.async GEMM --------------------------
// 256 thr, tile 128 x BN, 8 warps, K-slice 32 halves, 3 cp.async stages.
template<int BN>
__global__ __launch_bounds__(256, 2) void mma_k(GPH p) {
    constexpr int WGN  = (BN == 128) ? 4 : 2;
    constexpr int WGM  = 8 / WGN;
    constexpr int WM   = 128 / WGM;
    constexpr int WN   = BN / WGN;       // 32
    constexpr int MF   = WM / 16;
    constexpr int NF   = WN / 8;         // 4
    constexpr int ASTH = 56;             // A row stride halves (112B; conflict-free)
    constexpr int BSTH = BN + 8;         // B row stride halves (16B-multiple)
    constexpr int AW   = 128 * ASTH / 2; // words per A stage
    constexpr int BW   = 32 * BSTH / 2;

    extern __shared__ unsigned smw[];
    unsigned sb = (unsigned)__cvta_generic_to_shared(smw);
    unsigned aBase[3], bBase[3];
    #pragma unroll
    for (int s = 0; s < 3; s++) {
        aBase[s] = sb + (unsigned)(s * AW) * 4u;
        bBase[s] = sb + (unsigned)(3 * AW + s * BW) * 4u;
    }

    const __half *A, *B;
    float *C = nullptr; __half *Ch = nullptr;
    const float *bias = nullptr, *res = nullptr;
    if (p.hmode) {
        int hd = blockIdx.z;
        A = p.A + (((hd >> 1) & 1) ? p.aI : 0);
        B = p.B + (size_t)hd * p.bO;
        if (p.C)  C  = p.C  + (size_t)hd * p.cO;
        if (p.Ch) Ch = p.Ch + (size_t)hd * p.cO;
    } else {
        int zo = blockIdx.z / p.zDiv, zi = blockIdx.z % p.zDiv;
        A = p.A + zo * p.aO + zi * p.aI;
        B = p.B + zo * p.bO + zi * p.bI;
        if (p.C)  C  = p.C  + zo * p.cO + zi * p.cI;
        if (p.Ch) Ch = p.Ch + zo * p.cO + zi * p.cI;
        if (p.bias) bias = p.bias + zo * p.biasO;
        if (p.res)  res  = p.res + zo * p.rO + zi * p.rI;
    }

    int tid = threadIdx.x, lane = tid & 31, warp = tid >> 5;
    int wm = warp / WGN, wn = warp % WGN;
    int m0 = blockIdx.x * 128, n0 = blockIdx.y * BN;

    int ar0 = tid >> 2, ac = (tid & 3) * 8;          // A rows ar0, ar0+64
    bool av0 = (m0 + ar0) < p.M, av1 = (m0 + ar0 + 64) < p.M;

    auto issue = [&](int s, int k0) {
        cpa16(aBase[s] + (unsigned)(ar0 * ASTH + ac) * 2u,
              A + (size_t)(m0 + ar0) * p.lda + k0 + ac, av0);
        cpa16(aBase[s] + (unsigned)((ar0 + 64) * ASTH + ac) * 2u,
              A + (size_t)(m0 + ar0 + 64) * p.lda + k0 + ac, av1);
        if (BN == 128) {
            int br = tid >> 4, bc = (tid & 15) * 8;
            cpa16(bBase[s] + (unsigned)(br * BSTH + bc) * 2u,
                  B + (size_t)(k0 + br) * p.ldb + n0 + bc, true);
            cpa16(bBase[s] + (unsigned)((br + 16) * BSTH + bc) * 2u,
                  B + (size_t)(k0 + br + 16) * p.ldb + n0 + bc, true);
        } else {
            int br = tid >> 3, bc = (tid & 7) * 8;
            cpa16(bBase[s] + (unsigned)(br * BSTH + bc) * 2u,
                  B + (size_t)(k0 + br) * p.ldb + n0 + bc, true);
        }
    };

    float acc[MF][NF][4];
    #pragma unroll
    for (int f = 0; f < MF; f++)
        #pragma unroll
        for (int j = 0; j < NF; j++)
            #pragma unroll
            for (int q = 0; q < 4; q++) acc[f][j][q] = 0.f;

    int aRow = (lane & 7) + ((lane >> 3) & 1) * 8;
    unsigned aKoff = ((lane >> 4) & 1) * 16;
    int l15 = lane & 15;
    int bRowK = (l15 & 7) + (l15 >> 3) * 8;

    int nIter = p.K >> 5;
    issue(0, 0);  CP_COMMIT;
    issue(1, 32); CP_COMMIT;

    for (int i = 0; i < nIter; i++) {
        CP_WAIT1;
        __syncthreads();
        if (i + 2 < nIter) issue((i + 2) % 3, (i + 2) * 32);
        CP_COMMIT;

        int s = i % 3;
        unsigned aB = aBase[s], bB = bBase[s];
        #pragma unroll
        for (int kk = 0; kk < 32; kk += 16) {
            unsigned bfr[NF][2];
            #pragma unroll
            for (int j = 0; j < NF; j++) {
                unsigned addr = bB + (unsigned)((kk + bRowK) * BSTH + wn * WN + j * 8) * 2u;
                ldsm2t(bfr[j][0], bfr[j][1], addr);
            }
            #pragma unroll
            for (int f = 0; f < MF; f++) {
                int row = wm * WM + f * 16 + aRow;
                unsigned addr = aB + (unsigned)(row * ASTH + kk) * 2u + aKoff;
                unsigned afr[4];
                ldsm4(afr[0], afr[1], afr[2], afr[3], addr);
                #pragma unroll
                for (int j = 0; j < NF; j++) mma16(acc[f][j], afr, bfr[j]);
            }
        }
    }

    #pragma unroll
    for (int f = 0; f < MF; f++) {
        int r0 = m0 + wm * WM + f * 16 + (lane >> 2);
        int r1 = r0 + 8;
        #pragma unroll
        for (int j = 0; j < NF; j++) {
            int col = n0 + wn * WN + j * 8 + 2 * (lane & 3);
            float b0 = 0.f, b1 = 0.f;
            if (bias) { b0 = bias[col]; b1 = bias[col + 1]; }
            float v0 = acc[f][j][0] + b0, v1 = acc[f][j][1] + b1;
            float v2 = acc[f][j][2] + b0, v3 = acc[f][j][3] + b1;
            if (p.relu) {
                v0 = fmaxf(v0, 0.f); v1 = fmaxf(v1, 0.f);
                v2 = fmaxf(v2, 0.f); v3 = fmaxf(v3, 0.f);
            }
            if (r0 < p.M) {
                if (res) {
                    v0 += p.resScale * res[(size_t)r0 * p.ldres + col];
                    v1 += p.resScale * res[(size_t)r0 * p.ldres + col + 1];
                }
                if (C)  *(float2*)&C[(size_t)r0 * p.ldc + col] = make_float2(v0, v1);
                if (Ch) *(unsigned*)&Ch[(size_t)r0 * p.ldc + col] = h2u(v0, v1);
            }
            if (r1 < p.M) {
                if (res) {
                    v2 += p.resScale * res[(size_t)r1 * p.ldres + col];
                    v3 += p.resScale * res[(size_t)r1 * p.ldres + col + 1];
                }
                if (C)  *(float2*)&C[(size_t)r1 * p.ldc + col] = make_float2(v2, v3);
                if (Ch) *(unsigned*)&Ch[(size_t)r1 * p.ldc + col] = h2u(v2, v3);
            }
        }
    }
}

#define MMA_SMEM(BN) ((3 * (128*56/2) + 3 * (32*((BN)+8)/2)) * 4)

static void mgemm(const __half* A, int lda, const __half* B, int ldb,
                  float* C, __half* Ch, int ldc,
                  int M, int N, int K,
                  const float* bias = nullptr, const float* res = nullptr, int ldres = 0,
                  float resScale = 0.f, int relu = 0,
                  int z = 1, int zDiv = 1,
                  long long aO=0, long long aI=0, long long bO=0, long long bI=0,
                  long long cO=0, long long cI=0, long long rO=0, long long rI=0,
                  long long biasO=0, int hmode = 0) {
    GPH p;
    p.A=A; p.B=B; p.bias=bias; p.res=res; p.C=C; p.Ch=Ch;
    p.lda=lda; p.ldb=ldb; p.ldc=ldc; p.ldres=ldres;
    p.M=M; p.N=N; p.K=K; p.resScale=resScale; p.relu=relu; p.zDiv=zDiv; p.hmode=hmode;
    p.aO=aO; p.aI=aI; p.bO=bO; p.bI=bI; p.cO=cO; p.cI=cI; p.rO=rO; p.rI=rI; p.biasO=biasO;
    if (N % 128 == 0) {
        dim3 grid((M + 127) / 128, N / 128, z);
        mma_k<128><<<grid, 256, MMA_SMEM(128)>>>(p);
    } else {
        dim3 grid((M + 127) / 128, N / 64, z);
        mma_k<64><<<grid, 256, MMA_SMEM(64)>>>(p);
    }
}

// ----------------------------- weight f32->f16 -----------------------------
__global__ void k_tohalf(const float* __restrict__ in, __half* __restrict__ out, int n) {
    int i = (blockIdx.x * blockDim.x + threadIdx.x) * 8;
    if (i < n) {
        uint2 a = f4h(*(const float4*)(in + i));
        uint2 b = f4h(*(const float4*)(in + i + 4));
        *(uint4*)(out + i) = make_uint4(a.x, a.y, b.x, b.y);
    }
}

// ----------------------------- flash attention (fp16, cp.async) ------------
// grid (L/128, B*H), 256 thr. K/V double-buffered cp.async stages.
// smem words: K0=0,V0=2304,K1=4608,V1=6912,P=9216; each K/V stage 64x36 words.
#define KSTW 36
#define FLASH_SMEM ((4*64*KSTW + 128*KSTW) * 4)

__global__ __launch_bounds__(256, 2) void k_flash() {
    extern __shared__ unsigned sm[];
    unsigned sb = (unsigned)__cvta_generic_to_shared(sm);
    unsigned kOff[2] = { sb, sb + 4608u*4u };
    unsigned vOff[2] = { sb + 2304u*4u, sb + 6912u*4u };
    unsigned* sP = sm + 9216;
    unsigned sPb = sb + 9216u*4u;

    int tid = threadIdx.x, lane = tid & 31, w = tid >> 5;
    int m0 = blockIdx.x * 128;
    int bh = blockIdx.y; int h = bh & 7, b = bh >> 3;
    const __half* qb = g_qkvh + (size_t)(b * LL) * QKVD + h * 192;

    int l15 = lane & 15;
    int aRow = (lane & 7) + ((lane >> 3) & 1) * 8;
    unsigned aKoff = ((lane >> 4) & 1) * 16;
    int arow = 16*w + aRow;

    int key = tid >> 2, kc4 = tid & 3;
    auto issue = [&](int st, int kt) {
        const __half* kp = qb + (size_t)(kt*64 + key) * QKVD + 64;
        unsigned kd = kOff[st] + (unsigned)key * 144u;
        cpa16(kd + kc4*16,      kp + kc4*8,       true);
        cpa16(kd + (kc4+4)*16,  kp + (kc4+4)*8,   true);
        unsigned vd = vOff[st] + (unsigned)key * 144u;
        cpa16(vd + kc4*16,      kp + 64 + kc4*8,  true);
        cpa16(vd + (kc4+4)*16,  kp + 64 + (kc4+4)*8, true);
    };

    issue(0, 0); CP_COMMIT;

    // ---- stage Q (raw fp16) through sP, pull 4 k16 fragments to regs ----
    {
        int row = tid >> 1, dh = (tid & 1) * 32;
        const uint4* src = (const uint4*)(qb + (size_t)(m0 + row) * QKVD + dh);
        unsigned* dst = sP + row * KSTW + dh/2;
        #pragma unroll
        for (int c = 0; c < 4; c++) *(uint4*)(dst + c*4) = src[c];
    }
    __syncthreads();
    unsigned qf[4][4];
    #pragma unroll
    for (int kc = 0; kc < 4; kc++)
        ldsm4(qf[kc][0], qf[kc][1], qf[kc][2], qf[kc][3],
              sPb + (unsigned)(arow * KSTW) * 4u + (unsigned)kc * 32u + aKoff);

    float accO[8][4];
    #pragma unroll
    for (int j = 0; j < 8; j++)
        #pragma unroll
        for (int q = 0; q < 4; q++) accO[j][q] = 0.f;
    float m0r = -INFINITY, m1r = -INFINITY, l0r = 0.f, l1r = 0.f;

    const unsigned* pmr0 = g_pm + ((size_t)bh * LL + m0 + 16*w + (lane >> 2)) * 16;
    const unsigned* pmr1 = pmr0 + 8 * 16;

    for (int kt = 0; kt < 8; kt++) {
        CP_WAIT0;
        __syncthreads();            // stage kt visible to all; prev compute done
        if (kt + 1 < 8) { issue((kt + 1) & 1, kt + 1); CP_COMMIT; }
        int st = kt & 1;

        // ---- S = Q K^T ----
        float S[8][4];
        #pragma unroll
        for (int nt = 0; nt < 8; nt++)
            #pragma unroll
            for (int q = 0; q < 4; q++) S[nt][q] = 0.f;
        #pragma unroll
        for (int kc = 0; kc < 4; kc++) {
            #pragma unroll
            for (int nt = 0; nt < 8; nt++) {
                unsigned bb[2];
                unsigned addr = kOff[st] + (unsigned)((nt*8 + (l15 & 7)) * KSTW) * 4u
                                        + (unsigned)kc * 32u + (unsigned)(l15 >> 3) * 16u;
                ldsm2(bb[0], bb[1], addr);
                mma16(S[nt], qf[kc], bb);
            }
        }

        // ---- mask + scale ----
        uint2 mw0 = *(const uint2*)(pmr0 + kt*2);
        uint2 mw1 = *(const uint2*)(pmr1 + kt*2);
        unsigned q0[2] = {mw0.x, mw0.y};
        unsigned q1[2] = {mw1.x, mw1.y};
        float rm0 = -INFINITY, rm1 = -INFINITY;
        #pragma unroll
        for (int nt = 0; nt < 8; nt++) {
            int j0 = nt*8 + 2*(lane & 3), j1 = j0 + 1;
            S[nt][0] = ((q0[j0>>5] >> (j0&31)) & 1u) ? S[nt][0]*0.125f : -INFINITY;
            S[nt][1] = ((q0[j1>>5] >> (j1&31)) & 1u) ? S[nt][1]*0.125f : -INFINITY;
            S[nt][2] = ((q1[j0>>5] >> (j0&31)) & 1u) ? S[nt][2]*0.125f : -INFINITY;
            S[nt][3] = ((q1[j1>>5] >> (j1&31)) & 1u) ? S[nt][3]*0.125f : -INFINITY;
            rm0 = fmaxf(rm0, fmaxf(S[nt][0], S[nt][1]));
            rm1 = fmaxf(rm1, fmaxf(S[nt][2], S[nt][3]));
        }
        rm0 = fmaxf(rm0, __shfl_xor_sync(0xffffffffu, rm0, 1));
        rm0 = fmaxf(rm0, __shfl_xor_sync(0xffffffffu, rm0, 2));
        rm1 = fmaxf(rm1, __shfl_xor_sync(0xffffffffu, rm1, 1));
        rm1 = fmaxf(rm1, __shfl_xor_sync(0xffffffffu, rm1, 2));

        float mn0 = fmaxf(m0r, rm0), mn1 = fmaxf(m1r, rm1);
        float a0 = __expf(m0r - mn0), a1 = __expf(m1r - mn1);
        m0r = mn0; m1r = mn1;

        int prow0 = 16*w + (lane >> 2), prow1 = prow0 + 8;
        float rs0 = 0.f, rs1 = 0.f;
        #pragma unroll
        for (int nt = 0; nt < 8; nt++) {
            int jw = nt*4 + (lane & 3);
            float p00 = __expf(S[nt][0] - mn0), p01 = __expf(S[nt][1] - mn0);
            float p10 = __expf(S[nt][2] - mn1), p11 = __expf(S[nt][3] - mn1);
            rs0 += p00 + p01; rs1 += p10 + p11;
            sP[prow0*KSTW + jw] = h2u(p00, p01);
            sP[prow1*KSTW + jw] = h2u(p10, p11);
        }
        rs0 += __shfl_xor_sync(0xffffffffu, rs0, 1);
        rs0 += __shfl_xor_sync(0xffffffffu, rs0, 2);
        rs1 += __shfl_xor_sync(0xffffffffu, rs1, 1);
        rs1 += __shfl_xor_sync(0xffffffffu, rs1, 2);
        l0r = l0r * a0 + rs0;
        l1r = l1r * a1 + rs1;

        #pragma unroll
        for (int j = 0; j < 8; j++) {
            accO[j][0] *= a0; accO[j][1] *= a0;
            accO[j][2] *= a1; accO[j][3] *= a1;
        }
        __syncwarp();

        // ---- O += P @ V ----
        #pragma unroll
        for (int kc = 0; kc < 4; kc++) {
            unsigned pf[4];
            ldsm4(pf[0], pf[1], pf[2], pf[3],
                  sPb + (unsigned)(arow * KSTW) * 4u + (unsigned)kc * 32u + aKoff);
            #pragma unroll
            for (int nt = 0; nt < 8; nt++) {
                unsigned bb[2];
                unsigned addr = vOff[st] + (unsigned)((kc*16 + (l15 & 7) + (l15 >> 3)*8) * KSTW) * 4u
                                        + (unsigned)nt * 16u;
                ldsm2t(bb[0], bb[1], addr);
                mma16(accO[nt], pf, bb);
            }
        }
    }

    float inv0 = 1.f / l0r, inv1 = 1.f / l1r;
    int r0 = m0 + 16*w + (lane >> 2), r1 = r0 + 8;
    __half* o0 = g_oh + (size_t)(b*LL + r0) * NHID + h*64;
    __half* o1 = g_oh + (size_t)(b*LL + r1) * NHID + h*64;
    #pragma unroll
    for (int nt = 0; nt < 8; nt++) {
        int col = nt*8 + 2*(lane & 3);
        *(unsigned*)&o0[col] = h2u(accO[nt][0]*inv0, accO[nt][1]*inv0);
        *(unsigned*)&o1[col] = h2u(accO[nt][2]*inv1, accO[nt][3]*inv1);
    }
}

// pack mask (int32 bool, layout [b][i][h][j]) -> bits [b][h][i][j/32]
__global__ void k_packmask(const int* __restrict__ mask) {
    int row = blockIdx.x * 8 + (threadIdx.x >> 5);
    int lane = threadIdx.x & 31;
    const int* mr = mask + (size_t)row * LL;
    int b_i = row >> 3, h = row & 7;
    int b = b_i >> 9, i = b_i & 511;
    unsigned* out = g_pm + (((size_t)(b*HEADS + h) * LL + i) << 4);
    #pragma unroll
    for (int wd = 0; wd < 16; wd++) {
        unsigned bits = __ballot_sync(0xffffffffu, mr[wd*32 + lane] != 0);
        if (lane == 0) out[wd] = bits;
    }
}

// ----------------------------- small FFMA GEMM (M=1) -----------------------
__global__ void gemm1_k(GP p) {
    int zo = blockIdx.z;
    const float* A = p.A + zo * p.aO;
    const float* B = p.B + zo * p.bO;
    float* C = p.C + zo * p.cO;
    const float* bias = p.bias ? p.bias + zo * p.biasO : nullptr;
    int n = blockIdx.x * 64 + threadIdx.x;
    if (n >= p.N) return;
    float s = 0.f;
    for (int k = 0; k < p.K; k++) s += A[k] * B[(size_t)k * p.ldb + n];
    if (bias) s += bias[n];
    C[n] = s;
}

// ----------------------------- small kernels -------------------------------
__global__ void k_embed(const float* __restrict__ emb, const float* __restrict__ pos,
                        const int* __restrict__ idxs) {
    int tok = blockIdx.x;
    int b = tok >> 9, s = tok & 511;
    int id = (s == 0) ? 0 : idxs[b*SS + s - 1];
    const float4* e  = (const float4*)(emb + (size_t)id * NHID);
    const float4* pr = (const float4*)(pos + (size_t)s  * NHID);
    float4* hr = (float4*)(g_h + (size_t)tok * NHID);
    uint2*  hh = (uint2*)(g_hh + (size_t)tok * NHID);
    int t = threadIdx.x;
    float4 a = e[t], c = pr[t];
    float4 v = make_float4(a.x+c.x, a.y+c.y, a.z+c.z, a.w+c.w);
    hr[t] = v;
    hh[t] = f4h(v);
}

__global__ void k_ln_add(float* __restrict__ out, const float* __restrict__ inp,
                         const float* __restrict__ base, int hgMap,
                         const float* __restrict__ gw, const float* __restrict__ bw,
                         __half* __restrict__ outH) {
    int n = blockIdx.x;
    const float* xr = inp + (size_t)n * NHID;
    size_t brow;
    if (hgMap) { int b = n / SS, s = n % SS; brow = ((size_t)(b*LL + s + 1)) * NHID; }
    else brow = (size_t)n * NHID;
    int t = threadIdx.x;
    float x[4];
    #pragma unroll
    for (int i = 0; i < 4; i++) x[i] = xr[t + i*128];
    __shared__ float red[128];
    red[t] = x[0]+x[1]+x[2]+x[3]; __syncthreads();
    for (int s = 64; s > 0; s >>= 1) { if (t < s) red[t] += red[t+s]; __syncthreads(); }
    float mu = red[0] * (1.f/512.f); __syncthreads();
    float d[4], vs = 0.f;
    #pragma unroll
    for (int i = 0; i < 4; i++) { d[i] = x[i] - mu; vs += d[i]*d[i]; }
    red[t] = vs; __syncthreads();
    for (int s = 64; s > 0; s >>= 1) { if (t < s) red[t] += red[t+s]; __syncthreads(); }
    float inv = rsqrtf(red[0] * (1.f/512.f) + 1e-5f);
    #pragma unroll
    for (int i = 0; i < 4; i++) {
        int c = t + i*128;
        float v = base[brow + c] + d[i]*inv*gw[c] + bw[c];
        out[(size_t)n*NHID + c] = v;
        if (outH) outH[(size_t)n*NHID + c] = __float2half_rn(v);
    }
}

__global__ void k_zg(float* __restrict__ dout) {
    int b = blockIdx.x; int t = threadIdx.x;
    #pragma unroll
    for (int i = 0; i < 4; i++) {
        int c = t + i*128;
        dout[(size_t)NNODE*NHID + b*NHID + c] = g_h[((size_t)b*LL) * NHID + c];
    }
}

__global__ void k_copyxf() {
    int n = blockIdx.x;
    int b = n / SS, s = n % SS;
    const float4* src = (const float4*)(g_h + ((size_t)(b*LL + s + 1)) * NHID);
    float4* dst = (float4*)(g_xf + (size_t)n * NHID);
    dst[threadIdx.x] = src[threadIdx.x];
}

__global__ void k_zero_ints() {
    int i = blockIdx.x*blockDim.x + threadIdx.x;
    if (i < 2*NNODE) { g_ind[i] = 0; g_outd[i] = 0; g_cur[i] = 0; }
}

__global__ void k_count(const int* __restrict__ src, const int* __restrict__ dst, int gi) {
    int e = blockIdx.x*blockDim.x + threadIdx.x;
    if (e < EE) {
        atomicAdd(&g_ind [gi*NNODE + dst[e]], 1);
        atomicAdd(&g_outd[gi*NNODE + src[e]], 1);
    }
}

__global__ void k_scan(int gi) {
    __shared__ int sh[1024];
    int t = threadIdx.x;
    int base = gi * NNODE;
    int loc[8]; int sum = 0;
    #pragma unroll
    for (int i = 0; i < 8; i++) {
        int idx = t*8 + i;
        int v = (idx < NNODE) ? g_ind[base + idx] : 0;
        loc[i] = sum; sum += v;
    }
    sh[t] = sum; __syncthreads();
    for (int d = 1; d < 1024; d <<= 1) {
        int v = (t >= d) ? sh[t-d] : 0; __syncthreads();
        sh[t] += v; __syncthreads();
    }
    int pre = (t > 0) ? sh[t-1] : 0;
    #pragma unroll
    for (int i = 0; i < 8; i++) {
        int idx = t*8 + i;
        if (idx < NNODE) g_off[base + idx] = pre + loc[i];
    }
}

__global__ void k_scatter(const int* __restrict__ src, const int* __restrict__ dst, int gi) {
    int e = blockIdx.x*blockDim.x + threadIdx.x;
    if (e < EE) {
        int d = dst[e];
        int p = g_off[gi*NNODE + d] + atomicAdd(&g_cur[gi*NNODE + d], 1);
        g_csr[gi*EE + p] = src[e];
    }
}

__global__ void k_scales() {
    int i = blockIdx.x*blockDim.x + threadIdx.x;
    if (i < 2*NNODE) {
        float in = (float)g_ind[i], od = (float)g_outd[i];
        g_sin [i] = rsqrtf(fmaxf(in, 1.f));
        g_sout[i] = rsqrtf(fmaxf(od, 1.f));
        g_inv1[i] = 1.f / (in + 1.f);
    }
}

__global__ void k_prop_sage(const float* __restrict__ x, float* __restrict__ out, int gi) {
    int wid = blockIdx.x * (blockDim.x >> 5) + (threadIdx.x >> 5);
    if (wid >= NNODE) return;
    int lane = threadIdx.x & 31;
    const float4* xr = (const float4*)(x + (size_t)wid * NHID);
    float4 a0 = xr[lane], a1 = xr[lane+32], a2 = xr[lane+64], a3 = xr[lane+96];
    int s = g_off[gi*NNODE + wid], e = s + g_ind[gi*NNODE + wid];
    const int* csr = g_csr + gi*EE;
    for (int j = s; j < e; j++) {
        int sn = csr[j];
        const float4* sr = (const float4*)(x + (size_t)sn * NHID);
        float4 v;
        v = sr[lane];    a0.x+=v.x; a0.y+=v.y; a0.z+=v.z; a0.w+=v.w;
        v = sr[lane+32]; a1.x+=v.x; a1.y+=v.y; a1.z+=v.z; a1.w+=v.w;
        v = sr[lane+64]; a2.x+=v.x; a2.y+=v.y; a2.z+=v.z; a2.w+=v.w;
        v = sr[lane+96]; a3.x+=v.x; a3.y+=v.y; a3.z+=v.z; a3.w+=v.w;
    }
    float sc = g_inv1[gi*NNODE + wid];
    float4* o = (float4*)(out + (size_t)wid * NHID);
    a0.x*=sc; a0.y*=sc; a0.z*=sc; a0.w*=sc; o[lane]    = a0;
    a1.x*=sc; a1.y*=sc; a1.z*=sc; a1.w*=sc; o[lane+32] = a1;
    a2.x*=sc; a2.y*=sc; a2.z*=sc; a2.w*=sc; o[lane+64] = a2;
    a3.x*=sc; a3.y*=sc; a3.z*=sc; a3.w*=sc; o[lane+96] = a3;
}

// T (fp16 out) = sum_in s_out[src]*Q[src];  tvec = sum_in s_out[src]
__global__ void k_prop_gc(const float* __restrict__ q, __half* __restrict__ outT, int gi) {
    int wid = blockIdx.x * (blockDim.x >> 5) + (threadIdx.x >> 5);
    if (wid >= NNODE) return;
    int lane = threadIdx.x & 31;
    float4 a0 = make_float4(0,0,0,0), a1 = a0, a2 = a0, a3 = a0;
    float ts = 0.f;
    int s = g_off[gi*NNODE + wid], e = s + g_ind[gi*NNODE + wid];
    const int* csr = g_csr + gi*EE;
    for (int j = s; j < e; j++) {
        int sn = csr[j];
        float so = g_sout[gi*NNODE + sn];
        ts += so;
        const float4* sr = (const float4*)(q + (size_t)sn * NHID);
        float4 v;
        v = sr[lane];    a0.x+=v.x*so; a0.y+=v.y*so; a0.z+=v.z*so; a0.w+=v.w*so;
        v = sr[lane+32]; a1.x+=v.x*so; a1.y+=v.y*so; a1.z+=v.z*so; a1.w+=v.w*so;
        v = sr[lane+64]; a2.x+=v.x*so; a2.y+=v.y*so; a2.z+=v.z*so; a2.w+=v.w*so;
        v = sr[lane+96]; a3.x+=v.x*so; a3.y+=v.y*so; a3.z+=v.z*so; a3.w+=v.w*so;
    }
    uint2* o = (uint2*)(outT + (size_t)wid * NHID);
    o[lane] = f4h(a0); o[lane+32] = f4h(a1); o[lane+64] = f4h(a2); o[lane+96] = f4h(a3);
    if (lane == 0) g_tvec[gi*NNODE + wid] = ts;
}

__global__ void k_xcepi(const float* __restrict__ gc3b) {
    int n = blockIdx.x; int c = threadIdx.x;
    int g = c_pat[c >> 6];
    float si = g_sin[g*NNODE + n], tv = g_tvec[g*NNODE + n];
    size_t idx = (size_t)n*NHID + c;
    g_xc[idx] = si * g_xc[idx] + si * tv * g_dcat[c] + gc3b[c];
}

// ----------------------------- host orchestration --------------------------
#define SYMF(name, var) { void* _p; cudaGetSymbolAddress(&_p, name); var = (float*)_p; }
#define SYMH(name, var) { void* _p; cudaGetSymbolAddress(&_p, name); var = (__half*)_p; }

extern "C" void kernel_launch(void* const* d_in, const int* in_sizes, int n_in,
                              void* d_out, int out_size) {
    const float* in_embed  = (const float*)d_in[0];
    const float* pos_embed = (const float*)d_in[1];
    const float* qkv_w     = (const float*)d_in[2];
    const float* qkv_b     = (const float*)d_in[3];
    const float* attn_w    = (const float*)d_in[4];
    const float* attn_b    = (const float*)d_in[5];
    const float* ff1_w     = (const float*)d_in[6];
    const float* ff1_b     = (const float*)d_in[7];
    const float* ff2_w     = (const float*)d_in[8];
    const float* ff2_b     = (const float*)d_in[9];
    const float* sage1_w   = (const float*)d_in[10];
    const float* sage1_b   = (const float*)d_in[11];
    const float* sage2_w   = (const float*)d_in[12];
    const float* sage2_b   = (const float*)d_in[13];
    const float* gc3_w     = (const float*)d_in[14];
    const float* gc3_b     = (const float*)d_in[15];
    const float* gff1_w    = (const float*)d_in[16];
    const float* gff1_b    = (const float*)d_in[17];
    const float* gff2_w    = (const float*)d_in[18];
    const float* gff2_b    = (const float*)d_in[19];
    const float* ln_g      = (const float*)d_in[20];
    const float* ln_b      = (const float*)d_in[21];
    const int*   in_idxs   = (const int*)d_in[22];
    const int*   mask      = (const int*)d_in[23];   // bool marshalled as int32
    const int*   gt_src    = (const int*)d_in[24];
    const int*   gt_dst    = (const int*)d_in[25];
    const int*   at_src    = (const int*)d_in[26];
    const int*   at_dst    = (const int*)d_in[27];

    float *h, *x, *xf, *P, *Q, *xc, *xg, *cc, *dc;
    SYMF(g_h, h); SYMF(g_x, x); SYMF(g_xf, xf); SYMF(g_P, P); SYMF(g_Q, Q);
    SYMF(g_xc, xc); SYMF(g_xg, xg); SYMF(g_ccat, cc); SYMF(g_dcat, dc);
    __half *hh, *qkvh, *oh, *xh, *ffh, *Th, *Mh, *Nch, *xgh, *fgh;
    __half *qkvwh, *attnwh, *ff1wh, *ff2wh, *s1wh, *s2wh, *gc3wh, *gff1wh, *gff2wh;
    SYMH(g_hh, hh); SYMH(g_qkvh, qkvh); SYMH(g_oh, oh); SYMH(g_xh, xh); SYMH(g_ffh, ffh);
    SYMH(g_Th, Th); SYMH(g_Mh, Mh); SYMH(g_Nch, Nch); SYMH(g_xgh, xgh); SYMH(g_fgh, fgh);
    SYMH(g_qkvwh, qkvwh); SYMH(g_attnwh, attnwh); SYMH(g_ff1wh, ff1wh);
    SYMH(g_ff2wh, ff2wh); SYMH(g_s1wh, s1wh); SYMH(g_s2wh, s2wh);
    SYMH(g_gc3wh, gc3wh); SYMH(g_gff1wh, gff1wh); SYMH(g_gff2wh, gff2wh);

    static int smemSet = 0;
    if (!smemSet) {
        cudaFuncSetAttribute(k_flash, cudaFuncAttributeMaxDynamicSharedMemorySize, FLASH_SMEM);
        cudaFuncSetAttribute(mma_k<128>, cudaFuncAttributeMaxDynamicSharedMemorySize, MMA_SMEM(128));
        cudaFuncSetAttribute(mma_k<64>,  cudaFuncAttributeMaxDynamicSharedMemorySize, MMA_SMEM(64));
        smemSet = 1;
    }

    // ---- weight f32 -> f16 (once per launch) ----
    #define TOH(src, dst, n) k_tohalf<<<((n)/8 + 255)/256, 256>>>(src, dst, n)
    TOH(qkv_w,  qkvwh,  4*NHID*QKVD);
    TOH(attn_w, attnwh, 4*NHID*NHID);
    TOH(ff1_w,  ff1wh,  4*NHID*FFD);
    TOH(ff2_w,  ff2wh,  4*FFD*NHID);
    TOH(sage1_w, s1wh,  HEADS*NHID*NHID);
    TOH(sage2_w, s2wh,  HEADS*NHID*NHID);
    TOH(gc3_w,  gc3wh,  HEADS*NHID*64);
    TOH(gff1_w, gff1wh, NHID*NHID);
    TOH(gff2_w, gff2wh, NHID*NHID);

    // ---- embedding + mask packing ----
    k_embed<<<NTOK, 128>>>(in_embed, pos_embed, in_idxs);
    k_packmask<<<BB*LL*HEADS/8, 256>>>(mask);

    // ---- transformer layers ----
    for (int l = 0; l < 4; l++) {
        // qkvh = f16(hh @ W + b)
        mgemm(hh, NHID, qkvwh + (size_t)l*NHID*QKVD, QKVD, nullptr, qkvh, QKVD,
              NTOK, QKVD, NHID, qkv_b + l*QKVD);
        // oh = attention(qkvh)
        k_flash<<<dim3(LL/128, BB*HEADS), 256, FLASH_SMEM>>>();
        // x = 2h + (oh @ Wout + b); xh shadow
        mgemm(oh, NHID, attnwh + (size_t)l*NHID*NHID, NHID, x, xh, NHID,
              NTOK, NHID, NHID, attn_b + l*NHID, h, NHID, 2.0f);
        // ffh = f16(relu(xh @ W1 + b1))
        mgemm(xh, NHID, ff1wh + (size_t)l*NHID*FFD, FFD, nullptr, ffh, FFD,
              NTOK, FFD, NHID, ff1_b + l*FFD, nullptr, 0, 0.f, /*relu=*/1);
        // h = x + (ffh @ W2 + b2); hh shadow
        mgemm(ffh, FFD, ff2wh + (size_t)l*FFD*NHID, NHID, h, hh, NHID,
              NTOK, NHID, FFD, ff2_b + l*NHID, x, NHID, 1.0f);
    }

    // ---- graph preprocessing ----
    k_zero_ints<<<(2*NNODE + 255)/256, 256>>>();
    k_count<<<EE/256, 256>>>(gt_src, gt_dst, 0);
    k_count<<<EE/256, 256>>>(at_src, at_dst, 1);
    k_scan<<<1, 1024>>>(0);
    k_scan<<<1, 1024>>>(1);
    k_scatter<<<EE/256, 256>>>(gt_src, gt_dst, 0);
    k_scatter<<<EE/256, 256>>>(at_src, at_dst, 1);
    k_scales<<<(2*NNODE + 255)/256, 256>>>();
    k_copyxf<<<NNODE, 128>>>();

    // ---- propagations (3 per graph; T emitted fp16) ----
    int propBlocks = (NNODE + 7) / 8;
    for (int g = 0; g < 2; g++) {
        k_prop_sage<<<propBlocks, 256>>>(xf, P, g);
        k_prop_sage<<<propBlocks, 256>>>(P,  Q, g);
        k_prop_gc  <<<propBlocks, 256>>>(Q,  Th + (size_t)g*NNODE*NHID, g);
    }

    // ---- collapse per-head weights ----
    mgemm(s1wh, NHID, s2wh, NHID, nullptr, Mh, NHID, NHID, NHID, NHID,
          nullptr, nullptr, 0, 0.f, 0, HEADS, 1,
          (long long)NHID*NHID, 0, (long long)NHID*NHID, 0, (long long)NHID*NHID, 0);
    mgemm(Mh, NHID, gc3wh, 64, nullptr, Nch, 64, NHID, 64, NHID,
          nullptr, nullptr, 0, 0.f, 0, HEADS, 1,
          (long long)NHID*NHID, 0, (long long)NHID*64, 0, (long long)NHID*64, 0);
    {
        GP p; p.A=sage1_b; p.B=sage2_w; p.bias=sage2_b; p.C=cc;
        p.ldb=NHID; p.N=NHID; p.K=NHID;
        p.aO=NHID; p.bO=(long long)NHID*NHID; p.cO=NHID; p.biasO=NHID;
        gemm1_k<<<dim3((NHID+63)/64,1,HEADS), 64>>>(p);
    }
    {
        GP p; p.A=cc; p.B=gc3_w; p.bias=nullptr; p.C=dc;
        p.ldb=64; p.N=64; p.K=NHID;
        p.aO=NHID; p.bO=(long long)NHID*64; p.cO=64; p.biasO=0;
        gemm1_k<<<dim3(1,1,HEADS), 64>>>(p);
    }

    // ---- xc per head: A = Th[(z>>1)&1] via hmode ----
    mgemm(Th, NHID, Nch, 64, xc, nullptr, NHID,
          NNODE, 64, NHID, nullptr, nullptr, 0, 0.f, 0,
          HEADS, 1,
          0, (long long)NNODE*NHID,
          (long long)NHID*64, 0,
          64, 0, 0, 0, 0, /*hmode=*/1);
    k_xcepi<<<NNODE, 512>>>(gc3_b);

    // ---- final: xg = hg + LN(xc); ff path; zbar = xg + LN(ff) ----
    k_ln_add<<<NNODE, 128>>>(xg, xc, h, /*hgMap=*/1, ln_g, ln_b, xgh);
    mgemm(xgh, NHID, gff1wh, NHID, nullptr, fgh, NHID,
          NNODE, NHID, NHID, gff1_b, nullptr, 0, 0.f, /*relu=*/1);
    mgemm(fgh, NHID, gff2wh, NHID, xc, nullptr, NHID,
          NNODE, NHID, NHID, gff2_b);
    k_ln_add<<<NNODE, 128>>>((float*)d_out, xc, xg, /*hgMap=*/0, ln_g, ln_b, nullptr);

    // ---- zg ----
    if (out_size >= NNODE*NHID + BB*NHID)
        k_zg<<<BB, 128>>>((float*)d_out);
}

// round 12
// speedup vs baseline: 1.8273x; 1.0434x over previous
#include <cuda_runtime.h>
#include <cuda_fp16.h>
#include <math.h>
#include <stdint.h>

#define NHID   512
#define HEADS  8
#define BB     16
#define SS     511
#define LL     512
#define NNODE  8176
#define NTOK   8192
#define EE     131072
#define QKVD   1536
#define FFD    2048

// ----------------------------- scratch (device globals) --------------------
__device__ float g_h   [NTOK*NHID];
__device__ float g_x   [NTOK*NHID];
__device__ float g_xc  [NNODE*NHID];
__device__ float g_xg  [NNODE*NHID];
__device__ float g_ccat[HEADS*NHID];
__device__ float g_dcat[HEADS*64];
__device__ float g_tvec[2*NNODE];
__device__ float g_sin [2*NNODE];
__device__ float g_sout[2*NNODE];
__device__ float g_inv1[2*NNODE];
__device__ int   g_ind [2*NNODE];
__device__ int   g_outd[2*NNODE];
__device__ int   g_off [2*NNODE];
__device__ int   g_cur [2*NNODE];
__device__ int   g_csr [2*EE];
__device__ unsigned g_pm[(size_t)BB*HEADS*LL*(LL/32)];

// fp16 activations / weights
__device__ __half g_hh  [NTOK*NHID];
__device__ __half g_qkvh[NTOK*QKVD];
__device__ __half g_oh  [NTOK*NHID];
__device__ __half g_xh  [NTOK*NHID];
__device__ __half g_ffh [NTOK*FFD];
__device__ __half g_xfh [NNODE*NHID];
__device__ __half g_Ph  [2*NNODE*NHID];
__device__ __half g_Qh  [2*NNODE*NHID];
__device__ __half g_Th  [2*NNODE*NHID];
__device__ __half g_Mh  [HEADS*NHID*NHID];
__device__ __half g_Nch [HEADS*NHID*64];
__device__ __half g_xgh [NNODE*NHID];
__device__ __half g_fgh [NNODE*NHID];
__device__ __half g_qkvwh [4*NHID*QKVD];
__device__ __half g_attnwh[4*NHID*NHID];
__device__ __half g_ff1wh [4*NHID*FFD];
__device__ __half g_ff2wh [4*FFD*NHID];
__device__ __half g_s1wh  [HEADS*NHID*NHID];
__device__ __half g_s2wh  [HEADS*NHID*NHID];
__device__ __half g_gc3wh [HEADS*NHID*64];
__device__ __half g_gff1wh[NHID*NHID];
__device__ __half g_gff2wh[NHID*NHID];

__constant__ int c_pat[8] = {0,0,1,1,0,0,1,1};

// ----------------------------- helpers -------------------------------------
__device__ __forceinline__ unsigned h2u(float a, float b) {
    __half2 h = __floats2half2_rn(a, b);
    return *reinterpret_cast<unsigned*>(&h);
}
__device__ __forceinline__ uint2 f4h(float4 v) {
    uint2 r; r.x = h2u(v.x, v.y); r.y = h2u(v.z, v.w); return r;
}
__device__ __forceinline__ void addh8(float* a, uint4 u, float s) {
    __half2* hp = (__half2*)&u;
    #pragma unroll
    for (int i = 0; i < 4; i++) {
        float2 f = __half22float2(hp[i]);
        a[2*i]   += f.x * s;
        a[2*i+1] += f.y * s;
    }
}
__device__ __forceinline__ uint4 pack8(const float* a, float s) {
    return make_uint4(h2u(a[0]*s, a[1]*s), h2u(a[2]*s, a[3]*s),
                      h2u(a[4]*s, a[5]*s), h2u(a[6]*s, a[7]*s));
}
__device__ __forceinline__ void ldsm4(unsigned &d0, unsigned &d1, unsigned &d2, unsigned &d3,
                                      unsigned addr) {
    asm volatile("ldmatrix.sync.aligned.m8n8.x4.shared.b16 {%0,%1,%2,%3}, [%4];"
                 : "=r"(d0), "=r"(d1), "=r"(d2), "=r"(d3) : "r"(addr));
}
__device__ __forceinline__ void ldsm2(unsigned &d0, unsigned &d1, unsigned addr) {
    asm volatile("ldmatrix.sync.aligned.m8n8.x2.shared.b16 {%0,%1}, [%2];"
                 : "=r"(d0), "=r"(d1) : "r"(addr));
}
__device__ __forceinline__ void ldsm2t(unsigned &d0, unsigned &d1, unsigned addr) {
    asm volatile("ldmatrix.sync.aligned.m8n8.x2.trans.shared.b16 {%0,%1}, [%2];"
                 : "=r"(d0), "=r"(d1) : "r"(addr));
}
__device__ __forceinline__ void mma16(float* c, const unsigned* a, const unsigned* b) {
    asm volatile(
        "mma.sync.aligned.m16n8k16.row.col.f32.f16.f16.f32 "
        "{%0,%1,%2,%3}, {%4,%5,%6,%7}, {%8,%9}, {%0,%1,%2,%3};"
        : "+f"(c[0]), "+f"(c[1]), "+f"(c[2]), "+f"(c[3])
        : "r"(a[0]), "r"(a[1]), "r"(a[2]), "r"(a[3]), "r"(b[0]), "r"(b[1]));
}
__device__ __forceinline__ void cpa16(unsigned d, const void* s, bool v) {
    asm volatile("cp.async.cg.shared.global [%0], [%1], 16, %2;"
                 :: "r"(d), "l"(s), "r"(v ? 16u : 0u));
}
#define CP_COMMIT asm volatile("cp.async.commit_group;" ::: "memory")
#define CP_WAIT1  asm volatile("cp.async.wait_group 1;" ::: "memory")
#define CP_WAIT0  asm volatile("cp.async.wait_group 0;" ::: "memory")

// ----------------------------- GEMM param block -----------------------------
struct GPH {
    const __half *A, *B;
    const float *bias, *res;
    float *C; __half *Ch;
    int lda, ldb, ldc, ldres;
    int M, N, K;
    float resScale;
    int relu;
    int zDiv, hmode;
    long long aO, aI, bO, bI, cO, cI, rO, rI, biasO;
};
struct GP {
    const float *A, *B, *bias;
    float *C;
    int ldb, N, K;
    long long aO, bO, cO, biasO;
};

// ----------------------------- fp16 cp.async GEMM --------------------------
// 256 thr, tile 128 x BN, 8 warps, K-slice 32 halves, 3 cp.async stages.
template<int BN>
__global__ __launch_bounds__(256, 2) void mma_k(GPH p) {
    constexpr int WGN  = (BN == 128) ? 4 : 2;
    constexpr int WGM  = 8 / WGN;
    constexpr int WM   = 128 / WGM;
    constexpr int WN   = BN / WGN;
    constexpr int MF   = WM / 16;
    constexpr int NF   = WN / 8;
    constexpr int ASTH = 56;
    constexpr int BSTH = BN + 8;
    constexpr int AW   = 128 * ASTH / 2;
    constexpr int BW   = 32 * BSTH / 2;

    extern __shared__ unsigned smw[];
    unsigned sb = (unsigned)__cvta_generic_to_shared(smw);
    unsigned aBase[3], bBase[3];
    #pragma unroll
    for (int s = 0; s < 3; s++) {
        aBase[s] = sb + (unsigned)(s * AW) * 4u;
        bBase[s] = sb + (unsigned)(3 * AW + s * BW) * 4u;
    }

    const __half *A, *B;
    float *C = nullptr; __half *Ch = nullptr;
    const float *bias = nullptr, *res = nullptr;
    if (p.hmode) {
        int hd = blockIdx.z;
        A = p.A + (((hd >> 1) & 1) ? p.aI : 0);
        B = p.B + (size_t)hd * p.bO;
        if (p.C)  C  = p.C  + (size_t)hd * p.cO;
        if (p.Ch) Ch = p.Ch + (size_t)hd * p.cO;
    } else {
        int zo = blockIdx.z / p.zDiv, zi = blockIdx.z % p.zDiv;
        A = p.A + zo * p.aO + zi * p.aI;
        B = p.B + zo * p.bO + zi * p.bI;
        if (p.C)  C  = p.C  + zo * p.cO + zi * p.cI;
        if (p.Ch) Ch = p.Ch + zo * p.cO + zi * p.cI;
        if (p.bias) bias = p.bias + zo * p.biasO;
        if (p.res)  res  = p.res + zo * p.rO + zi * p.rI;
    }

    int tid = threadIdx.x, lane = tid & 31, warp = tid >> 5;
    int wm = warp / WGN, wn = warp % WGN;
    int m0 = blockIdx.x * 128, n0 = blockIdx.y * BN;

    int ar0 = tid >> 2, ac = (tid & 3) * 8;
    bool av0 = (m0 + ar0) < p.M, av1 = (m0 + ar0 + 64) < p.M;

    auto issue = [&](int s, int k0) {
        cpa16(aBase[s] + (unsigned)(ar0 * ASTH + ac) * 2u,
              A + (size_t)(m0 + ar0) * p.lda + k0 + ac, av0);
        cpa16(aBase[s] + (unsigned)((ar0 + 64) * ASTH + ac) * 2u,
              A + (size_t)(m0 + ar0 + 64) * p.lda + k0 + ac, av1);
        if (BN == 128) {
            int br = tid >> 4, bc = (tid & 15) * 8;
            cpa16(bBase[s] + (unsigned)(br * BSTH + bc) * 2u,
                  B + (size_t)(k0 + br) * p.ldb + n0 + bc, true);
            cpa16(bBase[s] + (unsigned)((br + 16) * BSTH + bc) * 2u,
                  B + (size_t)(k0 + br + 16) * p.ldb + n0 + bc, true);
        } else {
            int br = tid >> 3, bc = (tid & 7) * 8;
            cpa16(bBase[s] + (unsigned)(br * BSTH + bc) * 2u,
                  B + (size_t)(k0 + br) * p.ldb + n0 + bc, true);
        }
    };

    float acc[MF][NF][4];
    #pragma unroll
    for (int f = 0; f < MF; f++)
        #pragma unroll
        for (int j = 0; j < NF; j++)
            #pragma unroll
            for (int q = 0; q < 4; q++) acc[f][j][q] = 0.f;

    int aRow = (lane & 7) + ((lane >> 3) & 1) * 8;
    unsigned aKoff = ((lane >> 4) & 1) * 16;
    int l15 = lane & 15;
    int bRowK = (l15 & 7) + (l15 >> 3) * 8;

    int nIter = p.K >> 5;
    issue(0, 0);  CP_COMMIT;
    issue(1, 32); CP_COMMIT;

    for (int i = 0; i < nIter; i++) {
        CP_WAIT1;
        __syncthreads();
        if (i + 2 < nIter) issue((i + 2) % 3, (i + 2) * 32);
        CP_COMMIT;

        int s = i % 3;
        unsigned aB = aBase[s], bB = bBase[s];
        #pragma unroll
        for (int kk = 0; kk < 32; kk += 16) {
            unsigned bfr[NF][2];
            #pragma unroll
            for (int j = 0; j < NF; j++) {
                unsigned addr = bB + (unsigned)((kk + bRowK) * BSTH + wn * WN + j * 8) * 2u;
                ldsm2t(bfr[j][0], bfr[j][1], addr);
            }
            #pragma unroll
            for (int f = 0; f < MF; f++) {
                int row = wm * WM + f * 16 + aRow;
                unsigned addr = aB + (unsigned)(row * ASTH + kk) * 2u + aKoff;
                unsigned afr[4];
                ldsm4(afr[0], afr[1], afr[2], afr[3], addr);
                #pragma unroll
                for (int j = 0; j < NF; j++) mma16(acc[f][j], afr, bfr[j]);
            }
        }
    }

    #pragma unroll
    for (int f = 0; f < MF; f++) {
        int r0 = m0 + wm * WM + f * 16 + (lane >> 2);
        int r1 = r0 + 8;
        #pragma unroll
        for (int j = 0; j < NF; j++) {
            int col = n0 + wn * WN + j * 8 + 2 * (lane & 3);
            float b0 = 0.f, b1 = 0.f;
            if (bias) { b0 = bias[col]; b1 = bias[col + 1]; }
            float v0 = acc[f][j][0] + b0, v1 = acc[f][j][1] + b1;
            float v2 = acc[f][j][2] + b0, v3 = acc[f][j][3] + b1;
            if (p.relu) {
                v0 = fmaxf(v0, 0.f); v1 = fmaxf(v1, 0.f);
                v2 = fmaxf(v2, 0.f); v3 = fmaxf(v3, 0.f);
            }
            if (r0 < p.M) {
                if (res) {
                    v0 += p.resScale * res[(size_t)r0 * p.ldres + col];
                    v1 += p.resScale * res[(size_t)r0 * p.ldres + col + 1];
                }
                if (C)  *(float2*)&C[(size_t)r0 * p.ldc + col] = make_float2(v0, v1);
                if (Ch) *(unsigned*)&Ch[(size_t)r0 * p.ldc + col] = h2u(v0, v1);
            }
            if (r1 < p.M) {
                if (res) {
                    v2 += p.resScale * res[(size_t)r1 * p.ldres + col];
                    v3 += p.resScale * res[(size_t)r1 * p.ldres + col + 1];
                }
                if (C)  *(float2*)&C[(size_t)r1 * p.ldc + col] = make_float2(v2, v3);
                if (Ch) *(unsigned*)&Ch[(size_t)r1 * p.ldc + col] = h2u(v2, v3);
            }
        }
    }
}

#define MMA_SMEM(BN) ((3 * (128*56/2) + 3 * (32*((BN)+8)/2)) * 4)

static void mgemm(const __half* A, int lda, const __half* B, int ldb,
                  float* C, __half* Ch, int ldc,
                  int M, int N, int K,
                  const float* bias = nullptr, const float* res = nullptr, int ldres = 0,
                  float resScale = 0.f, int relu = 0,
                  int z = 1, int zDiv = 1,
                  long long aO=0, long long aI=0, long long bO=0, long long bI=0,
                  long long cO=0, long long cI=0, long long rO=0, long long rI=0,
                  long long biasO=0, int hmode = 0) {
    GPH p;
    p.A=A; p.B=B; p.bias=bias; p.res=res; p.C=C; p.Ch=Ch;
    p.lda=lda; p.ldb=ldb; p.ldc=ldc; p.ldres=ldres;
    p.M=M; p.N=N; p.K=K; p.resScale=resScale; p.relu=relu; p.zDiv=zDiv; p.hmode=hmode;
    p.aO=aO; p.aI=aI; p.bO=bO; p.bI=bI; p.cO=cO; p.cI=cI; p.rO=rO; p.rI=rI; p.biasO=biasO;
    if (N % 128 == 0) {
        dim3 grid((M + 127) / 128, N / 128, z);
        mma_k<128><<<grid, 256, MMA_SMEM(128)>>>(p);
    } else {
        dim3 grid((M + 127) / 128, N / 64, z);
        mma_k<64><<<grid, 256, MMA_SMEM(64)>>>(p);
    }
}

// ----------------------------- weight f32->f16 -----------------------------
__global__ void k_tohalf(const float* __restrict__ in, __half* __restrict__ out, int n) {
    int i = (blockIdx.x * blockDim.x + threadIdx.x) * 8;
    if (i < n) {
        uint2 a = f4h(*(const float4*)(in + i));
        uint2 b = f4h(*(const float4*)(in + i + 4));
        *(uint4*)(out + i) = make_uint4(a.x, a.y, b.x, b.y);
    }
}

// ----------------------------- flash attention (fp16, cp.async) ------------
#define KSTW 36
#define FLASH_SMEM ((4*64*KSTW + 128*KSTW) * 4)

__global__ __launch_bounds__(256, 2) void k_flash() {
    extern __shared__ unsigned sm[];
    unsigned sb = (unsigned)__cvta_generic_to_shared(sm);
    unsigned kOff[2] = { sb, sb + 4608u*4u };
    unsigned vOff[2] = { sb + 2304u*4u, sb + 6912u*4u };
    unsigned* sP = sm + 9216;
    unsigned sPb = sb + 9216u*4u;

    int tid = threadIdx.x, lane = tid & 31, w = tid >> 5;
    int m0 = blockIdx.x * 128;
    int bh = blockIdx.y; int h = bh & 7, b = bh >> 3;
    const __half* qb = g_qkvh + (size_t)(b * LL) * QKVD + h * 192;

    int l15 = lane & 15;
    int aRow = (lane & 7) + ((lane >> 3) & 1) * 8;
    unsigned aKoff = ((lane >> 4) & 1) * 16;
    int arow = 16*w + aRow;

    int key = tid >> 2, kc4 = tid & 3;
    auto issue = [&](int st, int kt) {
        const __half* kp = qb + (size_t)(kt*64 + key) * QKVD + 64;
        unsigned kd = kOff[st] + (unsigned)key * 144u;
        cpa16(kd + kc4*16,      kp + kc4*8,       true);
        cpa16(kd + (kc4+4)*16,  kp + (kc4+4)*8,   true);
        unsigned vd = vOff[st] + (unsigned)key * 144u;
        cpa16(vd + kc4*16,      kp + 64 + kc4*8,  true);
        cpa16(vd + (kc4+4)*16,  kp + 64 + (kc4+4)*8, true);
    };

    issue(0, 0); CP_COMMIT;

    {
        int row = tid >> 1, dh = (tid & 1) * 32;
        const uint4* src = (const uint4*)(qb + (size_t)(m0 + row) * QKVD + dh);
        unsigned* dst = sP + row * KSTW + dh/2;
        #pragma unroll
        for (int c = 0; c < 4; c++) *(uint4*)(dst + c*4) = src[c];
    }
    __syncthreads();
    unsigned qf[4][4];
    #pragma unroll
    for (int kc = 0; kc < 4; kc++)
        ldsm4(qf[kc][0], qf[kc][1], qf[kc][2], qf[kc][3],
              sPb + (unsigned)(arow * KSTW) * 4u + (unsigned)kc * 32u + aKoff);

    float accO[8][4];
    #pragma unroll
    for (int j = 0; j < 8; j++)
        #pragma unroll
        for (int q = 0; q < 4; q++) accO[j][q] = 0.f;
    float m0r = -INFINITY, m1r = -INFINITY, l0r = 0.f, l1r = 0.f;

    const unsigned* pmr0 = g_pm + ((size_t)bh * LL + m0 + 16*w + (lane >> 2)) * 16;
    const unsigned* pmr1 = pmr0 + 8 * 16;

    for (int kt = 0; kt < 8; kt++) {
        CP_WAIT0;
        __syncthreads();
        if (kt + 1 < 8) { issue((kt + 1) & 1, kt + 1); CP_COMMIT; }
        int st = kt & 1;

        float S[8][4];
        #pragma unroll
        for (int nt = 0; nt < 8; nt++)
            #pragma unroll
            for (int q = 0; q < 4; q++) S[nt][q] = 0.f;
        #pragma unroll
        for (int kc = 0; kc < 4; kc++) {
            #pragma unroll
            for (int nt = 0; nt < 8; nt++) {
                unsigned bb[2];
                unsigned addr = kOff[st] + (unsigned)((nt*8 + (l15 & 7)) * KSTW) * 4u
                                        + (unsigned)kc * 32u + (unsigned)(l15 >> 3) * 16u;
                ldsm2(bb[0], bb[1], addr);
                mma16(S[nt], qf[kc], bb);
            }
        }

        uint2 mw0 = *(const uint2*)(pmr0 + kt*2);
        uint2 mw1 = *(const uint2*)(pmr1 + kt*2);
        unsigned q0[2] = {mw0.x, mw0.y};
        unsigned q1[2] = {mw1.x, mw1.y};
        float rm0 = -INFINITY, rm1 = -INFINITY;
        #pragma unroll
        for (int nt = 0; nt < 8; nt++) {
            int j0 = nt*8 + 2*(lane & 3), j1 = j0 + 1;
            S[nt][0] = ((q0[j0>>5] >> (j0&31)) & 1u) ? S[nt][0]*0.125f : -INFINITY;
            S[nt][1] = ((q0[j1>>5] >> (j1&31)) & 1u) ? S[nt][1]*0.125f : -INFINITY;
            S[nt][2] = ((q1[j0>>5] >> (j0&31)) & 1u) ? S[nt][2]*0.125f : -INFINITY;
            S[nt][3] = ((q1[j1>>5] >> (j1&31)) & 1u) ? S[nt][3]*0.125f : -INFINITY;
            rm0 = fmaxf(rm0, fmaxf(S[nt][0], S[nt][1]));
            rm1 = fmaxf(rm1, fmaxf(S[nt][2], S[nt][3]));
        }
        rm0 = fmaxf(rm0, __shfl_xor_sync(0xffffffffu, rm0, 1));
        rm0 = fmaxf(rm0, __shfl_xor_sync(0xffffffffu, rm0, 2));
        rm1 = fmaxf(rm1, __shfl_xor_sync(0xffffffffu, rm1, 1));
        rm1 = fmaxf(rm1, __shfl_xor_sync(0xffffffffu, rm1, 2));

        float mn0 = fmaxf(m0r, rm0), mn1 = fmaxf(m1r, rm1);
        float a0 = __expf(m0r - mn0), a1 = __expf(m1r - mn1);
        m0r = mn0; m1r = mn1;

        int prow0 = 16*w + (lane >> 2), prow1 = prow0 + 8;
        float rs0 = 0.f, rs1 = 0.f;
        #pragma unroll
        for (int nt = 0; nt < 8; nt++) {
            int jw = nt*4 + (lane & 3);
            float p00 = __expf(S[nt][0] - mn0), p01 = __expf(S[nt][1] - mn0);
            float p10 = __expf(S[nt][2] - mn1), p11 = __expf(S[nt][3] - mn1);
            rs0 += p00 + p01; rs1 += p10 + p11;
            sP[prow0*KSTW + jw] = h2u(p00, p01);
            sP[prow1*KSTW + jw] = h2u(p10, p11);
        }
        rs0 += __shfl_xor_sync(0xffffffffu, rs0, 1);
        rs0 += __shfl_xor_sync(0xffffffffu, rs0, 2);
        rs1 += __shfl_xor_sync(0xffffffffu, rs1, 1);
        rs1 += __shfl_xor_sync(0xffffffffu, rs1, 2);
        l0r = l0r * a0 + rs0;
        l1r = l1r * a1 + rs1;

        #pragma unroll
        for (int j = 0; j < 8; j++) {
            accO[j][0] *= a0; accO[j][1] *= a0;
            accO[j][2] *= a1; accO[j][3] *= a1;
        }
        __syncwarp();

        #pragma unroll
        for (int kc = 0; kc < 4; kc++) {
            unsigned pf[4];
            ldsm4(pf[0], pf[1], pf[2], pf[3],
                  sPb + (unsigned)(arow * KSTW) * 4u + (unsigned)kc * 32u + aKoff);
            #pragma unroll
            for (int nt = 0; nt < 8; nt++) {
                unsigned bb[2];
                unsigned addr = vOff[st] + (unsigned)((kc*16 + (l15 & 7) + (l15 >> 3)*8) * KSTW) * 4u
                                        + (unsigned)nt * 16u;
                ldsm2t(bb[0], bb[1], addr);
                mma16(accO[nt], pf, bb);
            }
        }
    }

    float inv0 = 1.f / l0r, inv1 = 1.f / l1r;
    int r0 = m0 + 16*w + (lane >> 2), r1 = r0 + 8;
    __half* o0 = g_oh + (size_t)(b*LL + r0) * NHID + h*64;
    __half* o1 = g_oh + (size_t)(b*LL + r1) * NHID + h*64;
    #pragma unroll
    for (int nt = 0; nt < 8; nt++) {
        int col = nt*8 + 2*(lane & 3);
        *(unsigned*)&o0[col] = h2u(accO[nt][0]*inv0, accO[nt][1]*inv0);
        *(unsigned*)&o1[col] = h2u(accO[nt][2]*inv1, accO[nt][3]*inv1);
    }
}

// pack mask (int32 bool, layout [b][i][h][j]) -> bits [b][h][i][j/32]
__global__ void k_packmask(const int* __restrict__ mask) {
    int row = blockIdx.x * 8 + (threadIdx.x >> 5);
    int lane = threadIdx.x & 31;
    const int* mr = mask + (size_t)row * LL;
    int b_i = row >> 3, h = row & 7;
    int b = b_i >> 9, i = b_i & 511;
    unsigned* out = g_pm + (((size_t)(b*HEADS + h) * LL + i) << 4);
    #pragma unroll
    for (int wd = 0; wd < 16; wd++) {
        unsigned bits = __ballot_sync(0xffffffffu, mr[wd*32 + lane] != 0);
        if (lane == 0) out[wd] = bits;
    }
}

// ----------------------------- small FFMA GEMM (M=1) -----------------------
__global__ void gemm1_k(GP p) {
    int zo = blockIdx.z;
    const float* A = p.A + zo * p.aO;
    const float* B = p.B + zo * p.bO;
    float* C = p.C + zo * p.cO;
    const float* bias = p.bias ? p.bias + zo * p.biasO : nullptr;
    int n = blockIdx.x * 64 + threadIdx.x;
    if (n >= p.N) return;
    float s = 0.f;
    for (int k = 0; k < p.K; k++) s += A[k] * B[(size_t)k * p.ldb + n];
    if (bias) s += bias[n];
    C[n] = s;
}

// ----------------------------- small kernels -------------------------------
__global__ void k_embed(const float* __restrict__ emb, const float* __restrict__ pos,
                        const int* __restrict__ idxs) {
    int tok = blockIdx.x;
    int b = tok >> 9, s = tok & 511;
    int id = (s == 0) ? 0 : idxs[b*SS + s - 1];
    const float4* e  = (const float4*)(emb + (size_t)id * NHID);
    const float4* pr = (const float4*)(pos + (size_t)s  * NHID);
    float4* hr = (float4*)(g_h + (size_t)tok * NHID);
    uint2*  hh = (uint2*)(g_hh + (size_t)tok * NHID);
    int t = threadIdx.x;
    float4 a = e[t], c = pr[t];
    float4 v = make_float4(a.x+c.x, a.y+c.y, a.z+c.z, a.w+c.w);
    hr[t] = v;
    hh[t] = f4h(v);
}

__global__ void k_ln_add(float* __restrict__ out, const float* __restrict__ inp,
                         const float* __restrict__ base, int hgMap,
                         const float* __restrict__ gw, const float* __restrict__ bw,
                         __half* __restrict__ outH) {
    int n = blockIdx.x;
    const float* xr = inp + (size_t)n * NHID;
    size_t brow;
    if (hgMap) { int b = n / SS, s = n % SS; brow = ((size_t)(b*LL + s + 1)) * NHID; }
    else brow = (size_t)n * NHID;
    int t = threadIdx.x;
    float x[4];
    #pragma unroll
    for (int i = 0; i < 4; i++) x[i] = xr[t + i*128];
    __shared__ float red[128];
    red[t] = x[0]+x[1]+x[2]+x[3]; __syncthreads();
    for (int s = 64; s > 0; s >>= 1) { if (t < s) red[t] += red[t+s]; __syncthreads(); }
    float mu = red[0] * (1.f/512.f); __syncthreads();
    float d[4], vs = 0.f;
    #pragma unroll
    for (int i = 0; i < 4; i++) { d[i] = x[i] - mu; vs += d[i]*d[i]; }
    red[t] = vs; __syncthreads();
    for (int s = 64; s > 0; s >>= 1) { if (t < s) red[t] += red[t+s]; __syncthreads(); }
    float inv = rsqrtf(red[0] * (1.f/512.f) + 1e-5f);
    #pragma unroll
    for (int i = 0; i < 4; i++) {
        int c = t + i*128;
        float v = base[brow + c] + d[i]*inv*gw[c] + bw[c];
        out[(size_t)n*NHID + c] = v;
        if (outH) outH[(size_t)n*NHID + c] = __float2half_rn(v);
    }
}

__global__ void k_zg(float* __restrict__ dout) {
    int b = blockIdx.x; int t = threadIdx.x;
    #pragma unroll
    for (int i = 0; i < 4; i++) {
        int c = t + i*128;
        dout[(size_t)NNODE*NHID + b*NHID + c] = g_h[((size_t)b*LL) * NHID + c];
    }
}

// copy hg rows into fp16 xf
__global__ void k_copyxf() {
    int n = blockIdx.x;
    int b = n / SS, s = n % SS;
    const float4* src = (const float4*)(g_h + ((size_t)(b*LL + s + 1)) * NHID);
    uint2* dst = (uint2*)(g_xfh + (size_t)n * NHID);
    dst[threadIdx.x] = f4h(src[threadIdx.x]);
}

__global__ void k_zero_ints() {
    int i = blockIdx.x*blockDim.x + threadIdx.x;
    if (i < 2*NNODE) { g_ind[i] = 0; g_outd[i] = 0; g_cur[i] = 0; }
}

__global__ void k_count(const int* __restrict__ src, const int* __restrict__ dst, int gi) {
    int e = blockIdx.x*blockDim.x + threadIdx.x;
    if (e < EE) {
        atomicAdd(&g_ind [gi*NNODE + dst[e]], 1);
        atomicAdd(&g_outd[gi*NNODE + src[e]], 1);
    }
}

__global__ void k_scan(int gi) {
    __shared__ int sh[1024];
    int t = threadIdx.x;
    int base = gi * NNODE;
    int loc[8]; int sum = 0;
    #pragma unroll
    for (int i = 0; i < 8; i++) {
        int idx = t*8 + i;
        int v = (idx < NNODE) ? g_ind[base + idx] : 0;
        loc[i] = sum; sum += v;
    }
    sh[t] = sum; __syncthreads();
    for (int d = 1; d < 1024; d <<= 1) {
        int v = (t >= d) ? sh[t-d] : 0; __syncthreads();
        sh[t] += v; __syncthreads();
    }
    int pre = (t > 0) ? sh[t-1] : 0;
    #pragma unroll
    for (int i = 0; i < 8; i++) {
        int idx = t*8 + i;
        if (idx < NNODE) g_off[base + idx] = pre + loc[i];
    }
}

__global__ void k_scatter(const int* __restrict__ src, const int* __restrict__ dst, int gi) {
    int e = blockIdx.x*blockDim.x + threadIdx.x;
    if (e < EE) {
        int d = dst[e];
        int p = g_off[gi*NNODE + d] + atomicAdd(&g_cur[gi*NNODE + d], 1);
        g_csr[gi*EE + p] = src[e];
    }
}

__global__ void k_scales() {
    int i = blockIdx.x*blockDim.x + threadIdx.x;
    if (i < 2*NNODE) {
        float in = (float)g_ind[i], od = (float)g_outd[i];
        g_sin [i] = rsqrtf(fmaxf(in, 1.f));
        g_sout[i] = rsqrtf(fmaxf(od, 1.f));
        g_inv1[i] = 1.f / (in + 1.f);
    }
}

// fp16 SAGE propagation: out[gi][n] = (x[n] + sum_in x[src]) / (ind+1)
// gridDim.y = 2 (both graphs). xper = 0 (shared input) or NNODE*NHID.
__global__ void k_prop_sage(const __half* __restrict__ x, long long xper,
                            __half* __restrict__ out) {
    int gi = blockIdx.y;
    int wid = blockIdx.x * (blockDim.x >> 5) + (threadIdx.x >> 5);
    if (wid >= NNODE) return;
    int lane = threadIdx.x & 31;
    const __half* xb = x + (size_t)gi * xper;
    float a[16];
    #pragma unroll
    for (int i = 0; i < 16; i++) a[i] = 0.f;
    {
        const uint4* xr = (const uint4*)(xb + (size_t)wid * NHID);
        addh8(a, xr[lane], 1.f);
        addh8(a + 8, xr[lane + 32], 1.f);
    }
    int s = g_off[gi*NNODE + wid], e = s + g_ind[gi*NNODE + wid];
    const int* csr = g_csr + gi*EE;
    for (int j = s; j < e; j++) {
        const uint4* sr = (const uint4*)(xb + (size_t)csr[j] * NHID);
        addh8(a, sr[lane], 1.f);
        addh8(a + 8, sr[lane + 32], 1.f);
    }
    float sc = g_inv1[gi*NNODE + wid];
    uint4* o = (uint4*)(out + (size_t)gi * NNODE * NHID + (size_t)wid * NHID);
    o[lane]      = pack8(a, sc);
    o[lane + 32] = pack8(a + 8, sc);
}

// fp16 GC propagation: T[gi][n] = sum_in s_out[src]*Q[gi][src]; tvec = sum s_out
__global__ void k_prop_gc(const __half* __restrict__ q, __half* __restrict__ outT) {
    int gi = blockIdx.y;
    int wid = blockIdx.x * (blockDim.x >> 5) + (threadIdx.x >> 5);
    if (wid >= NNODE) return;
    int lane = threadIdx.x & 31;
    const __half* qb = q + (size_t)gi * NNODE * NHID;
    float a[16];
    #pragma unroll
    for (int i = 0; i < 16; i++) a[i] = 0.f;
    float ts = 0.f;
    int s = g_off[gi*NNODE + wid], e = s + g_ind[gi*NNODE + wid];
    const int* csr = g_csr + gi*EE;
    for (int j = s; j < e; j++) {
        int sn = csr[j];
        float so = g_sout[gi*NNODE + sn];
        ts += so;
        const uint4* sr = (const uint4*)(qb + (size_t)sn * NHID);
        addh8(a, sr[lane], so);
        addh8(a + 8, sr[lane + 32], so);
    }
    uint4* o = (uint4*)(outT + (size_t)gi * NNODE * NHID + (size_t)wid * NHID);
    o[lane]      = pack8(a, 1.f);
    o[lane + 32] = pack8(a + 8, 1.f);
    if (lane == 0) g_tvec[gi*NNODE + wid] = ts;
}

__global__ void k_xcepi(const float* __restrict__ gc3b) {
    int n = blockIdx.x; int c = threadIdx.x;
    int g = c_pat[c >> 6];
    float si = g_sin[g*NNODE + n], tv = g_tvec[g*NNODE + n];
    size_t idx = (size_t)n*NHID + c;
    g_xc[idx] = si * g_xc[idx] + si * tv * g_dcat[c] + gc3b[c];
}

// ----------------------------- host orchestration --------------------------
#define SYMF(name, var) { void* _p; cudaGetSymbolAddress(&_p, name); var = (float*)_p; }
#define SYMH(name, var) { void* _p; cudaGetSymbolAddress(&_p, name); var = (__half*)_p; }

extern "C" void kernel_launch(void* const* d_in, const int* in_sizes, int n_in,
                              void* d_out, int out_size) {
    const float* in_embed  = (const float*)d_in[0];
    const float* pos_embed = (const float*)d_in[1];
    const float* qkv_w     = (const float*)d_in[2];
    const float* qkv_b     = (const float*)d_in[3];
    const float* attn_w    = (const float*)d_in[4];
    const float* attn_b    = (const float*)d_in[5];
    const float* ff1_w     = (const float*)d_in[6];
    const float* ff1_b     = (const float*)d_in[7];
    const float* ff2_w     = (const float*)d_in[8];
    const float* ff2_b     = (const float*)d_in[9];
    const float* sage1_w   = (const float*)d_in[10];
    const float* sage1_b   = (const float*)d_in[11];
    const float* sage2_w   = (const float*)d_in[12];
    const float* sage2_b   = (const float*)d_in[13];
    const float* gc3_w     = (const float*)d_in[14];
    const float* gc3_b     = (const float*)d_in[15];
    const float* gff1_w    = (const float*)d_in[16];
    const float* gff1_b    = (const float*)d_in[17];
    const float* gff2_w    = (const float*)d_in[18];
    const float* gff2_b    = (const float*)d_in[19];
    const float* ln_g      = (const float*)d_in[20];
    const float* ln_b      = (const float*)d_in[21];
    const int*   in_idxs   = (const int*)d_in[22];
    const int*   mask      = (const int*)d_in[23];   // bool marshalled as int32
    const int*   gt_src    = (const int*)d_in[24];
    const int*   gt_dst    = (const int*)d_in[25];
    const int*   at_src    = (const int*)d_in[26];
    const int*   at_dst    = (const int*)d_in[27];

    float *h, *x, *xc, *xg, *cc, *dc;
    SYMF(g_h, h); SYMF(g_x, x); SYMF(g_xc, xc); SYMF(g_xg, xg);
    SYMF(g_ccat, cc); SYMF(g_dcat, dc);
    __half *hh, *qkvh, *oh, *xh, *ffh, *xfh, *Ph, *Qh, *Th, *Mh, *Nch, *xgh, *fgh;
    __half *qkvwh, *attnwh, *ff1wh, *ff2wh, *s1wh, *s2wh, *gc3wh, *gff1wh, *gff2wh;
    SYMH(g_hh, hh); SYMH(g_qkvh, qkvh); SYMH(g_oh, oh); SYMH(g_xh, xh); SYMH(g_ffh, ffh);
    SYMH(g_xfh, xfh); SYMH(g_Ph, Ph); SYMH(g_Qh, Qh); SYMH(g_Th, Th);
    SYMH(g_Mh, Mh); SYMH(g_Nch, Nch); SYMH(g_xgh, xgh); SYMH(g_fgh, fgh);
    SYMH(g_qkvwh, qkvwh); SYMH(g_attnwh, attnwh); SYMH(g_ff1wh, ff1wh);
    SYMH(g_ff2wh, ff2wh); SYMH(g_s1wh, s1wh); SYMH(g_s2wh, s2wh);
    SYMH(g_gc3wh, gc3wh); SYMH(g_gff1wh, gff1wh); SYMH(g_gff2wh, gff2wh);

    static int smemSet = 0;
    if (!smemSet) {
        cudaFuncSetAttribute(k_flash, cudaFuncAttributeMaxDynamicSharedMemorySize, FLASH_SMEM);
        cudaFuncSetAttribute(mma_k<128>, cudaFuncAttributeMaxDynamicSharedMemorySize, MMA_SMEM(128));
        cudaFuncSetAttribute(mma_k<64>,  cudaFuncAttributeMaxDynamicSharedMemorySize, MMA_SMEM(64));
        smemSet = 1;
    }

    // ---- weight f32 -> f16 (once per launch) ----
    #define TOH(src, dst, n) k_tohalf<<<((n)/8 + 255)/256, 256>>>(src, dst, n)
    TOH(qkv_w,  qkvwh,  4*NHID*QKVD);
    TOH(attn_w, attnwh, 4*NHID*NHID);
    TOH(ff1_w,  ff1wh,  4*NHID*FFD);
    TOH(ff2_w,  ff2wh,  4*FFD*NHID);
    TOH(sage1_w, s1wh,  HEADS*NHID*NHID);
    TOH(sage2_w, s2wh,  HEADS*NHID*NHID);
    TOH(gc3_w,  gc3wh,  HEADS*NHID*64);
    TOH(gff1_w, gff1wh, NHID*NHID);
    TOH(gff2_w, gff2wh, NHID*NHID);

    // ---- embedding + mask packing ----
    k_embed<<<NTOK, 128>>>(in_embed, pos_embed, in_idxs);
    k_packmask<<<BB*LL*HEADS/8, 256>>>(mask);

    // ---- transformer layers ----
    for (int l = 0; l < 4; l++) {
        mgemm(hh, NHID, qkvwh + (size_t)l*NHID*QKVD, QKVD, nullptr, qkvh, QKVD,
              NTOK, QKVD, NHID, qkv_b + l*QKVD);
        k_flash<<<dim3(LL/128, BB*HEADS), 256, FLASH_SMEM>>>();
        mgemm(oh, NHID, attnwh + (size_t)l*NHID*NHID, NHID, x, xh, NHID,
              NTOK, NHID, NHID, attn_b + l*NHID, h, NHID, 2.0f);
        mgemm(xh, NHID, ff1wh + (size_t)l*NHID*FFD, FFD, nullptr, ffh, FFD,
              NTOK, FFD, NHID, ff1_b + l*FFD, nullptr, 0, 0.f, /*relu=*/1);
        mgemm(ffh, FFD, ff2wh + (size_t)l*FFD*NHID, NHID, h, hh, NHID,
              NTOK, NHID, FFD, ff2_b + l*NHID, x, NHID, 1.0f);
    }

    // ---- graph preprocessing ----
    k_zero_ints<<<(2*NNODE + 255)/256, 256>>>();
    k_count<<<EE/256, 256>>>(gt_src, gt_dst, 0);
    k_count<<<EE/256, 256>>>(at_src, at_dst, 1);
    k_scan<<<1, 1024>>>(0);
    k_scan<<<1, 1024>>>(1);
    k_scatter<<<EE/256, 256>>>(gt_src, gt_dst, 0);
    k_scatter<<<EE/256, 256>>>(at_src, at_dst, 1);
    k_scales<<<(2*NNODE + 255)/256, 256>>>();
    k_copyxf<<<NNODE, 128>>>();

    // ---- propagations: both graphs per launch (blockIdx.y), fp16 data ----
    int propBlocks = (NNODE + 7) / 8;
    k_prop_sage<<<dim3(propBlocks, 2), 256>>>(xfh, 0, Ph);
    k_prop_sage<<<dim3(propBlocks, 2), 256>>>(Ph, (long long)NNODE*NHID, Qh);
    k_prop_gc  <<<dim3(propBlocks, 2), 256>>>(Qh, Th);

    // ---- collapse per-head weights ----
    mgemm(s1wh, NHID, s2wh, NHID, nullptr, Mh, NHID, NHID, NHID, NHID,
          nullptr, nullptr, 0, 0.f, 0, HEADS, 1,
          (long long)NHID*NHID, 0, (long long)NHID*NHID, 0, (long long)NHID*NHID, 0);
    mgemm(Mh, NHID, gc3wh, 64, nullptr, Nch, 64, NHID, 64, NHID,
          nullptr, nullptr, 0, 0.f, 0, HEADS, 1,
          (long long)NHID*NHID, 0, (long long)NHID*64, 0, (long long)NHID*64, 0);
    {
        GP p; p.A=sage1_b; p.B=sage2_w; p.bias=sage2_b; p.C=cc;
        p.ldb=NHID; p.N=NHID; p.K=NHID;
        p.aO=NHID; p.bO=(long long)NHID*NHID; p.cO=NHID; p.biasO=NHID;
        gemm1_k<<<dim3((NHID+63)/64,1,HEADS), 64>>>(p);
    }
    {
        GP p; p.A=cc; p.B=gc3_w; p.bias=nullptr; p.C=dc;
        p.ldb=64; p.N=64; p.K=NHID;
        p.aO=NHID; p.bO=(long long)NHID*64; p.cO=64; p.biasO=0;
        gemm1_k<<<dim3(1,1,HEADS), 64>>>(p);
    }

    // ---- xc per head: A = Th[(z>>1)&1] via hmode ----
    mgemm(Th, NHID, Nch, 64, xc, nullptr, NHID,
          NNODE, 64, NHID, nullptr, nullptr, 0, 0.f, 0,
          HEADS, 1,
          0, (long long)NNODE*NHID,
          (long long)NHID*64, 0,
          64, 0, 0, 0, 0, /*hmode=*/1);
    k_xcepi<<<NNODE, 512>>>(gc3_b);

    // ---- final: xg = hg + LN(xc); ff path; zbar = xg + LN(ff) ----
    k_ln_add<<<NNODE, 128>>>(xg, xc, h, /*hgMap=*/1, ln_g, ln_b, xgh);
    mgemm(xgh, NHID, gff1wh, NHID, nullptr, fgh, NHID,
          NNODE, NHID, NHID, gff1_b, nullptr, 0, 0.f, /*relu=*/1);
    mgemm(fgh, NHID, gff2wh, NHID, xc, nullptr, NHID,
          NNODE, NHID, NHID, gff2_b);
    k_ln_add<<<NNODE, 128>>>((float*)d_out, xc, xg, /*hgMap=*/0, ln_g, ln_b, nullptr);

    // ---- zg ----
    if (out_size >= NNODE*NHID + BB*NHID)
        k_zg<<<BB, 128>>>((float*)d_out);
}

// round 13
// speedup vs baseline: 1.8490x; 1.0119x over previous
#include <cuda_runtime.h>
#include <cuda_fp16.h>
#include <math.h>
#include <stdint.h>

#define NHID   512
#define HEADS  8
#define BB     16
#define SS     511
#define LL     512
#define NNODE  8176
#define NTOK   8192
#define EE     131072
#define QKVD   1536
#define FFD    2048

// ----------------------------- scratch (device globals) --------------------
__device__ float g_h   [NTOK*NHID];
__device__ float g_x   [NTOK*NHID];
__device__ float g_xc  [NNODE*NHID];
__device__ float g_xg  [NNODE*NHID];
__device__ float g_ccat[HEADS*NHID];
__device__ float g_dcat[HEADS*64];
__device__ float g_tvec[2*NNODE];
__device__ float g_sin [2*NNODE];
__device__ float g_sout[2*NNODE];
__device__ float g_inv1[2*NNODE];
__device__ int   g_ind [2*NNODE];
__device__ int   g_outd[2*NNODE];
__device__ int   g_off [2*NNODE];
__device__ int   g_cur [2*NNODE];
__device__ int   g_csr [2*EE];
__device__ unsigned g_pm[(size_t)BB*HEADS*LL*(LL/32)];

// fp16 activations / weights
__device__ __half g_hh  [NTOK*NHID];
__device__ __half g_qkvh[NTOK*QKVD];
__device__ __half g_oh  [NTOK*NHID];
__device__ __half g_xh  [NTOK*NHID];
__device__ __half g_ffh [NTOK*FFD];
__device__ __half g_xfh [NNODE*NHID];
__device__ __half g_Ph  [2*NNODE*NHID];
__device__ __half g_Qh  [2*NNODE*NHID];
__device__ __half g_Th  [2*NNODE*NHID];
__device__ __half g_Mh  [HEADS*NHID*NHID];
__device__ __half g_Nch [HEADS*NHID*64];
__device__ __half g_xgh [NNODE*NHID];
__device__ __half g_fgh [NNODE*NHID];
__device__ __half g_qkvwh [4*NHID*QKVD];
__device__ __half g_attnwh[4*NHID*NHID];
__device__ __half g_ff1wh [4*NHID*FFD];
__device__ __half g_ff2wh [4*FFD*NHID];
__device__ __half g_s1wh  [HEADS*NHID*NHID];
__device__ __half g_s2wh  [HEADS*NHID*NHID];
__device__ __half g_gc3wh [HEADS*NHID*64];
__device__ __half g_gff1wh[NHID*NHID];
__device__ __half g_gff2wh[NHID*NHID];

__constant__ int c_pat[8] = {0,0,1,1,0,0,1,1};

// ----------------------------- helpers -------------------------------------
__device__ __forceinline__ unsigned h2u(float a, float b) {
    __half2 h = __floats2half2_rn(a, b);
    return *reinterpret_cast<unsigned*>(&h);
}
__device__ __forceinline__ uint2 f4h(float4 v) {
    uint2 r; r.x = h2u(v.x, v.y); r.y = h2u(v.z, v.w); return r;
}
__device__ __forceinline__ void addh8(float* a, uint4 u, float s) {
    __half2* hp = (__half2*)&u;
    #pragma unroll
    for (int i = 0; i < 4; i++) {
        float2 f = __half22float2(hp[i]);
        a[2*i]   += f.x * s;
        a[2*i+1] += f.y * s;
    }
}
__device__ __forceinline__ uint4 pack8(const float* a, float s) {
    return make_uint4(h2u(a[0]*s, a[1]*s), h2u(a[2]*s, a[3]*s),
                      h2u(a[4]*s, a[5]*s), h2u(a[6]*s, a[7]*s));
}
__device__ __forceinline__ void ldsm4(unsigned &d0, unsigned &d1, unsigned &d2, unsigned &d3,
                                      unsigned addr) {
    asm volatile("ldmatrix.sync.aligned.m8n8.x4.shared.b16 {%0,%1,%2,%3}, [%4];"
                 : "=r"(d0), "=r"(d1), "=r"(d2), "=r"(d3) : "r"(addr));
}
__device__ __forceinline__ void ldsm4t(unsigned &d0, unsigned &d1, unsigned &d2, unsigned &d3,
                                       unsigned addr) {
    asm volatile("ldmatrix.sync.aligned.m8n8.x4.trans.shared.b16 {%0,%1,%2,%3}, [%4];"
                 : "=r"(d0), "=r"(d1), "=r"(d2), "=r"(d3) : "r"(addr));
}
__device__ __forceinline__ void ldsm2(unsigned &d0, unsigned &d1, unsigned addr) {
    asm volatile("ldmatrix.sync.aligned.m8n8.x2.shared.b16 {%0,%1}, [%2];"
                 : "=r"(d0), "=r"(d1) : "r"(addr));
}
__device__ __forceinline__ void ldsm2t(unsigned &d0, unsigned &d1, unsigned addr) {
    asm volatile("ldmatrix.sync.aligned.m8n8.x2.trans.shared.b16 {%0,%1}, [%2];"
                 : "=r"(d0), "=r"(d1) : "r"(addr));
}
__device__ __forceinline__ void mma16(float* c, const unsigned* a, const unsigned* b) {
    asm volatile(
        "mma.sync.aligned.m16n8k16.row.col.f32.f16.f16.f32 "
        "{%0,%1,%2,%3}, {%4,%5,%6,%7}, {%8,%9}, {%0,%1,%2,%3};"
        : "+f"(c[0]), "+f"(c[1]), "+f"(c[2]), "+f"(c[3])
        : "r"(a[0]), "r"(a[1]), "r"(a[2]), "r"(a[3]), "r"(b[0]), "r"(b[1]));
}
__device__ __forceinline__ void cpa16(unsigned d, const void* s, bool v) {
    asm volatile("cp.async.cg.shared.global [%0], [%1], 16, %2;"
                 :: "r"(d), "l"(s), "r"(v ? 16u : 0u));
}
#define CP_COMMIT asm volatile("cp.async.commit_group;" ::: "memory")
#define CP_WAIT1  asm volatile("cp.async.wait_group 1;" ::: "memory")
#define CP_WAIT0  asm volatile("cp.async.wait_group 0;" ::: "memory")

// ----------------------------- GEMM param block -----------------------------
struct GPH {
    const __half *A, *B;
    const float *bias, *res;
    float *C; __half *Ch;
    int lda, ldb, ldc, ldres;
    int M, N, K;
    float resScale;
    int relu;
    int zDiv, hmode;
    int gx, gy, tiles;
    long long aO, aI, bO, bI, cO, cI, rO, rI, biasO;
};
struct GP {
    const float *A, *B, *bias;
    float *C;
    int ldb, N, K;
    long long aO, bO, cO, biasO;
};

// ----------------------------- fp16 cp.async GEMM (persistent tiles) -------
// 256 thr, tile 128 x BN, 8 warps, K-slice 32 halves, 3 cp.async stages.
// Grid-strided over (gx, gy, z) tiles for minimal wave-quantization loss.
template<int BN>
__global__ __launch_bounds__(256, 2) void mma_k(GPH p) {
    constexpr int WGN  = (BN == 128) ? 4 : 2;
    constexpr int WGM  = 8 / WGN;
    constexpr int WM   = 128 / WGM;
    constexpr int WN   = BN / WGN;
    constexpr int MF   = WM / 16;
    constexpr int NF   = WN / 8;
    constexpr int ASTH = 56;
    constexpr int BSTH = BN + 8;
    constexpr int AW   = 128 * ASTH / 2;
    constexpr int BW   = 32 * BSTH / 2;

    extern __shared__ unsigned smw[];
    unsigned sb = (unsigned)__cvta_generic_to_shared(smw);
    unsigned aBase[3], bBase[3];
    #pragma unroll
    for (int s = 0; s < 3; s++) {
        aBase[s] = sb + (unsigned)(s * AW) * 4u;
        bBase[s] = sb + (unsigned)(3 * AW + s * BW) * 4u;
    }

    int tid = threadIdx.x, lane = tid & 31, warp = tid >> 5;
    int wm = warp / WGN, wn = warp % WGN;
    int ar0 = tid >> 2, ac = (tid & 3) * 8;
    int aRow = (lane & 7) + ((lane >> 3) & 1) * 8;
    unsigned aKoff = ((lane >> 4) & 1) * 16;
    int bRowT = (lane & 7) + ((lane >> 3) & 1) * 8;     // ldsm4t row component
    int bColT = ((lane >> 4) & 1) * 8;                  // ldsm4t col component

    for (int t = blockIdx.x; t < p.tiles; t += gridDim.x) {
        int bx = t % p.gx; int rr = t / p.gx;
        int by = rr % p.gy; int bz = rr / p.gy;

        __syncthreads();   // all warps done reading smem from previous tile

        const __half *A, *B;
        float *C = nullptr; __half *Ch = nullptr;
        const float *bias = nullptr, *res = nullptr;
        if (p.hmode) {
            A = p.A + (((bz >> 1) & 1) ? p.aI : 0);
            B = p.B + (size_t)bz * p.bO;
            if (p.C)  C  = p.C  + (size_t)bz * p.cO;
            if (p.Ch) Ch = p.Ch + (size_t)bz * p.cO;
        } else {
            int zo = bz / p.zDiv, zi = bz % p.zDiv;
            A = p.A + zo * p.aO + zi * p.aI;
            B = p.B + zo * p.bO + zi * p.bI;
            if (p.C)  C  = p.C  + zo * p.cO + zi * p.cI;
            if (p.Ch) Ch = p.Ch + zo * p.cO + zi * p.cI;
            if (p.bias) bias = p.bias + zo * p.biasO;
            if (p.res)  res  = p.res + zo * p.rO + zi * p.rI;
        }
        int m0 = bx * 128, n0 = by * BN;
        bool av0 = (m0 + ar0) < p.M, av1 = (m0 + ar0 + 64) < p.M;

        auto issue = [&](int s, int k0) {
            cpa16(aBase[s] + (unsigned)(ar0 * ASTH + ac) * 2u,
                  A + (size_t)(m0 + ar0) * p.lda + k0 + ac, av0);
            cpa16(aBase[s] + (unsigned)((ar0 + 64) * ASTH + ac) * 2u,
                  A + (size_t)(m0 + ar0 + 64) * p.lda + k0 + ac, av1);
            if (BN == 128) {
                int br = tid >> 4, bc = (tid & 15) * 8;
                cpa16(bBase[s] + (unsigned)(br * BSTH + bc) * 2u,
                      B + (size_t)(k0 + br) * p.ldb + n0 + bc, true);
                cpa16(bBase[s] + (unsigned)((br + 16) * BSTH + bc) * 2u,
                      B + (size_t)(k0 + br + 16) * p.ldb + n0 + bc, true);
            } else {
                int br = tid >> 3, bc = (tid & 7) * 8;
                cpa16(bBase[s] + (unsigned)(br * BSTH + bc) * 2u,
                      B + (size_t)(k0 + br) * p.ldb + n0 + bc, true);
            }
        };

        float acc[MF][NF][4];
        #pragma unroll
        for (int f = 0; f < MF; f++)
            #pragma unroll
            for (int j = 0; j < NF; j++)
                #pragma unroll
                for (int q = 0; q < 4; q++) acc[f][j][q] = 0.f;

        int nIter = p.K >> 5;
        issue(0, 0);  CP_COMMIT;
        issue(1, 32); CP_COMMIT;

        for (int i = 0; i < nIter; i++) {
            CP_WAIT1;
            __syncthreads();
            if (i + 2 < nIter) issue((i + 2) % 3, (i + 2) * 32);
            CP_COMMIT;

            int s = i % 3;
            unsigned aB = aBase[s], bB = bBase[s];
            #pragma unroll
            for (int kk = 0; kk < 32; kk += 16) {
                unsigned bfr[NF][2];
                #pragma unroll
                for (int j = 0; j < NF; j += 2) {
                    unsigned addr = bB + (unsigned)((kk + bRowT) * BSTH
                                  + wn * WN + j * 8 + bColT) * 2u;
                    ldsm4t(bfr[j][0], bfr[j][1], bfr[j+1][0], bfr[j+1][1], addr);
                }
                #pragma unroll
                for (int f = 0; f < MF; f++) {
                    int row = wm * WM + f * 16 + aRow;
                    unsigned addr = aB + (unsigned)(row * ASTH + kk) * 2u + aKoff;
                    unsigned afr[4];
                    ldsm4(afr[0], afr[1], afr[2], afr[3], addr);
                    #pragma unroll
                    for (int j = 0; j < NF; j++) mma16(acc[f][j], afr, bfr[j]);
                }
            }
        }

        #pragma unroll
        for (int f = 0; f < MF; f++) {
            int r0 = m0 + wm * WM + f * 16 + (lane >> 2);
            int r1 = r0 + 8;
            #pragma unroll
            for (int j = 0; j < NF; j++) {
                int col = n0 + wn * WN + j * 8 + 2 * (lane & 3);
                float b0 = 0.f, b1 = 0.f;
                if (bias) { b0 = bias[col]; b1 = bias[col + 1]; }
                float v0 = acc[f][j][0] + b0, v1 = acc[f][j][1] + b1;
                float v2 = acc[f][j][2] + b0, v3 = acc[f][j][3] + b1;
                if (p.relu) {
                    v0 = fmaxf(v0, 0.f); v1 = fmaxf(v1, 0.f);
                    v2 = fmaxf(v2, 0.f); v3 = fmaxf(v3, 0.f);
                }
                if (r0 < p.M) {
                    if (res) {
                        v0 += p.resScale * res[(size_t)r0 * p.ldres + col];
                        v1 += p.resScale * res[(size_t)r0 * p.ldres + col + 1];
                    }
                    if (C)  *(float2*)&C[(size_t)r0 * p.ldc + col] = make_float2(v0, v1);
                    if (Ch) *(unsigned*)&Ch[(size_t)r0 * p.ldc + col] = h2u(v0, v1);
                }
                if (r1 < p.M) {
                    if (res) {
                        v2 += p.resScale * res[(size_t)r1 * p.ldres + col];
                        v3 += p.resScale * res[(size_t)r1 * p.ldres + col + 1];
                    }
                    if (C)  *(float2*)&C[(size_t)r1 * p.ldc + col] = make_float2(v2, v3);
                    if (Ch) *(unsigned*)&Ch[(size_t)r1 * p.ldc + col] = h2u(v2, v3);
                }
            }
        }
    }
}

#define MMA_SMEM(BN) ((3 * (128*56/2) + 3 * (32*((BN)+8)/2)) * 4)
#define PERSIST_CTAS 296

static void mgemm(const __half* A, int lda, const __half* B, int ldb,
                  float* C, __half* Ch, int ldc,
                  int M, int N, int K,
                  const float* bias = nullptr, const float* res = nullptr, int ldres = 0,
                  float resScale = 0.f, int relu = 0,
                  int z = 1, int zDiv = 1,
                  long long aO=0, long long aI=0, long long bO=0, long long bI=0,
                  long long cO=0, long long cI=0, long long rO=0, long long rI=0,
                  long long biasO=0, int hmode = 0) {
    GPH p;
    p.A=A; p.B=B; p.bias=bias; p.res=res; p.C=C; p.Ch=Ch;
    p.lda=lda; p.ldb=ldb; p.ldc=ldc; p.ldres=ldres;
    p.M=M; p.N=N; p.K=K; p.resScale=resScale; p.relu=relu; p.zDiv=zDiv; p.hmode=hmode;
    p.aO=aO; p.aI=aI; p.bO=bO; p.bI=bI; p.cO=cO; p.cI=cI; p.rO=rO; p.rI=rI; p.biasO=biasO;
    p.gx = (M + 127) / 128;
    if (N % 128 == 0) {
        p.gy = N / 128;
        p.tiles = p.gx * p.gy * z;
        int ctas = p.tiles < PERSIST_CTAS ? p.tiles : PERSIST_CTAS;
        mma_k<128><<<ctas, 256, MMA_SMEM(128)>>>(p);
    } else {
        p.gy = N / 64;
        p.tiles = p.gx * p.gy * z;
        int ctas = p.tiles < PERSIST_CTAS ? p.tiles : PERSIST_CTAS;
        mma_k<64><<<ctas, 256, MMA_SMEM(64)>>>(p);
    }
}

// ----------------------------- weight f32->f16 -----------------------------
__global__ void k_tohalf(const float* __restrict__ in, __half* __restrict__ out, int n) {
    int i = (blockIdx.x * blockDim.x + threadIdx.x) * 8;
    if (i < n) {
        uint2 a = f4h(*(const float4*)(in + i));
        uint2 b = f4h(*(const float4*)(in + i + 4));
        *(uint4*)(out + i) = make_uint4(a.x, a.y, b.x, b.y);
    }
}

// ----------------------------- flash attention (fp16, cp.async) ------------
#define KSTW 36
#define FLASH_SMEM ((4*64*KSTW + 128*KSTW) * 4)

__global__ __launch_bounds__(256, 2) void k_flash() {
    extern __shared__ unsigned sm[];
    unsigned sb = (unsigned)__cvta_generic_to_shared(sm);
    unsigned kOff[2] = { sb, sb + 4608u*4u };
    unsigned vOff[2] = { sb + 2304u*4u, sb + 6912u*4u };
    unsigned* sP = sm + 9216;
    unsigned sPb = sb + 9216u*4u;

    int tid = threadIdx.x, lane = tid & 31, w = tid >> 5;
    int m0 = blockIdx.x * 128;
    int bh = blockIdx.y; int h = bh & 7, b = bh >> 3;
    const __half* qb = g_qkvh + (size_t)(b * LL) * QKVD + h * 192;

    int l15 = lane & 15;
    int aRow = (lane & 7) + ((lane >> 3) & 1) * 8;
    unsigned aKoff = ((lane >> 4) & 1) * 16;
    int arow = 16*w + aRow;

    int key = tid >> 2, kc4 = tid & 3;
    auto issue = [&](int st, int kt) {
        const __half* kp = qb + (size_t)(kt*64 + key) * QKVD + 64;
        unsigned kd = kOff[st] + (unsigned)key * 144u;
        cpa16(kd + kc4*16,      kp + kc4*8,       true);
        cpa16(kd + (kc4+4)*16,  kp + (kc4+4)*8,   true);
        unsigned vd = vOff[st] + (unsigned)key * 144u;
        cpa16(vd + kc4*16,      kp + 64 + kc4*8,  true);
        cpa16(vd + (kc4+4)*16,  kp + 64 + (kc4+4)*8, true);
    };

    issue(0, 0); CP_COMMIT;

    {
        int row = tid >> 1, dh = (tid & 1) * 32;
        const uint4* src = (const uint4*)(qb + (size_t)(m0 + row) * QKVD + dh);
        unsigned* dst = sP + row * KSTW + dh/2;
        #pragma unroll
        for (int c = 0; c < 4; c++) *(uint4*)(dst + c*4) = src[c];
    }
    __syncthreads();
    unsigned qf[4][4];
    #pragma unroll
    for (int kc = 0; kc < 4; kc++)
        ldsm4(qf[kc][0], qf[kc][1], qf[kc][2], qf[kc][3],
              sPb + (unsigned)(arow * KSTW) * 4u + (unsigned)kc * 32u + aKoff);

    float accO[8][4];
    #pragma unroll
    for (int j = 0; j < 8; j++)
        #pragma unroll
        for (int q = 0; q < 4; q++) accO[j][q] = 0.f;
    float m0r = -INFINITY, m1r = -INFINITY, l0r = 0.f, l1r = 0.f;

    const unsigned* pmr0 = g_pm + ((size_t)bh * LL + m0 + 16*w + (lane >> 2)) * 16;
    const unsigned* pmr1 = pmr0 + 8 * 16;

    for (int kt = 0; kt < 8; kt++) {
        CP_WAIT0;
        __syncthreads();
        if (kt + 1 < 8) { issue((kt + 1) & 1, kt + 1); CP_COMMIT; }
        int st = kt & 1;

        float S[8][4];
        #pragma unroll
        for (int nt = 0; nt < 8; nt++)
            #pragma unroll
            for (int q = 0; q < 4; q++) S[nt][q] = 0.f;
        #pragma unroll
        for (int kc = 0; kc < 4; kc++) {
            #pragma unroll
            for (int nt = 0; nt < 8; nt++) {
                unsigned bb[2];
                unsigned addr = kOff[st] + (unsigned)((nt*8 + (l15 & 7)) * KSTW) * 4u
                                        + (unsigned)kc * 32u + (unsigned)(l15 >> 3) * 16u;
                ldsm2(bb[0], bb[1], addr);
                mma16(S[nt], qf[kc], bb);
            }
        }

        uint2 mw0 = *(const uint2*)(pmr0 + kt*2);
        uint2 mw1 = *(const uint2*)(pmr1 + kt*2);
        unsigned q0[2] = {mw0.x, mw0.y};
        unsigned q1[2] = {mw1.x, mw1.y};
        float rm0 = -INFINITY, rm1 = -INFINITY;
        #pragma unroll
        for (int nt = 0; nt < 8; nt++) {
            int j0 = nt*8 + 2*(lane & 3), j1 = j0 + 1;
            S[nt][0] = ((q0[j0>>5] >> (j0&31)) & 1u) ? S[nt][0]*0.125f : -INFINITY;
            S[nt][1] = ((q0[j1>>5] >> (j1&31)) & 1u) ? S[nt][1]*0.125f : -INFINITY;
            S[nt][2] = ((q1[j0>>5] >> (j0&31)) & 1u) ? S[nt][2]*0.125f : -INFINITY;
            S[nt][3] = ((q1[j1>>5] >> (j1&31)) & 1u) ? S[nt][3]*0.125f : -INFINITY;
            rm0 = fmaxf(rm0, fmaxf(S[nt][0], S[nt][1]));
            rm1 = fmaxf(rm1, fmaxf(S[nt][2], S[nt][3]));
        }
        rm0 = fmaxf(rm0, __shfl_xor_sync(0xffffffffu, rm0, 1));
        rm0 = fmaxf(rm0, __shfl_xor_sync(0xffffffffu, rm0, 2));
        rm1 = fmaxf(rm1, __shfl_xor_sync(0xffffffffu, rm1, 1));
        rm1 = fmaxf(rm1, __shfl_xor_sync(0xffffffffu, rm1, 2));

        float mn0 = fmaxf(m0r, rm0), mn1 = fmaxf(m1r, rm1);
        float a0 = __expf(m0r - mn0), a1 = __expf(m1r - mn1);
        m0r = mn0; m1r = mn1;

        int prow0 = 16*w + (lane >> 2), prow1 = prow0 + 8;
        float rs0 = 0.f, rs1 = 0.f;
        #pragma unroll
        for (int nt = 0; nt < 8; nt++) {
            int jw = nt*4 + (lane & 3);
            float p00 = __expf(S[nt][0] - mn0), p01 = __expf(S[nt][1] - mn0);
            float p10 = __expf(S[nt][2] - mn1), p11 = __expf(S[nt][3] - mn1);
            rs0 += p00 + p01; rs1 += p10 + p11;
            sP[prow0*KSTW + jw] = h2u(p00, p01);
            sP[prow1*KSTW + jw] = h2u(p10, p11);
        }
        rs0 += __shfl_xor_sync(0xffffffffu, rs0, 1);
        rs0 += __shfl_xor_sync(0xffffffffu, rs0, 2);
        rs1 += __shfl_xor_sync(0xffffffffu, rs1, 1);
        rs1 += __shfl_xor_sync(0xffffffffu, rs1, 2);
        l0r = l0r * a0 + rs0;
        l1r = l1r * a1 + rs1;

        #pragma unroll
        for (int j = 0; j < 8; j++) {
            accO[j][0] *= a0; accO[j][1] *= a0;
            accO[j][2] *= a1; accO[j][3] *= a1;
        }
        __syncwarp();

        #pragma unroll
        for (int kc = 0; kc < 4; kc++) {
            unsigned pf[4];
            ldsm4(pf[0], pf[1], pf[2], pf[3],
                  sPb + (unsigned)(arow * KSTW) * 4u + (unsigned)kc * 32u + aKoff);
            #pragma unroll
            for (int nt = 0; nt < 8; nt++) {
                unsigned bb[2];
                unsigned addr = vOff[st] + (unsigned)((kc*16 + (l15 & 7) + (l15 >> 3)*8) * KSTW) * 4u
                                        + (unsigned)nt * 16u;
                ldsm2t(bb[0], bb[1], addr);
                mma16(accO[nt], pf, bb);
            }
        }
    }

    float inv0 = 1.f / l0r, inv1 = 1.f / l1r;
    int r0 = m0 + 16*w + (lane >> 2), r1 = r0 + 8;
    __half* o0 = g_oh + (size_t)(b*LL + r0) * NHID + h*64;
    __half* o1 = g_oh + (size_t)(b*LL + r1) * NHID + h*64;
    #pragma unroll
    for (int nt = 0; nt < 8; nt++) {
        int col = nt*8 + 2*(lane & 3);
        *(unsigned*)&o0[col] = h2u(accO[nt][0]*inv0, accO[nt][1]*inv0);
        *(unsigned*)&o1[col] = h2u(accO[nt][2]*inv1, accO[nt][3]*inv1);
    }
}

// pack mask (int32 bool, layout [b][i][h][j]) -> bits [b][h][i][j/32]
__global__ void k_packmask(const int* __restrict__ mask) {
    int row = blockIdx.x * 8 + (threadIdx.x >> 5);
    int lane = threadIdx.x & 31;
    const int* mr = mask + (size_t)row * LL;
    int b_i = row >> 3, h = row & 7;
    int b = b_i >> 9, i = b_i & 511;
    unsigned* out = g_pm + (((size_t)(b*HEADS + h) * LL + i) << 4);
    #pragma unroll
    for (int wd = 0; wd < 16; wd++) {
        unsigned bits = __ballot_sync(0xffffffffu, mr[wd*32 + lane] != 0);
        if (lane == 0) out[wd] = bits;
    }
}

// ----------------------------- small FFMA GEMM (M=1) -----------------------
__global__ void gemm1_k(GP p) {
    int zo = blockIdx.z;
    const float* A = p.A + zo * p.aO;
    const float* B = p.B + zo * p.bO;
    float* C = p.C + zo * p.cO;
    const float* bias = p.bias ? p.bias + zo * p.biasO : nullptr;
    int n = blockIdx.x * 64 + threadIdx.x;
    if (n >= p.N) return;
    float s = 0.f;
    for (int k = 0; k < p.K; k++) s += A[k] * B[(size_t)k * p.ldb + n];
    if (bias) s += bias[n];
    C[n] = s;
}

// ----------------------------- small kernels -------------------------------
__global__ void k_embed(const float* __restrict__ emb, const float* __restrict__ pos,
                        const int* __restrict__ idxs) {
    int tok = blockIdx.x;
    int b = tok >> 9, s = tok & 511;
    int id = (s == 0) ? 0 : idxs[b*SS + s - 1];
    const float4* e  = (const float4*)(emb + (size_t)id * NHID);
    const float4* pr = (const float4*)(pos + (size_t)s  * NHID);
    float4* hr = (float4*)(g_h + (size_t)tok * NHID);
    uint2*  hh = (uint2*)(g_hh + (size_t)tok * NHID);
    int t = threadIdx.x;
    float4 a = e[t], c = pr[t];
    float4 v = make_float4(a.x+c.x, a.y+c.y, a.z+c.z, a.w+c.w);
    hr[t] = v;
    hh[t] = f4h(v);
}

__global__ void k_ln_add(float* __restrict__ out, const float* __restrict__ inp,
                         const float* __restrict__ base, int hgMap,
                         const float* __restrict__ gw, const float* __restrict__ bw,
                         __half* __restrict__ outH) {
    int n = blockIdx.x;
    const float* xr = inp + (size_t)n * NHID;
    size_t brow;
    if (hgMap) { int b = n / SS, s = n % SS; brow = ((size_t)(b*LL + s + 1)) * NHID; }
    else brow = (size_t)n * NHID;
    int t = threadIdx.x;
    float x[4];
    #pragma unroll
    for (int i = 0; i < 4; i++) x[i] = xr[t + i*128];
    __shared__ float red[128];
    red[t] = x[0]+x[1]+x[2]+x[3]; __syncthreads();
    for (int s = 64; s > 0; s >>= 1) { if (t < s) red[t] += red[t+s]; __syncthreads(); }
    float mu = red[0] * (1.f/512.f); __syncthreads();
    float d[4], vs = 0.f;
    #pragma unroll
    for (int i = 0; i < 4; i++) { d[i] = x[i] - mu; vs += d[i]*d[i]; }
    red[t] = vs; __syncthreads();
    for (int s = 64; s > 0; s >>= 1) { if (t < s) red[t] += red[t+s]; __syncthreads(); }
    float inv = rsqrtf(red[0] * (1.f/512.f) + 1e-5f);
    #pragma unroll
    for (int i = 0; i < 4; i++) {
        int c = t + i*128;
        float v = base[brow + c] + d[i]*inv*gw[c] + bw[c];
        out[(size_t)n*NHID + c] = v;
        if (outH) outH[(size_t)n*NHID + c] = __float2half_rn(v);
    }
}

__global__ void k_zg(float* __restrict__ dout) {
    int b = blockIdx.x; int t = threadIdx.x;
    #pragma unroll
    for (int i = 0; i < 4; i++) {
        int c = t + i*128;
        dout[(size_t)NNODE*NHID + b*NHID + c] = g_h[((size_t)b*LL) * NHID + c];
    }
}

// copy hg rows into fp16 xf
__global__ void k_copyxf() {
    int n = blockIdx.x;
    int b = n / SS, s = n % SS;
    const float4* src = (const float4*)(g_h + ((size_t)(b*LL + s + 1)) * NHID);
    uint2* dst = (uint2*)(g_xfh + (size_t)n * NHID);
    dst[threadIdx.x] = f4h(src[threadIdx.x]);
}

__global__ void k_zero_ints() {
    int i = blockIdx.x*blockDim.x + threadIdx.x;
    if (i < 2*NNODE) { g_ind[i] = 0; g_outd[i] = 0; g_cur[i] = 0; }
}

__global__ void k_count(const int* __restrict__ src, const int* __restrict__ dst, int gi) {
    int e = blockIdx.x*blockDim.x + threadIdx.x;
    if (e < EE) {
        atomicAdd(&g_ind [gi*NNODE + dst[e]], 1);
        atomicAdd(&g_outd[gi*NNODE + src[e]], 1);
    }
}

__global__ void k_scan(int gi) {
    __shared__ int sh[1024];
    int t = threadIdx.x;
    int base = gi * NNODE;
    int loc[8]; int sum = 0;
    #pragma unroll
    for (int i = 0; i < 8; i++) {
        int idx = t*8 + i;
        int v = (idx < NNODE) ? g_ind[base + idx] : 0;
        loc[i] = sum; sum += v;
    }
    sh[t] = sum; __syncthreads();
    for (int d = 1; d < 1024; d <<= 1) {
        int v = (t >= d) ? sh[t-d] : 0; __syncthreads();
        sh[t] += v; __syncthreads();
    }
    int pre = (t > 0) ? sh[t-1] : 0;
    #pragma unroll
    for (int i = 0; i < 8; i++) {
        int idx = t*8 + i;
        if (idx < NNODE) g_off[base + idx] = pre + loc[i];
    }
}

__global__ void k_scatter(const int* __restrict__ src, const int* __restrict__ dst, int gi) {
    int e = blockIdx.x*blockDim.x + threadIdx.x;
    if (e < EE) {
        int d = dst[e];
        int p = g_off[gi*NNODE + d] + atomicAdd(&g_cur[gi*NNODE + d], 1);
        g_csr[gi*EE + p] = src[e];
    }
}

__global__ void k_scales() {
    int i = blockIdx.x*blockDim.x + threadIdx.x;
    if (i < 2*NNODE) {
        float in = (float)g_ind[i], od = (float)g_outd[i];
        g_sin [i] = rsqrtf(fmaxf(in, 1.f));
        g_sout[i] = rsqrtf(fmaxf(od, 1.f));
        g_inv1[i] = 1.f / (in + 1.f);
    }
}

// fp16 SAGE propagation: out[gi][n] = (x[n] + sum_in x[src]) / (ind+1)
__global__ void k_prop_sage(const __half* __restrict__ x, long long xper,
                            __half* __restrict__ out) {
    int gi = blockIdx.y;
    int wid = blockIdx.x * (blockDim.x >> 5) + (threadIdx.x >> 5);
    if (wid >= NNODE) return;
    int lane = threadIdx.x & 31;
    const __half* xb = x + (size_t)gi * xper;
    float a[16];
    #pragma unroll
    for (int i = 0; i < 16; i++) a[i] = 0.f;
    {
        const uint4* xr = (const uint4*)(xb + (size_t)wid * NHID);
        addh8(a, xr[lane], 1.f);
        addh8(a + 8, xr[lane + 32], 1.f);
    }
    int s = g_off[gi*NNODE + wid], e = s + g_ind[gi*NNODE + wid];
    const int* csr = g_csr + gi*EE;
    for (int j = s; j < e; j++) {
        const uint4* sr = (const uint4*)(xb + (size_t)csr[j] * NHID);
        addh8(a, sr[lane], 1.f);
        addh8(a + 8, sr[lane + 32], 1.f);
    }
    float sc = g_inv1[gi*NNODE + wid];
    uint4* o = (uint4*)(out + (size_t)gi * NNODE * NHID + (size_t)wid * NHID);
    o[lane]      = pack8(a, sc);
    o[lane + 32] = pack8(a + 8, sc);
}

// fp16 GC propagation: T[gi][n] = sum_in s_out[src]*Q[gi][src]; tvec = sum s_out
__global__ void k_prop_gc(const __half* __restrict__ q, __half* __restrict__ outT) {
    int gi = blockIdx.y;
    int wid = blockIdx.x * (blockDim.x >> 5) + (threadIdx.x >> 5);
    if (wid >= NNODE) return;
    int lane = threadIdx.x & 31;
    const __half* qb = q + (size_t)gi * NNODE * NHID;
    float a[16];
    #pragma unroll
    for (int i = 0; i < 16; i++) a[i] = 0.f;
    float ts = 0.f;
    int s = g_off[gi*NNODE + wid], e = s + g_ind[gi*NNODE + wid];
    const int* csr = g_csr + gi*EE;
    for (int j = s; j < e; j++) {
        int sn = csr[j];
        float so = g_sout[gi*NNODE + sn];
        ts += so;
        const uint4* sr = (const uint4*)(qb + (size_t)sn * NHID);
        addh8(a, sr[lane], so);
        addh8(a + 8, sr[lane + 32], so);
    }
    uint4* o = (uint4*)(outT + (size_t)gi * NNODE * NHID + (size_t)wid * NHID);
    o[lane]      = pack8(a, 1.f);
    o[lane + 32] = pack8(a + 8, 1.f);
    if (lane == 0) g_tvec[gi*NNODE + wid] = ts;
}

__global__ void k_xcepi(const float* __restrict__ gc3b) {
    int n = blockIdx.x; int c = threadIdx.x;
    int g = c_pat[c >> 6];
    float si = g_sin[g*NNODE + n], tv = g_tvec[g*NNODE + n];
    size_t idx = (size_t)n*NHID + c;
    g_xc[idx] = si * g_xc[idx] + si * tv * g_dcat[c] + gc3b[c];
}

// ----------------------------- host orchestration --------------------------
#define SYMF(name, var) { void* _p; cudaGetSymbolAddress(&_p, name); var = (float*)_p; }
#define SYMH(name, var) { void* _p; cudaGetSymbolAddress(&_p, name); var = (__half*)_p; }

extern "C" void kernel_launch(void* const* d_in, const int* in_sizes, int n_in,
                              void* d_out, int out_size) {
    const float* in_embed  = (const float*)d_in[0];
    const float* pos_embed = (const float*)d_in[1];
    const float* qkv_w     = (const float*)d_in[2];
    const float* qkv_b     = (const float*)d_in[3];
    const float* attn_w    = (const float*)d_in[4];
    const float* attn_b    = (const float*)d_in[5];
    const float* ff1_w     = (const float*)d_in[6];
    const float* ff1_b     = (const float*)d_in[7];
    const float* ff2_w     = (const float*)d_in[8];
    const float* ff2_b     = (const float*)d_in[9];
    const float* sage1_w   = (const float*)d_in[10];
    const float* sage1_b   = (const float*)d_in[11];
    const float* sage2_w   = (const float*)d_in[12];
    const float* sage2_b   = (const float*)d_in[13];
    const float* gc3_w     = (const float*)d_in[14];
    const float* gc3_b     = (const float*)d_in[15];
    const float* gff1_w    = (const float*)d_in[16];
    const float* gff1_b    = (const float*)d_in[17];
    const float* gff2_w    = (const float*)d_in[18];
    const float* gff2_b    = (const float*)d_in[19];
    const float* ln_g      = (const float*)d_in[20];
    const float* ln_b      = (const float*)d_in[21];
    const int*   in_idxs   = (const int*)d_in[22];
    const int*   mask      = (const int*)d_in[23];   // bool marshalled as int32
    const int*   gt_src    = (const int*)d_in[24];
    const int*   gt_dst    = (const int*)d_in[25];
    const int*   at_src    = (const int*)d_in[26];
    const int*   at_dst    = (const int*)d_in[27];

    float *h, *x, *xc, *xg, *cc, *dc;
    SYMF(g_h, h); SYMF(g_x, x); SYMF(g_xc, xc); SYMF(g_xg, xg);
    SYMF(g_ccat, cc); SYMF(g_dcat, dc);
    __half *hh, *qkvh, *oh, *xh, *ffh, *xfh, *Ph, *Qh, *Th, *Mh, *Nch, *xgh, *fgh;
    __half *qkvwh, *attnwh, *ff1wh, *ff2wh, *s1wh, *s2wh, *gc3wh, *gff1wh, *gff2wh;
    SYMH(g_hh, hh); SYMH(g_qkvh, qkvh); SYMH(g_oh, oh); SYMH(g_xh, xh); SYMH(g_ffh, ffh);
    SYMH(g_xfh, xfh); SYMH(g_Ph, Ph); SYMH(g_Qh, Qh); SYMH(g_Th, Th);
    SYMH(g_Mh, Mh); SYMH(g_Nch, Nch); SYMH(g_xgh, xgh); SYMH(g_fgh, fgh);
    SYMH(g_qkvwh, qkvwh); SYMH(g_attnwh, attnwh); SYMH(g_ff1wh, ff1wh);
    SYMH(g_ff2wh, ff2wh); SYMH(g_s1wh, s1wh); SYMH(g_s2wh, s2wh);
    SYMH(g_gc3wh, gc3wh); SYMH(g_gff1wh, gff1wh); SYMH(g_gff2wh, gff2wh);

    static int smemSet = 0;
    if (!smemSet) {
        cudaFuncSetAttribute(k_flash, cudaFuncAttributeMaxDynamicSharedMemorySize, FLASH_SMEM);
        cudaFuncSetAttribute(mma_k<128>, cudaFuncAttributeMaxDynamicSharedMemorySize, MMA_SMEM(128));
        cudaFuncSetAttribute(mma_k<64>,  cudaFuncAttributeMaxDynamicSharedMemorySize, MMA_SMEM(64));
        smemSet = 1;
    }

    // ---- weight f32 -> f16 (once per launch) ----
    #define TOH(src, dst, n) k_tohalf<<<((n)/8 + 255)/256, 256>>>(src, dst, n)
    TOH(qkv_w,  qkvwh,  4*NHID*QKVD);
    TOH(attn_w, attnwh, 4*NHID*NHID);
    TOH(ff1_w,  ff1wh,  4*NHID*FFD);
    TOH(ff2_w,  ff2wh,  4*FFD*NHID);
    TOH(sage1_w, s1wh,  HEADS*NHID*NHID);
    TOH(sage2_w, s2wh,  HEADS*NHID*NHID);
    TOH(gc3_w,  gc3wh,  HEADS*NHID*64);
    TOH(gff1_w, gff1wh, NHID*NHID);
    TOH(gff2_w, gff2wh, NHID*NHID);

    // ---- embedding + mask packing ----
    k_embed<<<NTOK, 128>>>(in_embed, pos_embed, in_idxs);
    k_packmask<<<BB*LL*HEADS/8, 256>>>(mask);

    // ---- transformer layers ----
    for (int l = 0; l < 4; l++) {
        mgemm(hh, NHID, qkvwh + (size_t)l*NHID*QKVD, QKVD, nullptr, qkvh, QKVD,
              NTOK, QKVD, NHID, qkv_b + l*QKVD);
        k_flash<<<dim3(LL/128, BB*HEADS), 256, FLASH_SMEM>>>();
        mgemm(oh, NHID, attnwh + (size_t)l*NHID*NHID, NHID, x, xh, NHID,
              NTOK, NHID, NHID, attn_b + l*NHID, h, NHID, 2.0f);
        mgemm(xh, NHID, ff1wh + (size_t)l*NHID*FFD, FFD, nullptr, ffh, FFD,
              NTOK, FFD, NHID, ff1_b + l*FFD, nullptr, 0, 0.f, /*relu=*/1);
        mgemm(ffh, FFD, ff2wh + (size_t)l*FFD*NHID, NHID, h, hh, NHID,
              NTOK, NHID, FFD, ff2_b + l*NHID, x, NHID, 1.0f);
    }

    // ---- graph preprocessing ----
    k_zero_ints<<<(2*NNODE + 255)/256, 256>>>();
    k_count<<<EE/256, 256>>>(gt_src, gt_dst, 0);
    k_count<<<EE/256, 256>>>(at_src, at_dst, 1);
    k_scan<<<1, 1024>>>(0);
    k_scan<<<1, 1024>>>(1);
    k_scatter<<<EE/256, 256>>>(gt_src, gt_dst, 0);
    k_scatter<<<EE/256, 256>>>(at_src, at_dst, 1);
    k_scales<<<(2*NNODE + 255)/256, 256>>>();
    k_copyxf<<<NNODE, 128>>>();

    // ---- propagations: both graphs per launch, fp16 data ----
    int propBlocks = (NNODE + 7) / 8;
    k_prop_sage<<<dim3(propBlocks, 2), 256>>>(xfh, 0, Ph);
    k_prop_sage<<<dim3(propBlocks, 2), 256>>>(Ph, (long long)NNODE*NHID, Qh);
    k_prop_gc  <<<dim3(propBlocks, 2), 256>>>(Qh, Th);

    // ---- collapse per-head weights ----
    mgemm(s1wh, NHID, s2wh, NHID, nullptr, Mh, NHID, NHID, NHID, NHID,
          nullptr, nullptr, 0, 0.f, 0, HEADS, 1,
          (long long)NHID*NHID, 0, (long long)NHID*NHID, 0, (long long)NHID*NHID, 0);
    mgemm(Mh, NHID, gc3wh, 64, nullptr, Nch, 64, NHID, 64, NHID,
          nullptr, nullptr, 0, 0.f, 0, HEADS, 1,
          (long long)NHID*NHID, 0, (long long)NHID*64, 0, (long long)NHID*64, 0);
    {
        GP p; p.A=sage1_b; p.B=sage2_w; p.bias=sage2_b; p.C=cc;
        p.ldb=NHID; p.N=NHID; p.K=NHID;
        p.aO=NHID; p.bO=(long long)NHID*NHID; p.cO=NHID; p.biasO=NHID;
        gemm1_k<<<dim3((NHID+63)/64,1,HEADS), 64>>>(p);
    }
    {
        GP p; p.A=cc; p.B=gc3_w; p.bias=nullptr; p.C=dc;
        p.ldb=64; p.N=64; p.K=NHID;
        p.aO=NHID; p.bO=(long long)NHID*64; p.cO=64; p.biasO=0;
        gemm1_k<<<dim3(1,1,HEADS), 64>>>(p);
    }

    // ---- xc per head: A = Th[(z>>1)&1] via hmode ----
    mgemm(Th, NHID, Nch, 64, xc, nullptr, NHID,
          NNODE, 64, NHID, nullptr, nullptr, 0, 0.f, 0,
          HEADS, 1,
          0, (long long)NNODE*NHID,
          (long long)NHID*64, 0,
          64, 0, 0, 0, 0, /*hmode=*/1);
    k_xcepi<<<NNODE, 512>>>(gc3_b);

    // ---- final: xg = hg + LN(xc); ff path; zbar = xg + LN(ff) ----
    k_ln_add<<<NNODE, 128>>>(xg, xc, h, /*hgMap=*/1, ln_g, ln_b, xgh);
    mgemm(xgh, NHID, gff1wh, NHID, nullptr, fgh, NHID,
          NNODE, NHID, NHID, gff1_b, nullptr, 0, 0.f, /*relu=*/1);
    mgemm(fgh, NHID, gff2wh, NHID, xc, nullptr, NHID,
          NNODE, NHID, NHID, gff2_b);
    k_ln_add<<<NNODE, 128>>>((float*)d_out, xc, xg, /*hgMap=*/0, ln_g, ln_b, nullptr);

    // ---- zg ----
    if (out_size >= NNODE*NHID + BB*NHID)
        k_zg<<<BB, 128>>>((float*)d_out);
}

// round 14
// speedup vs baseline: 1.9462x; 1.0526x over previous
#include <cuda_runtime.h>
#include <cuda_fp16.h>
#include <math.h>
#include <stdint.h>

#define NHID   512
#define HEADS  8
#define BB     16
#define SS     511
#define LL     512
#define NNODE  8176
#define NTOK   8192
#define EE     131072
#define QKVD   1536
#define FFD    2048

// ----------------------------- scratch (device globals) --------------------
__device__ float g_h   [NTOK*NHID];
__device__ float g_x   [NTOK*NHID];
__device__ float g_xc  [NNODE*NHID];
__device__ float g_xg  [NNODE*NHID];
__device__ float g_ccat[HEADS*NHID];
__device__ float g_dcat[HEADS*64];
__device__ float g_tvec[2*NNODE];
__device__ float g_sin [2*NNODE];
__device__ float g_sout[2*NNODE];
__device__ float g_inv1[2*NNODE];
__device__ int   g_ind [2*NNODE];
__device__ int   g_outd[2*NNODE];
__device__ int   g_off [2*NNODE];
__device__ int   g_cur [2*NNODE];
__device__ int   g_csr [2*EE];
__device__ unsigned g_pm[(size_t)BB*HEADS*LL*(LL/32)];

// fp16 activations / weights
__device__ __half g_hh  [NTOK*NHID];
__device__ __half g_qkvh[NTOK*QKVD];
__device__ __half g_oh  [NTOK*NHID];
__device__ __half g_xh  [NTOK*NHID];
__device__ __half g_ffh [NTOK*FFD];
__device__ __half g_xfh [NNODE*NHID];
__device__ __half g_Ph  [2*NNODE*NHID];
__device__ __half g_Qh  [2*NNODE*NHID];
__device__ __half g_Th  [2*NNODE*NHID];
__device__ __half g_Mh  [HEADS*NHID*NHID];
__device__ __half g_Nch [HEADS*NHID*64];
__device__ __half g_xgh [NNODE*NHID];
__device__ __half g_fgh [NNODE*NHID];
__device__ __half g_qkvwh [4*NHID*QKVD];
__device__ __half g_attnwh[4*NHID*NHID];
__device__ __half g_ff1wh [4*NHID*FFD];
__device__ __half g_ff2wh [4*FFD*NHID];
__device__ __half g_s1wh  [HEADS*NHID*NHID];
__device__ __half g_s2wh  [HEADS*NHID*NHID];
__device__ __half g_gc3wh [HEADS*NHID*64];
__device__ __half g_gff1wh[NHID*NHID];
__device__ __half g_gff2wh[NHID*NHID];

__constant__ int c_pat[8] = {0,0,1,1,0,0,1,1};

// ----------------------------- helpers -------------------------------------
__device__ __forceinline__ unsigned h2u(float a, float b) {
    __half2 h = __floats2half2_rn(a, b);
    return *reinterpret_cast<unsigned*>(&h);
}
__device__ __forceinline__ uint2 f4h(float4 v) {
    uint2 r; r.x = h2u(v.x, v.y); r.y = h2u(v.z, v.w); return r;
}
__device__ __forceinline__ void addh8(float* a, uint4 u, float s) {
    __half2* hp = (__half2*)&u;
    #pragma unroll
    for (int i = 0; i < 4; i++) {
        float2 f = __half22float2(hp[i]);
        a[2*i]   += f.x * s;
        a[2*i+1] += f.y * s;
    }
}
__device__ __forceinline__ uint4 pack8(const float* a, float s) {
    return make_uint4(h2u(a[0]*s, a[1]*s), h2u(a[2]*s, a[3]*s),
                      h2u(a[4]*s, a[5]*s), h2u(a[6]*s, a[7]*s));
}
__device__ __forceinline__ void ldsm4(unsigned &d0, unsigned &d1, unsigned &d2, unsigned &d3,
                                      unsigned addr) {
    asm volatile("ldmatrix.sync.aligned.m8n8.x4.shared.b16 {%0,%1,%2,%3}, [%4];"
                 : "=r"(d0), "=r"(d1), "=r"(d2), "=r"(d3) : "r"(addr));
}
__device__ __forceinline__ void ldsm4t(unsigned &d0, unsigned &d1, unsigned &d2, unsigned &d3,
                                       unsigned addr) {
    asm volatile("ldmatrix.sync.aligned.m8n8.x4.trans.shared.b16 {%0,%1,%2,%3}, [%4];"
                 : "=r"(d0), "=r"(d1), "=r"(d2), "=r"(d3) : "r"(addr));
}
__device__ __forceinline__ void ldsm2(unsigned &d0, unsigned &d1, unsigned addr) {
    asm volatile("ldmatrix.sync.aligned.m8n8.x2.shared.b16 {%0,%1}, [%2];"
                 : "=r"(d0), "=r"(d1) : "r"(addr));
}
__device__ __forceinline__ void ldsm2t(unsigned &d0, unsigned &d1, unsigned addr) {
    asm volatile("ldmatrix.sync.aligned.m8n8.x2.trans.shared.b16 {%0,%1}, [%2];"
                 : "=r"(d0), "=r"(d1) : "r"(addr));
}
__device__ __forceinline__ void mma16(float* c, const unsigned* a, const unsigned* b) {
    asm volatile(
        "mma.sync.aligned.m16n8k16.row.col.f32.f16.f16.f32 "
        "{%0,%1,%2,%3}, {%4,%5,%6,%7}, {%8,%9}, {%0,%1,%2,%3};"
        : "+f"(c[0]), "+f"(c[1]), "+f"(c[2]), "+f"(c[3])
        : "r"(a[0]), "r"(a[1]), "r"(a[2]), "r"(a[3]), "r"(b[0]), "r"(b[1]));
}
__device__ __forceinline__ void cpa16(unsigned d, const void* s, bool v) {
    asm volatile("cp.async.cg.shared.global [%0], [%1], 16, %2;"
                 :: "r"(d), "l"(s), "r"(v ? 16u : 0u));
}
#define CP_COMMIT asm volatile("cp.async.commit_group;" ::: "memory")
#define CP_WAIT2  asm volatile("cp.async.wait_group 2;" ::: "memory")
#define CP_WAIT0  asm volatile("cp.async.wait_group 0;" ::: "memory")

// ----------------------------- GEMM param block -----------------------------
struct GPH {
    const __half *A, *B;
    const float *bias, *res;
    float *C; __half *Ch;
    int lda, ldb, ldc, ldres;
    int M, N, K;
    float resScale;
    int relu;
    int zDiv, hmode;
    int gx, gy, tiles;
    long long aO, aI, bO, bI, cO, cI, rO, rI, biasO;
};
struct GP {
    const float *A, *B, *bias;
    float *C;
    int ldb, N, K;
    long long aO, bO, cO, biasO;
};

// ----------------------------- fp16 cp.async GEMM (persistent, 4-stage) ----
template<int BN>
__global__ __launch_bounds__(256, 2) void mma_k(GPH p) {
    constexpr int WGN  = (BN == 128) ? 4 : 2;
    constexpr int WGM  = 8 / WGN;
    constexpr int WM   = 128 / WGM;
    constexpr int WN   = BN / WGN;
    constexpr int MF   = WM / 16;
    constexpr int NF   = WN / 8;
    constexpr int ASTH = 56;
    constexpr int BSTH = BN + 8;
    constexpr int AW   = 128 * ASTH / 2;
    constexpr int BW   = 32 * BSTH / 2;

    extern __shared__ unsigned smw[];
    unsigned sb = (unsigned)__cvta_generic_to_shared(smw);
    unsigned aBase[4], bBase[4];
    #pragma unroll
    for (int s = 0; s < 4; s++) {
        aBase[s] = sb + (unsigned)(s * AW) * 4u;
        bBase[s] = sb + (unsigned)(4 * AW + s * BW) * 4u;
    }

    int tid = threadIdx.x, lane = tid & 31, warp = tid >> 5;
    int wm = warp / WGN, wn = warp % WGN;
    int ar0 = tid >> 2, ac = (tid & 3) * 8;
    int aRow = (lane & 7) + ((lane >> 3) & 1) * 8;
    unsigned aKoff = ((lane >> 4) & 1) * 16;
    int bRowT = (lane & 7) + ((lane >> 3) & 1) * 8;
    int bColT = ((lane >> 4) & 1) * 8;

    for (int t = blockIdx.x; t < p.tiles; t += gridDim.x) {
        int bx = t % p.gx; int rr = t / p.gx;
        int by = rr % p.gy; int bz = rr / p.gy;

        __syncthreads();

        const __half *A, *B;
        float *C = nullptr; __half *Ch = nullptr;
        const float *bias = nullptr, *res = nullptr;
        if (p.hmode) {
            A = p.A + (((bz >> 1) & 1) ? p.aI : 0);
            B = p.B + (size_t)bz * p.bO;
            if (p.C)  C  = p.C  + (size_t)bz * p.cO;
            if (p.Ch) Ch = p.Ch + (size_t)bz * p.cO;
        } else {
            int zo = bz / p.zDiv, zi = bz % p.zDiv;
            A = p.A + zo * p.aO + zi * p.aI;
            B = p.B + zo * p.bO + zi * p.bI;
            if (p.C)  C  = p.C  + zo * p.cO + zi * p.cI;
            if (p.Ch) Ch = p.Ch + zo * p.cO + zi * p.cI;
            if (p.bias) bias = p.bias + zo * p.biasO;
            if (p.res)  res  = p.res + zo * p.rO + zi * p.rI;
        }
        int m0 = bx * 128, n0 = by * BN;
        bool av0 = (m0 + ar0) < p.M, av1 = (m0 + ar0 + 64) < p.M;

        auto issue = [&](int s, int k0) {
            cpa16(aBase[s] + (unsigned)(ar0 * ASTH + ac) * 2u,
                  A + (size_t)(m0 + ar0) * p.lda + k0 + ac, av0);
            cpa16(aBase[s] + (unsigned)((ar0 + 64) * ASTH + ac) * 2u,
                  A + (size_t)(m0 + ar0 + 64) * p.lda + k0 + ac, av1);
            if (BN == 128) {
                int br = tid >> 4, bc = (tid & 15) * 8;
                cpa16(bBase[s] + (unsigned)(br * BSTH + bc) * 2u,
                      B + (size_t)(k0 + br) * p.ldb + n0 + bc, true);
                cpa16(bBase[s] + (unsigned)((br + 16) * BSTH + bc) * 2u,
                      B + (size_t)(k0 + br + 16) * p.ldb + n0 + bc, true);
            } else {
                int br = tid >> 3, bc = (tid & 7) * 8;
                cpa16(bBase[s] + (unsigned)(br * BSTH + bc) * 2u,
                      B + (size_t)(k0 + br) * p.ldb + n0 + bc, true);
            }
        };

        float acc[MF][NF][4];
        #pragma unroll
        for (int f = 0; f < MF; f++)
            #pragma unroll
            for (int j = 0; j < NF; j++)
                #pragma unroll
                for (int q = 0; q < 4; q++) acc[f][j][q] = 0.f;

        int nIter = p.K >> 5;
        issue(0, 0);  CP_COMMIT;
        issue(1, 32); CP_COMMIT;
        issue(2, 64); CP_COMMIT;

        for (int i = 0; i < nIter; i++) {
            CP_WAIT2;
            __syncthreads();
            if (i + 3 < nIter) issue((i + 3) & 3, (i + 3) * 32);
            CP_COMMIT;

            int s = i & 3;
            unsigned aB = aBase[s], bB = bBase[s];
            #pragma unroll
            for (int kk = 0; kk < 32; kk += 16) {
                unsigned bfr[NF][2];
                #pragma unroll
                for (int j = 0; j < NF; j += 2) {
                    unsigned addr = bB + (unsigned)((kk + bRowT) * BSTH
                                  + wn * WN + j * 8 + bColT) * 2u;
                    ldsm4t(bfr[j][0], bfr[j][1], bfr[j+1][0], bfr[j+1][1], addr);
                }
                #pragma unroll
                for (int f = 0; f < MF; f++) {
                    int row = wm * WM + f * 16 + aRow;
                    unsigned addr = aB + (unsigned)(row * ASTH + kk) * 2u + aKoff;
                    unsigned afr[4];
                    ldsm4(afr[0], afr[1], afr[2], afr[3], addr);
                    #pragma unroll
                    for (int j = 0; j < NF; j++) mma16(acc[f][j], afr, bfr[j]);
                }
            }
        }

        #pragma unroll
        for (int f = 0; f < MF; f++) {
            int r0 = m0 + wm * WM + f * 16 + (lane >> 2);
            int r1 = r0 + 8;
            #pragma unroll
            for (int j = 0; j < NF; j++) {
                int col = n0 + wn * WN + j * 8 + 2 * (lane & 3);
                float b0 = 0.f, b1 = 0.f;
                if (bias) { b0 = bias[col]; b1 = bias[col + 1]; }
                float v0 = acc[f][j][0] + b0, v1 = acc[f][j][1] + b1;
                float v2 = acc[f][j][2] + b0, v3 = acc[f][j][3] + b1;
                if (p.relu) {
                    v0 = fmaxf(v0, 0.f); v1 = fmaxf(v1, 0.f);
                    v2 = fmaxf(v2, 0.f); v3 = fmaxf(v3, 0.f);
                }
                if (r0 < p.M) {
                    if (res) {
                        v0 += p.resScale * res[(size_t)r0 * p.ldres + col];
                        v1 += p.resScale * res[(size_t)r0 * p.ldres + col + 1];
                    }
                    if (C)  *(float2*)&C[(size_t)r0 * p.ldc + col] = make_float2(v0, v1);
                    if (Ch) *(unsigned*)&Ch[(size_t)r0 * p.ldc + col] = h2u(v0, v1);
                }
                if (r1 < p.M) {
                    if (res) {
                        v2 += p.resScale * res[(size_t)r1 * p.ldres + col];
                        v3 += p.resScale * res[(size_t)r1 * p.ldres + col + 1];
                    }
                    if (C)  *(float2*)&C[(size_t)r1 * p.ldc + col] = make_float2(v2, v3);
                    if (Ch) *(unsigned*)&Ch[(size_t)r1 * p.ldc + col] = h2u(v2, v3);
                }
            }
        }
    }
}

#define MMA_SMEM(BN) ((4 * (128*56/2) + 4 * (32*((BN)+8)/2)) * 4)
#define PERSIST_CTAS 296

static void mgemm(const __half* A, int lda, const __half* B, int ldb,
                  float* C, __half* Ch, int ldc,
                  int M, int N, int K,
                  const float* bias = nullptr, const float* res = nullptr, int ldres = 0,
                  float resScale = 0.f, int relu = 0,
                  int z = 1, int zDiv = 1,
                  long long aO=0, long long aI=0, long long bO=0, long long bI=0,
                  long long cO=0, long long cI=0, long long rO=0, long long rI=0,
                  long long biasO=0, int hmode = 0) {
    GPH p;
    p.A=A; p.B=B; p.bias=bias; p.res=res; p.C=C; p.Ch=Ch;
    p.lda=lda; p.ldb=ldb; p.ldc=ldc; p.ldres=ldres;
    p.M=M; p.N=N; p.K=K; p.resScale=resScale; p.relu=relu; p.zDiv=zDiv; p.hmode=hmode;
    p.aO=aO; p.aI=aI; p.bO=bO; p.bI=bI; p.cO=cO; p.cI=cI; p.rO=rO; p.rI=rI; p.biasO=biasO;
    p.gx = (M + 127) / 128;
    if (N % 128 == 0) {
        p.gy = N / 128;
        p.tiles = p.gx * p.gy * z;
        int ctas = p.tiles < PERSIST_CTAS ? p.tiles : PERSIST_CTAS;
        mma_k<128><<<ctas, 256, MMA_SMEM(128)>>>(p);
    } else {
        p.gy = N / 64;
        p.tiles = p.gx * p.gy * z;
        int ctas = p.tiles < PERSIST_CTAS ? p.tiles : PERSIST_CTAS;
        mma_k<64><<<ctas, 256, MMA_SMEM(64)>>>(p);
    }
}

// ----------------------------- fused weight f32->f16 (9 segments) ----------
struct TOH9 {
    const float* s[9];
    __half* d[9];
    int off[10];          // cumulative 8-elem group offsets
};
__global__ void k_tohalf_all(TOH9 t) {
    int g = blockIdx.x * blockDim.x + threadIdx.x;
    if (g >= t.off[9]) return;
    int seg = 0;
    #pragma unroll
    for (int i = 1; i < 9; i++) seg += (g >= t.off[i]);
    int loc = (g - t.off[seg]) * 8;
    const float* in = t.s[seg] + loc;
    __half* out = t.d[seg] + loc;
    uint2 a = f4h(*(const float4*)(in));
    uint2 b = f4h(*(const float4*)(in + 4));
    *(uint4*)(out) = make_uint4(a.x, a.y, b.x, b.y);
}

// ----------------------------- flash attention (fp16, cp.async) ------------
#define KSTW 36
#define FLASH_SMEM ((4*64*KSTW + 128*KSTW) * 4)

__global__ __launch_bounds__(256, 2) void k_flash() {
    extern __shared__ unsigned sm[];
    unsigned sb = (unsigned)__cvta_generic_to_shared(sm);
    unsigned kOff[2] = { sb, sb + 4608u*4u };
    unsigned vOff[2] = { sb + 2304u*4u, sb + 6912u*4u };
    unsigned* sP = sm + 9216;
    unsigned sPb = sb + 9216u*4u;

    int tid = threadIdx.x, lane = tid & 31, w = tid >> 5;
    int m0 = blockIdx.x * 128;
    int bh = blockIdx.y; int h = bh & 7, b = bh >> 3;
    const __half* qb = g_qkvh + (size_t)(b * LL) * QKVD + h * 192;

    int l15 = lane & 15;
    int aRow = (lane & 7) + ((lane >> 3) & 1) * 8;
    unsigned aKoff = ((lane >> 4) & 1) * 16;
    int arow = 16*w + aRow;

    int key = tid >> 2, kc4 = tid & 3;
    auto issue = [&](int st, int kt) {
        const __half* kp = qb + (size_t)(kt*64 + key) * QKVD + 64;
        unsigned kd = kOff[st] + (unsigned)key * 144u;
        cpa16(kd + kc4*16,      kp + kc4*8,       true);
        cpa16(kd + (kc4+4)*16,  kp + (kc4+4)*8,   true);
        unsigned vd = vOff[st] + (unsigned)key * 144u;
        cpa16(vd + kc4*16,      kp + 64 + kc4*8,  true);
        cpa16(vd + (kc4+4)*16,  kp + 64 + (kc4+4)*8, true);
    };

    issue(0, 0); CP_COMMIT;

    {
        int row = tid >> 1, dh = (tid & 1) * 32;
        const uint4* src = (const uint4*)(qb + (size_t)(m0 + row) * QKVD + dh);
        unsigned* dst = sP + row * KSTW + dh/2;
        #pragma unroll
        for (int c = 0; c < 4; c++) *(uint4*)(dst + c*4) = src[c];
    }
    __syncthreads();
    unsigned qf[4][4];
    #pragma unroll
    for (int kc = 0; kc < 4; kc++)
        ldsm4(qf[kc][0], qf[kc][1], qf[kc][2], qf[kc][3],
              sPb + (unsigned)(arow * KSTW) * 4u + (unsigned)kc * 32u + aKoff);

    float accO[8][4];
    #pragma unroll
    for (int j = 0; j < 8; j++)
        #pragma unroll
        for (int q = 0; q < 4; q++) accO[j][q] = 0.f;
    float m0r = -INFINITY, m1r = -INFINITY, l0r = 0.f, l1r = 0.f;

    const unsigned* pmr0 = g_pm + ((size_t)bh * LL + m0 + 16*w + (lane >> 2)) * 16;
    const unsigned* pmr1 = pmr0 + 8 * 16;

    for (int kt = 0; kt < 8; kt++) {
        CP_WAIT0;
        __syncthreads();
        if (kt + 1 < 8) { issue((kt + 1) & 1, kt + 1); CP_COMMIT; }
        int st = kt & 1;

        float S[8][4];
        #pragma unroll
        for (int nt = 0; nt < 8; nt++)
            #pragma unroll
            for (int q = 0; q < 4; q++) S[nt][q] = 0.f;
        #pragma unroll
        for (int kc = 0; kc < 4; kc++) {
            #pragma unroll
            for (int nt = 0; nt < 8; nt++) {
                unsigned bb[2];
                unsigned addr = kOff[st] + (unsigned)((nt*8 + (l15 & 7)) * KSTW) * 4u
                                        + (unsigned)kc * 32u + (unsigned)(l15 >> 3) * 16u;
                ldsm2(bb[0], bb[1], addr);
                mma16(S[nt], qf[kc], bb);
            }
        }

        uint2 mw0 = *(const uint2*)(pmr0 + kt*2);
        uint2 mw1 = *(const uint2*)(pmr1 + kt*2);
        unsigned q0[2] = {mw0.x, mw0.y};
        unsigned q1[2] = {mw1.x, mw1.y};
        float rm0 = -INFINITY, rm1 = -INFINITY;
        #pragma unroll
        for (int nt = 0; nt < 8; nt++) {
            int j0 = nt*8 + 2*(lane & 3), j1 = j0 + 1;
            S[nt][0] = ((q0[j0>>5] >> (j0&31)) & 1u) ? S[nt][0]*0.125f : -INFINITY;
            S[nt][1] = ((q0[j1>>5] >> (j1&31)) & 1u) ? S[nt][1]*0.125f : -INFINITY;
            S[nt][2] = ((q1[j0>>5] >> (j0&31)) & 1u) ? S[nt][2]*0.125f : -INFINITY;
            S[nt][3] = ((q1[j1>>5] >> (j1&31)) & 1u) ? S[nt][3]*0.125f : -INFINITY;
            rm0 = fmaxf(rm0, fmaxf(S[nt][0], S[nt][1]));
            rm1 = fmaxf(rm1, fmaxf(S[nt][2], S[nt][3]));
        }
        rm0 = fmaxf(rm0, __shfl_xor_sync(0xffffffffu, rm0, 1));
        rm0 = fmaxf(rm0, __shfl_xor_sync(0xffffffffu, rm0, 2));
        rm1 = fmaxf(rm1, __shfl_xor_sync(0xffffffffu, rm1, 1));
        rm1 = fmaxf(rm1, __shfl_xor_sync(0xffffffffu, rm1, 2));

        float mn0 = fmaxf(m0r, rm0), mn1 = fmaxf(m1r, rm1);
        float a0 = __expf(m0r - mn0), a1 = __expf(m1r - mn1);
        m0r = mn0; m1r = mn1;

        int prow0 = 16*w + (lane >> 2), prow1 = prow0 + 8;
        float rs0 = 0.f, rs1 = 0.f;
        #pragma unroll
        for (int nt = 0; nt < 8; nt++) {
            int jw = nt*4 + (lane & 3);
            float p00 = __expf(S[nt][0] - mn0), p01 = __expf(S[nt][1] - mn0);
            float p10 = __expf(S[nt][2] - mn1), p11 = __expf(S[nt][3] - mn1);
            rs0 += p00 + p01; rs1 += p10 + p11;
            sP[prow0*KSTW + jw] = h2u(p00, p01);
            sP[prow1*KSTW + jw] = h2u(p10, p11);
        }
        rs0 += __shfl_xor_sync(0xffffffffu, rs0, 1);
        rs0 += __shfl_xor_sync(0xffffffffu, rs0, 2);
        rs1 += __shfl_xor_sync(0xffffffffu, rs1, 1);
        rs1 += __shfl_xor_sync(0xffffffffu, rs1, 2);
        l0r = l0r * a0 + rs0;
        l1r = l1r * a1 + rs1;

        #pragma unroll
        for (int j = 0; j < 8; j++) {
            accO[j][0] *= a0; accO[j][1] *= a0;
            accO[j][2] *= a1; accO[j][3] *= a1;
        }
        __syncwarp();

        #pragma unroll
        for (int kc = 0; kc < 4; kc++) {
            unsigned pf[4];
            ldsm4(pf[0], pf[1], pf[2], pf[3],
                  sPb + (unsigned)(arow * KSTW) * 4u + (unsigned)kc * 32u + aKoff);
            #pragma unroll
            for (int nt = 0; nt < 8; nt++) {
                unsigned bb[2];
                unsigned addr = vOff[st] + (unsigned)((kc*16 + (l15 & 7) + (l15 >> 3)*8) * KSTW) * 4u
                                        + (unsigned)nt * 16u;
                ldsm2t(bb[0], bb[1], addr);
                mma16(accO[nt], pf, bb);
            }
        }
    }

    float inv0 = 1.f / l0r, inv1 = 1.f / l1r;
    int r0 = m0 + 16*w + (lane >> 2), r1 = r0 + 8;
    __half* o0 = g_oh + (size_t)(b*LL + r0) * NHID + h*64;
    __half* o1 = g_oh + (size_t)(b*LL + r1) * NHID + h*64;
    #pragma unroll
    for (int nt = 0; nt < 8; nt++) {
        int col = nt*8 + 2*(lane & 3);
        *(unsigned*)&o0[col] = h2u(accO[nt][0]*inv0, accO[nt][1]*inv0);
        *(unsigned*)&o1[col] = h2u(accO[nt][2]*inv1, accO[nt][3]*inv1);
    }
}

// pack mask (int32 bool, layout [b][i][h][j]) -> bits [b][h][i][j/32]
__global__ void k_packmask(const int* __restrict__ mask) {
    int row = blockIdx.x * 8 + (threadIdx.x >> 5);
    int lane = threadIdx.x & 31;
    const int* mr = mask + (size_t)row * LL;
    int b_i = row >> 3, h = row & 7;
    int b = b_i >> 9, i = b_i & 511;
    unsigned* out = g_pm + (((size_t)(b*HEADS + h) * LL + i) << 4);
    #pragma unroll
    for (int wd = 0; wd < 16; wd++) {
        unsigned bits = __ballot_sync(0xffffffffu, mr[wd*32 + lane] != 0);
        if (lane == 0) out[wd] = bits;
    }
}

// ----------------------------- small FFMA GEMM (M=1) -----------------------
__global__ void gemm1_k(GP p) {
    int zo = blockIdx.z;
    const float* A = p.A + zo * p.aO;
    const float* B = p.B + zo * p.bO;
    float* C = p.C + zo * p.cO;
    const float* bias = p.bias ? p.bias + zo * p.biasO : nullptr;
    int n = blockIdx.x * 64 + threadIdx.x;
    if (n >= p.N) return;
    float s = 0.f;
    for (int k = 0; k < p.K; k++) s += A[k] * B[(size_t)k * p.ldb + n];
    if (bias) s += bias[n];
    C[n] = s;
}

// ----------------------------- small kernels -------------------------------
__global__ void k_embed(const float* __restrict__ emb, const float* __restrict__ pos,
                        const int* __restrict__ idxs) {
    int tok = blockIdx.x;
    int b = tok >> 9, s = tok & 511;
    int id = (s == 0) ? 0 : idxs[b*SS + s - 1];
    const float4* e  = (const float4*)(emb + (size_t)id * NHID);
    const float4* pr = (const float4*)(pos + (size_t)s  * NHID);
    float4* hr = (float4*)(g_h + (size_t)tok * NHID);
    uint2*  hh = (uint2*)(g_hh + (size_t)tok * NHID);
    int t = threadIdx.x;
    float4 a = e[t], c = pr[t];
    float4 v = make_float4(a.x+c.x, a.y+c.y, a.z+c.z, a.w+c.w);
    hr[t] = v;
    hh[t] = f4h(v);
}

__global__ void k_ln_add(float* __restrict__ out, const float* __restrict__ inp,
                         const float* __restrict__ base, int hgMap,
                         const float* __restrict__ gw, const float* __restrict__ bw,
                         __half* __restrict__ outH) {
    int n = blockIdx.x;
    const float* xr = inp + (size_t)n * NHID;
    size_t brow;
    if (hgMap) { int b = n / SS, s = n % SS; brow = ((size_t)(b*LL + s + 1)) * NHID; }
    else brow = (size_t)n * NHID;
    int t = threadIdx.x;
    float x[4];
    #pragma unroll
    for (int i = 0; i < 4; i++) x[i] = xr[t + i*128];
    __shared__ float red[128];
    red[t] = x[0]+x[1]+x[2]+x[3]; __syncthreads();
    for (int s = 64; s > 0; s >>= 1) { if (t < s) red[t] += red[t+s]; __syncthreads(); }
    float mu = red[0] * (1.f/512.f); __syncthreads();
    float d[4], vs = 0.f;
    #pragma unroll
    for (int i = 0; i < 4; i++) { d[i] = x[i] - mu; vs += d[i]*d[i]; }
    red[t] = vs; __syncthreads();
    for (int s = 64; s > 0; s >>= 1) { if (t < s) red[t] += red[t+s]; __syncthreads(); }
    float inv = rsqrtf(red[0] * (1.f/512.f) + 1e-5f);
    #pragma unroll
    for (int i = 0; i < 4; i++) {
        int c = t + i*128;
        float v = base[brow + c] + d[i]*inv*gw[c] + bw[c];
        out[(size_t)n*NHID + c] = v;
        if (outH) outH[(size_t)n*NHID + c] = __float2half_rn(v);
    }
}

__global__ void k_zg(float* __restrict__ dout) {
    int b = blockIdx.x; int t = threadIdx.x;
    #pragma unroll
    for (int i = 0; i < 4; i++) {
        int c = t + i*128;
        dout[(size_t)NNODE*NHID + b*NHID + c] = g_h[((size_t)b*LL) * NHID + c];
    }
}

__global__ void k_copyxf() {
    int n = blockIdx.x;
    int b = n / SS, s = n % SS;
    const float4* src = (const float4*)(g_h + ((size_t)(b*LL + s + 1)) * NHID);
    uint2* dst = (uint2*)(g_xfh + (size_t)n * NHID);
    dst[threadIdx.x] = f4h(src[threadIdx.x]);
}

__global__ void k_zero_ints() {
    int i = blockIdx.x*blockDim.x + threadIdx.x;
    if (i < 2*NNODE) { g_ind[i] = 0; g_outd[i] = 0; g_cur[i] = 0; }
}

// both graphs in one launch (blockIdx.y selects)
__global__ void k_count2(const int* __restrict__ s0, const int* __restrict__ d0,
                         const int* __restrict__ s1, const int* __restrict__ d1) {
    int gi = blockIdx.y;
    const int* src = gi ? s1 : s0;
    const int* dst = gi ? d1 : d0;
    int e = blockIdx.x*blockDim.x + threadIdx.x;
    if (e < EE) {
        atomicAdd(&g_ind [gi*NNODE + dst[e]], 1);
        atomicAdd(&g_outd[gi*NNODE + src[e]], 1);
    }
}

__global__ void k_scan() {
    __shared__ int sh[1024];
    int gi = blockIdx.x;
    int t = threadIdx.x;
    int base = gi * NNODE;
    int loc[8]; int sum = 0;
    #pragma unroll
    for (int i = 0; i < 8; i++) {
        int idx = t*8 + i;
        int v = (idx < NNODE) ? g_ind[base + idx] : 0;
        loc[i] = sum; sum += v;
    }
    sh[t] = sum; __syncthreads();
    for (int d = 1; d < 1024; d <<= 1) {
        int v = (t >= d) ? sh[t-d] : 0; __syncthreads();
        sh[t] += v; __syncthreads();
    }
    int pre = (t > 0) ? sh[t-1] : 0;
    #pragma unroll
    for (int i = 0; i < 8; i++) {
        int idx = t*8 + i;
        if (idx < NNODE) g_off[base + idx] = pre + loc[i];
    }
}

__global__ void k_scatter2(const int* __restrict__ s0, const int* __restrict__ d0,
                           const int* __restrict__ s1, const int* __restrict__ d1) {
    int gi = blockIdx.y;
    const int* src = gi ? s1 : s0;
    const int* dst = gi ? d1 : d0;
    int e = blockIdx.x*blockDim.x + threadIdx.x;
    if (e < EE) {
        int d = dst[e];
        int p = g_off[gi*NNODE + d] + atomicAdd(&g_cur[gi*NNODE + d], 1);
        g_csr[gi*EE + p] = src[e];
    }
}

__global__ void k_scales() {
    int i = blockIdx.x*blockDim.x + threadIdx.x;
    if (i < 2*NNODE) {
        float in = (float)g_ind[i], od = (float)g_outd[i];
        g_sin [i] = rsqrtf(fmaxf(in, 1.f));
        g_sout[i] = rsqrtf(fmaxf(od, 1.f));
        g_inv1[i] = 1.f / (in + 1.f);
    }
}

// fp16 SAGE propagation: out[gi][n] = (x[n] + sum_in x[src]) / (ind+1)
__global__ void k_prop_sage(const __half* __restrict__ x, long long xper,
                            __half* __restrict__ out) {
    int gi = blockIdx.y;
    int wid = blockIdx.x * (blockDim.x >> 5) + (threadIdx.x >> 5);
    if (wid >= NNODE) return;
    int lane = threadIdx.x & 31;
    const __half* xb = x + (size_t)gi * xper;
    float a[16];
    #pragma unroll
    for (int i = 0; i < 16; i++) a[i] = 0.f;
    {
        const uint4* xr = (const uint4*)(xb + (size_t)wid * NHID);
        addh8(a, xr[lane], 1.f);
        addh8(a + 8, xr[lane + 32], 1.f);
    }
    int s = g_off[gi*NNODE + wid], e = s + g_ind[gi*NNODE + wid];
    const int* csr = g_csr + gi*EE;
    for (int j = s; j < e; j++) {
        const uint4* sr = (const uint4*)(xb + (size_t)csr[j] * NHID);
        addh8(a, sr[lane], 1.f);
        addh8(a + 8, sr[lane + 32], 1.f);
    }
    float sc = g_inv1[gi*NNODE + wid];
    uint4* o = (uint4*)(out + (size_t)gi * NNODE * NHID + (size_t)wid * NHID);
    o[lane]      = pack8(a, sc);
    o[lane + 32] = pack8(a + 8, sc);
}

// fp16 GC propagation
__global__ void k_prop_gc(const __half* __restrict__ q, __half* __restrict__ outT) {
    int gi = blockIdx.y;
    int wid = blockIdx.x * (blockDim.x >> 5) + (threadIdx.x >> 5);
    if (wid >= NNODE) return;
    int lane = threadIdx.x & 31;
    const __half* qb = q + (size_t)gi * NNODE * NHID;
    float a[16];
    #pragma unroll
    for (int i = 0; i < 16; i++) a[i] = 0.f;
    float ts = 0.f;
    int s = g_off[gi*NNODE + wid], e = s + g_ind[gi*NNODE + wid];
    const int* csr = g_csr + gi*EE;
    for (int j = s; j < e; j++) {
        int sn = csr[j];
        float so = g_sout[gi*NNODE + sn];
        ts += so;
        const uint4* sr = (const uint4*)(qb + (size_t)sn * NHID);
        addh8(a, sr[lane], so);
        addh8(a + 8, sr[lane + 32], so);
    }
    uint4* o = (uint4*)(outT + (size_t)gi * NNODE * NHID + (size_t)wid * NHID);
    o[lane]      = pack8(a, 1.f);
    o[lane + 32] = pack8(a + 8, 1.f);
    if (lane == 0) g_tvec[gi*NNODE + wid] = ts;
}

__global__ void k_xcepi(const float* __restrict__ gc3b) {
    int n = blockIdx.x; int c = threadIdx.x;
    int g = c_pat[c >> 6];
    float si = g_sin[g*NNODE + n], tv = g_tvec[g*NNODE + n];
    size_t idx = (size_t)n*NHID + c;
    g_xc[idx] = si * g_xc[idx] + si * tv * g_dcat[c] + gc3b[c];
}

// ----------------------------- host orchestration --------------------------
#define SYMF(name, var) { void* _p; cudaGetSymbolAddress(&_p, name); var = (float*)_p; }
#define SYMH(name, var) { void* _p; cudaGetSymbolAddress(&_p, name); var = (__half*)_p; }

extern "C" void kernel_launch(void* const* d_in, const int* in_sizes, int n_in,
                              void* d_out, int out_size) {
    const float* in_embed  = (const float*)d_in[0];
    const float* pos_embed = (const float*)d_in[1];
    const float* qkv_w     = (const float*)d_in[2];
    const float* qkv_b     = (const float*)d_in[3];
    const float* attn_w    = (const float*)d_in[4];
    const float* attn_b    = (const float*)d_in[5];
    const float* ff1_w     = (const float*)d_in[6];
    const float* ff1_b     = (const float*)d_in[7];
    const float* ff2_w     = (const float*)d_in[8];
    const float* ff2_b     = (const float*)d_in[9];
    const float* sage1_w   = (const float*)d_in[10];
    const float* sage1_b   = (const float*)d_in[11];
    const float* sage2_w   = (const float*)d_in[12];
    const float* sage2_b   = (const float*)d_in[13];
    const float* gc3_w     = (const float*)d_in[14];
    const float* gc3_b     = (const float*)d_in[15];
    const float* gff1_w    = (const float*)d_in[16];
    const float* gff1_b    = (const float*)d_in[17];
    const float* gff2_w    = (const float*)d_in[18];
    const float* gff2_b    = (const float*)d_in[19];
    const float* ln_g      = (const float*)d_in[20];
    const float* ln_b      = (const float*)d_in[21];
    const int*   in_idxs   = (const int*)d_in[22];
    const int*   mask      = (const int*)d_in[23];   // bool marshalled as int32
    const int*   gt_src    = (const int*)d_in[24];
    const int*   gt_dst    = (const int*)d_in[25];
    const int*   at_src    = (const int*)d_in[26];
    const int*   at_dst    = (const int*)d_in[27];

    float *h, *x, *xc, *xg, *cc, *dc;
    SYMF(g_h, h); SYMF(g_x, x); SYMF(g_xc, xc); SYMF(g_xg, xg);
    SYMF(g_ccat, cc); SYMF(g_dcat, dc);
    __half *hh, *qkvh, *oh, *xh, *ffh, *xfh, *Ph, *Qh, *Th, *Mh, *Nch, *xgh, *fgh;
    __half *qkvwh, *attnwh, *ff1wh, *ff2wh, *s1wh, *s2wh, *gc3wh, *gff1wh, *gff2wh;
    SYMH(g_hh, hh); SYMH(g_qkvh, qkvh); SYMH(g_oh, oh); SYMH(g_xh, xh); SYMH(g_ffh, ffh);
    SYMH(g_xfh, xfh); SYMH(g_Ph, Ph); SYMH(g_Qh, Qh); SYMH(g_Th, Th);
    SYMH(g_Mh, Mh); SYMH(g_Nch, Nch); SYMH(g_xgh, xgh); SYMH(g_fgh, fgh);
    SYMH(g_qkvwh, qkvwh); SYMH(g_attnwh, attnwh); SYMH(g_ff1wh, ff1wh);
    SYMH(g_ff2wh, ff2wh); SYMH(g_s1wh, s1wh); SYMH(g_s2wh, s2wh);
    SYMH(g_gc3wh, gc3wh); SYMH(g_gff1wh, gff1wh); SYMH(g_gff2wh, gff2wh);

    static int smemSet = 0;
    if (!smemSet) {
        cudaFuncSetAttribute(k_flash, cudaFuncAttributeMaxDynamicSharedMemorySize, FLASH_SMEM);
        cudaFuncSetAttribute(mma_k<128>, cudaFuncAttributeMaxDynamicSharedMemorySize, MMA_SMEM(128));
        cudaFuncSetAttribute(mma_k<64>,  cudaFuncAttributeMaxDynamicSharedMemorySize, MMA_SMEM(64));
        smemSet = 1;
    }

    // ---- fused weight f32 -> f16 (single launch) ----
    {
        TOH9 t;
        const float* srcs[9] = {qkv_w, attn_w, ff1_w, ff2_w, sage1_w, sage2_w,
                                gc3_w, gff1_w, gff2_w};
        __half* dsts[9] = {qkvwh, attnwh, ff1wh, ff2wh, s1wh, s2wh,
                           gc3wh, gff1wh, gff2wh};
        int ns[9] = {4*NHID*QKVD, 4*NHID*NHID, 4*NHID*FFD, 4*FFD*NHID,
                     HEADS*NHID*NHID, HEADS*NHID*NHID, HEADS*NHID*64,
                     NHID*NHID, NHID*NHID};
        int acc = 0;
        for (int i = 0; i < 9; i++) { t.s[i] = srcs[i]; t.d[i] = dsts[i];
                                      t.off[i] = acc; acc += ns[i] / 8; }
        t.off[9] = acc;
        k_tohalf_all<<<(acc + 255)/256, 256>>>(t);
    }

    // ---- embedding + mask packing ----
    k_embed<<<NTOK, 128>>>(in_embed, pos_embed, in_idxs);
    k_packmask<<<BB*LL*HEADS/8, 256>>>(mask);

    // ---- transformer layers ----
    for (int l = 0; l < 4; l++) {
        mgemm(hh, NHID, qkvwh + (size_t)l*NHID*QKVD, QKVD, nullptr, qkvh, QKVD,
              NTOK, QKVD, NHID, qkv_b + l*QKVD);
        k_flash<<<dim3(LL/128, BB*HEADS), 256, FLASH_SMEM>>>();
        mgemm(oh, NHID, attnwh + (size_t)l*NHID*NHID, NHID, x, xh, NHID,
              NTOK, NHID, NHID, attn_b + l*NHID, h, NHID, 2.0f);
        mgemm(xh, NHID, ff1wh + (size_t)l*NHID*FFD, FFD, nullptr, ffh, FFD,
              NTOK, FFD, NHID, ff1_b + l*FFD, nullptr, 0, 0.f, /*relu=*/1);
        mgemm(ffh, FFD, ff2wh + (size_t)l*FFD*NHID, NHID, h, hh, NHID,
              NTOK, NHID, FFD, ff2_b + l*NHID, x, NHID, 1.0f);
    }

    // ---- graph preprocessing (merged launches) ----
    k_zero_ints<<<(2*NNODE + 255)/256, 256>>>();
    k_count2<<<dim3(EE/256, 2), 256>>>(gt_src, gt_dst, at_src, at_dst);
    k_scan<<<2, 1024>>>();
    k_scatter2<<<dim3(EE/256, 2), 256>>>(gt_src, gt_dst, at_src, at_dst);
    k_scales<<<(2*NNODE + 255)/256, 256>>>();
    k_copyxf<<<NNODE, 128>>>();

    // ---- propagations: both graphs per launch, fp16 data ----
    int propBlocks = (NNODE + 7) / 8;
    k_prop_sage<<<dim3(propBlocks, 2), 256>>>(xfh, 0, Ph);
    k_prop_sage<<<dim3(propBlocks, 2), 256>>>(Ph, (long long)NNODE*NHID, Qh);
    k_prop_gc  <<<dim3(propBlocks, 2), 256>>>(Qh, Th);

    // ---- collapse per-head weights ----
    mgemm(s1wh, NHID, s2wh, NHID, nullptr, Mh, NHID, NHID, NHID, NHID,
          nullptr, nullptr, 0, 0.f, 0, HEADS, 1,
          (long long)NHID*NHID, 0, (long long)NHID*NHID, 0, (long long)NHID*NHID, 0);
    mgemm(Mh, NHID, gc3wh, 64, nullptr, Nch, 64, NHID, 64, NHID,
          nullptr, nullptr, 0, 0.f, 0, HEADS, 1,
          (long long)NHID*NHID, 0, (long long)NHID*64, 0, (long long)NHID*64, 0);
    {
        GP p; p.A=sage1_b; p.B=sage2_w; p.bias=sage2_b; p.C=cc;
        p.ldb=NHID; p.N=NHID; p.K=NHID;
        p.aO=NHID; p.bO=(long long)NHID*NHID; p.cO=NHID; p.biasO=NHID;
        gemm1_k<<<dim3((NHID+63)/64,1,HEADS), 64>>>(p);
    }
    {
        GP p; p.A=cc; p.B=gc3_w; p.bias=nullptr; p.C=dc;
        p.ldb=64; p.N=64; p.K=NHID;
        p.aO=NHID; p.bO=(long long)NHID*64; p.cO=64; p.biasO=0;
        gemm1_k<<<dim3(1,1,HEADS), 64>>>(p);
    }

    // ---- xc per head: A = Th[(z>>1)&1] via hmode ----
    mgemm(Th, NHID, Nch, 64, xc, nullptr, NHID,
          NNODE, 64, NHID, nullptr, nullptr, 0, 0.f, 0,
          HEADS, 1,
          0, (long long)NNODE*NHID,
          (long long)NHID*64, 0,
          64, 0, 0, 0, 0, /*hmode=*/1);
    k_xcepi<<<NNODE, 512>>>(gc3_b);

    // ---- final: xg = hg + LN(xc); ff path; zbar = xg + LN(ff) ----
    k_ln_add<<<NNODE, 128>>>(xg, xc, h, /*hgMap=*/1, ln_g, ln_b, xgh);
    mgemm(xgh, NHID, gff1wh, NHID, nullptr, fgh, NHID,
          NNODE, NHID, NHID, gff1_b, nullptr, 0, 0.f, /*relu=*/1);
    mgemm(fgh, NHID, gff2wh, NHID, xc, nullptr, NHID,
          NNODE, NHID, NHID, gff2_b);
    k_ln_add<<<NNODE, 128>>>((float*)d_out, xc, xg, /*hgMap=*/0, ln_g, ln_b, nullptr);

    // ---- zg ----
    if (out_size >= NNODE*NHID + BB*NHID)
        k_zg<<<BB, 128>>>((float*)d_out);
}